// round 9
// baseline (speedup 1.0000x reference)
#include <cuda_runtime.h>
#include <cuda_fp16.h>
#include <cuda_fp8.h>
#include <math.h>
#include <stdint.h>

#define NP 8192
#define MP 8192
#define DIMS 32
#define EPSV 10.0f
#define THRESH2 (1e-5f * 1e-5f)
#define FP8_ITERS 24
#define TOTAL_ITERS 30 /* 24 fp8 + 6 fp16 polish */
#define SCALE_F 65536.0f
#define INV_SCALE_F (1.0f / 65536.0f)
#define LOG_SCALE_F 11.090354888959125f /* ln(65536) */
#define CS 16
#define CHUNK (MP / CS) /* 512 */
#define RPB 32
#define AH_SCALE 1024.0f
#define NCOMB 32 /* combiner blocks per fused kernel */

#define PDL_TOP()                                                              \
    do {                                                                       \
        asm volatile("griddepcontrol.launch_dependents;" ::: "memory");        \
        asm volatile("griddepcontrol.wait;" ::: "memory");                     \
    } while (0)

__device__ __half   g_K1[(size_t)NP * MP];
__device__ __half   g_K1T[(size_t)NP * MP];
__device__ uint8_t  g_K8[(size_t)NP * MP];
__device__ uint8_t  g_K8T[(size_t)NP * MP];
__device__ float    g_a[NP];
__device__ float    g_b[MP];
__device__ __half   g_ah[NP];
__device__ __half   g_bh[MP];
__device__ float    g_pa[NP * CS]; // partials, layout [row][16]
__device__ float    g_pb[MP * CS];
__device__ float    g_errp[NCOMB];
__device__ unsigned g_sync; // monotonic combiner counter (reset per launch)
__device__ float    g_part[16384];

// ---------------------------------------------------------------------------
__global__ void sink_init()
{
    int i = blockIdx.x * 256 + threadIdx.x;
    if (i < MP) { g_b[i] = 1.0f; g_bh[i] = __float2half_rn(1.0f); }
    if (i < NCOMB) g_errp[i] = 1e30f;
    if (i == 0) g_sync = 0u;
}

// ---------------------------------------------------------------------------
// Build: e = exp(-max(C,0)/EPS). Store e*2^16 fp16 (K1,K1T), e*2^8 fp8
// (K8,K8T). 64x64 tile per block.
__global__ __launch_bounds__(256) void build_K(const float* __restrict__ x,
                                               const float* __restrict__ y)
{
    __shared__ float sx[64][DIMS + 1];
    __shared__ float sy[64][DIMS + 1];
    __shared__ float sx2[64];
    __shared__ float sy2[64];
    __shared__ __half  stile[64][65];
    __shared__ uint8_t s8tile[64][68];

    const int tid = threadIdx.x;
    const int I0 = blockIdx.y * 64;
    const int J0 = blockIdx.x * 64;

    for (int idx = tid; idx < 64 * DIMS; idx += 256) {
        int r = idx >> 5, k = idx & 31;
        sx[r][k] = x[(I0 + r) * DIMS + k];
        sy[r][k] = y[(J0 + r) * DIMS + k];
    }
    __syncthreads();
    if (tid < 64) {
        float s = 0.f;
        #pragma unroll
        for (int k = 0; k < DIMS; k++) { float v = sx[tid][k]; s = fmaf(v, v, s); }
        sx2[tid] = s;
    } else if (tid < 128) {
        int r = tid - 64;
        float s = 0.f;
        #pragma unroll
        for (int k = 0; k < DIMS; k++) { float v = sy[r][k]; s = fmaf(v, v, s); }
        sy2[r] = s;
    }
    __syncthreads();

    const int ty = tid >> 4, tx = tid & 15;
    const int r0 = ty * 4, c0 = tx * 4;
    float acc[4][4];
    #pragma unroll
    for (int i = 0; i < 4; i++)
        #pragma unroll
        for (int j = 0; j < 4; j++) acc[i][j] = 0.f;

    #pragma unroll
    for (int k = 0; k < DIMS; k++) {
        float a0 = sx[r0 + 0][k], a1 = sx[r0 + 1][k];
        float a2 = sx[r0 + 2][k], a3 = sx[r0 + 3][k];
        float b0 = sy[c0 + 0][k], b1 = sy[c0 + 1][k];
        float b2 = sy[c0 + 2][k], b3 = sy[c0 + 3][k];
        acc[0][0] = fmaf(a0, b0, acc[0][0]); acc[0][1] = fmaf(a0, b1, acc[0][1]);
        acc[0][2] = fmaf(a0, b2, acc[0][2]); acc[0][3] = fmaf(a0, b3, acc[0][3]);
        acc[1][0] = fmaf(a1, b0, acc[1][0]); acc[1][1] = fmaf(a1, b1, acc[1][1]);
        acc[1][2] = fmaf(a1, b2, acc[1][2]); acc[1][3] = fmaf(a1, b3, acc[1][3]);
        acc[2][0] = fmaf(a2, b0, acc[2][0]); acc[2][1] = fmaf(a2, b1, acc[2][1]);
        acc[2][2] = fmaf(a2, b2, acc[2][2]); acc[2][3] = fmaf(a2, b3, acc[2][3]);
        acc[3][0] = fmaf(a3, b0, acc[3][0]); acc[3][1] = fmaf(a3, b1, acc[3][1]);
        acc[3][2] = fmaf(a3, b2, acc[3][2]); acc[3][3] = fmaf(a3, b3, acc[3][3]);
    }

    #pragma unroll
    for (int i = 0; i < 4; i++) {
        #pragma unroll
        for (int j = 0; j < 4; j++) {
            float C = sx2[r0 + i] + sy2[c0 + j] - 2.f * acc[i][j];
            C = fmaxf(C, 0.f);
            float e16 = exp2f(fmaf(C, -0.14426950408889634f, 16.0f));
            stile[r0 + i][c0 + j] = __float2half_rn(fminf(e16, 65504.f));
            s8tile[r0 + i][c0 + j] = (uint8_t)__nv_cvt_float_to_fp8(
                e16 * 0.00390625f, __NV_SATFINITE, __NV_E4M3);
        }
    }
    __syncthreads();

    for (int idx = tid; idx < 4096; idx += 256) {
        int r = idx >> 6, c = idx & 63;
        g_K1[(size_t)(I0 + r) * MP + (J0 + c)] = stile[r][c];
        g_K1T[(size_t)(J0 + r) * NP + (I0 + c)] = stile[c][r];
    }
    for (int idx = tid; idx < 1024; idx += 256) {
        int r = idx >> 4, c4 = (idx & 15) * 4;
        uchar4 v;
        v.x = s8tile[r][c4 + 0]; v.y = s8tile[r][c4 + 1];
        v.z = s8tile[r][c4 + 2]; v.w = s8tile[r][c4 + 3];
        *(uchar4*)(g_K8 + (size_t)(I0 + r) * MP + (J0 + c4)) = v;
        uchar4 t;
        t.x = s8tile[c4 + 0][r]; t.y = s8tile[c4 + 1][r];
        t.z = s8tile[c4 + 2][r]; t.w = s8tile[c4 + 3][r];
        *(uchar4*)(g_K8T + (size_t)(J0 + r) * NP + (I0 + c4)) = t;
    }
}

// ---------------------------------------------------------------------------
__device__ __forceinline__ float combine16(const float* __restrict__ part,
                                           int i)
{
    const float4* p4 = (const float4*)(part + i * CS);
    float4 q0 = p4[0], q1 = p4[1], q2 = p4[2], q3 = p4[3];
    return ((q0.x + q0.y) + (q0.z + q0.w)) + ((q1.x + q1.y) + (q1.z + q1.w)) +
           ((q2.x + q2.y) + (q2.z + q2.w)) + ((q3.x + q3.y) + (q3.z + q3.w));
}

// Combiner role (blocks 0..31): finish previous pass's vector update, then
// publish via fence + counter add. Deterministic (fixed-order sums).
__device__ __forceinline__ void combiner_role(
    const float* __restrict__ part_in, const float* __restrict__ mul_c,
    float cscale, float hscale, float* __restrict__ vecf,
    __half* __restrict__ vech, int do_combine, int do_err)
{
    const int tid = threadIdx.x;
    if (do_combine) {
        const int i = blockIdx.x * 256 + tid;
        float s = combine16(part_in, i);
        float nv = __fdividef(mul_c[i] * cscale, s);
        if (do_err) {
            float d = nv - vecf[i];
            __shared__ float sd[256];
            sd[tid] = d * d;
            vecf[i] = nv;
            vech[i] = __float2half_rn(nv * hscale);
            __syncthreads();
            for (int o = 128; o; o >>= 1) {
                if (tid < o) sd[tid] += sd[tid + o];
                __syncthreads();
            }
            if (tid == 0) g_errp[blockIdx.x] = sd[0];
        } else {
            vecf[i] = nv;
            vech[i] = __float2half_rn(nv * hscale);
        }
    }
    __syncthreads();
    if (tid == 0) {
        __threadfence();
        atomicAdd(&g_sync, 1u);
    }
}

// Matvec gate: wait for this kernel's combiners, then freeze check.
// Returns true if frozen (skip work, leaving partials stale).
__device__ __forceinline__ bool matvec_gate(unsigned expected)
{
    __shared__ float s_err;
    if (threadIdx.x == 0) {
        volatile unsigned* sp = (volatile unsigned*)&g_sync;
        while (*sp < expected) { }
        __threadfence();
    }
    __syncthreads();
    if (threadIdx.x < 32) {
        float v = g_errp[threadIdx.x];
        #pragma unroll
        for (int o = 16; o; o >>= 1) v += __shfl_xor_sync(0xffffffffu, v, o);
        if (threadIdx.x == 0) s_err = v;
    }
    __syncthreads();
    return s_err < THRESH2;
}

// ---------------------------------------------------------------------------
// fp8 decode: e4m3 bits placed into fp16 carry an exact 2^-8 factor (folded
// into the combine scale); exact incl. subnormals (values non-negative).
__device__ __forceinline__ __half2 dec8(uint32_t w, uint32_t sel)
{
    uint32_t r = (__byte_perm(w, 0u, sel) >> 1) & 0x7F807F80u;
    return *reinterpret_cast<__half2*>(&r);
}

__device__ __forceinline__ float row16_fp8(uint4 u, uint4 bA, uint4 bB)
{
    const __half2* ba = reinterpret_cast<const __half2*>(&bA);
    const __half2* bb = reinterpret_cast<const __half2*>(&bB);
    __half2 acc = __hmul2(dec8(u.x, 0x1404u), ba[0]);
    acc = __hfma2(dec8(u.x, 0x3424u), ba[1], acc);
    acc = __hfma2(dec8(u.y, 0x1404u), ba[2], acc);
    acc = __hfma2(dec8(u.y, 0x3424u), ba[3], acc);
    acc = __hfma2(dec8(u.z, 0x1404u), bb[0], acc);
    acc = __hfma2(dec8(u.z, 0x3424u), bb[1], acc);
    acc = __hfma2(dec8(u.w, 0x1404u), bb[2], acc);
    acc = __hfma2(dec8(u.w, 0x3424u), bb[3], acc);
    float2 f = __half22float2(acc);
    return f.x + f.y;
}

// Fused fp8 pass: 32 combiner blocks + 4096 matvec blocks (32 rows x 512
// cols tiles; warp = 4 rows, lane = 16 cols; partials [row][16]).
__global__ __launch_bounds__(256) void fused8(
    const uint8_t* __restrict__ K8, float* __restrict__ part_out,
    const float* __restrict__ part_in, const float* __restrict__ mul_c,
    float cscale, float hscale, float* __restrict__ vecf,
    __half* __restrict__ vech, int do_combine, int do_err, unsigned expected)
{
    PDL_TOP();
    if (blockIdx.x < NCOMB) {
        combiner_role(part_in, mul_c, cscale, hscale, vecf, vech, do_combine,
                      do_err);
        return;
    }
    if (matvec_gate(expected)) return;
    const int bid = blockIdx.x - NCOMB;
    const int cs = bid & (CS - 1);
    const int rb = bid / CS;
    const int warp = threadIdx.x >> 5;
    const int lane = threadIdx.x & 31;
    const int rbase = rb * RPB + warp * 4;
    const int col0 = cs * CHUNK + lane * 16;

    const uint4* bhp = (const uint4*)(vech + col0);
    uint4 bA = bhp[0], bB = bhp[1];

    const size_t base = (size_t)rbase * MP + col0;
    uint4 u0 = __ldcg((const uint4*)(K8 + base));
    uint4 u1 = __ldcg((const uint4*)(K8 + base + MP));
    uint4 u2 = __ldcg((const uint4*)(K8 + base + 2 * MP));
    uint4 u3 = __ldcg((const uint4*)(K8 + base + 3 * MP));

    float a0 = row16_fp8(u0, bA, bB);
    float a1 = row16_fp8(u1, bA, bB);
    float a2 = row16_fp8(u2, bA, bB);
    float a3 = row16_fp8(u3, bA, bB);

    #pragma unroll
    for (int o = 16; o; o >>= 1) {
        a0 += __shfl_xor_sync(0xffffffffu, a0, o);
        a1 += __shfl_xor_sync(0xffffffffu, a1, o);
        a2 += __shfl_xor_sync(0xffffffffu, a2, o);
        a3 += __shfl_xor_sync(0xffffffffu, a3, o);
    }
    if (lane == 0) {
        part_out[(rbase + 0) * CS + cs] = a0;
        part_out[(rbase + 1) * CS + cs] = a1;
        part_out[(rbase + 2) * CS + cs] = a2;
        part_out[(rbase + 3) * CS + cs] = a3;
    }
}

// ---------------------------------------------------------------------------
#define HQ_FMA(u, bA, bB, acc)                                                 \
    {                                                                          \
        float2 f0_ = __half22float2(*reinterpret_cast<__half2*>(&(u).x));      \
        float2 f1_ = __half22float2(*reinterpret_cast<__half2*>(&(u).y));      \
        float2 f2_ = __half22float2(*reinterpret_cast<__half2*>(&(u).z));      \
        float2 f3_ = __half22float2(*reinterpret_cast<__half2*>(&(u).w));      \
        acc = fmaf(f0_.x, (bA).x, acc); acc = fmaf(f0_.y, (bA).y, acc);        \
        acc = fmaf(f1_.x, (bA).z, acc); acc = fmaf(f1_.y, (bA).w, acc);        \
        acc = fmaf(f2_.x, (bB).x, acc); acc = fmaf(f2_.y, (bB).y, acc);        \
        acc = fmaf(f3_.x, (bB).z, acc); acc = fmaf(f3_.y, (bB).w, acc);        \
    }

// Fused fp16 pass (polish): same structure, float input vector.
__global__ __launch_bounds__(256) void fused16(
    const __half* __restrict__ K, float* __restrict__ part_out,
    const float* __restrict__ part_in, const float* __restrict__ mul_c,
    float cscale, float hscale, float* __restrict__ vecf,
    __half* __restrict__ vech, int do_combine, int do_err, unsigned expected)
{
    PDL_TOP();
    if (blockIdx.x < NCOMB) {
        combiner_role(part_in, mul_c, cscale, hscale, vecf, vech, do_combine,
                      do_err);
        return;
    }
    if (matvec_gate(expected)) return;
    const int bid = blockIdx.x - NCOMB;
    const int cs = bid & (CS - 1);
    const int rb = bid / CS;
    const int warp = threadIdx.x >> 5;
    const int lane = threadIdx.x & 31;
    const int rbase = rb * RPB + warp * 4;
    const int col0 = cs * CHUNK + lane * 16;

    const float4* bv = (const float4*)(vecf + col0);
    float4 b0 = bv[0], b1 = bv[1], b2 = bv[2], b3 = bv[3];

    const __half* kr = K + (size_t)rbase * MP + col0;
    float a0 = 0.f, a1 = 0.f, a2 = 0.f, a3 = 0.f;
    {
        uint4 u0 = __ldcg((const uint4*)kr);
        uint4 u1 = __ldcg((const uint4*)kr + 1);
        HQ_FMA(u0, b0, b1, a0); HQ_FMA(u1, b2, b3, a0);
    }
    {
        uint4 u0 = __ldcg((const uint4*)(kr + MP));
        uint4 u1 = __ldcg((const uint4*)(kr + MP) + 1);
        HQ_FMA(u0, b0, b1, a1); HQ_FMA(u1, b2, b3, a1);
    }
    {
        uint4 u0 = __ldcg((const uint4*)(kr + 2 * MP));
        uint4 u1 = __ldcg((const uint4*)(kr + 2 * MP) + 1);
        HQ_FMA(u0, b0, b1, a2); HQ_FMA(u1, b2, b3, a2);
    }
    {
        uint4 u0 = __ldcg((const uint4*)(kr + 3 * MP));
        uint4 u1 = __ldcg((const uint4*)(kr + 3 * MP) + 1);
        HQ_FMA(u0, b0, b1, a3); HQ_FMA(u1, b2, b3, a3);
    }

    #pragma unroll
    for (int o = 16; o; o >>= 1) {
        a0 += __shfl_xor_sync(0xffffffffu, a0, o);
        a1 += __shfl_xor_sync(0xffffffffu, a1, o);
        a2 += __shfl_xor_sync(0xffffffffu, a2, o);
        a3 += __shfl_xor_sync(0xffffffffu, a3, o);
    }
    if (lane == 0) {
        part_out[(rbase + 0) * CS + cs] = a0;
        part_out[(rbase + 1) * CS + cs] = a1;
        part_out[(rbase + 2) * CS + cs] = a2;
        part_out[(rbase + 3) * CS + cs] = a3;
    }
}

// Final b combine after the loop (fp16-phase partials).
__global__ __launch_bounds__(256) void combine_b_final(
    const float* __restrict__ q, float cscale)
{
    const int i = blockIdx.x * 256 + threadIdx.x;
    float s = combine16(g_pb, i);
    g_b[i] = __fdividef(q[i] * cscale, s);
}

// ---------------------------------------------------------------------------
// T = a * (K1/2^16) * b; cost term = T * C with C = EPS*(ln 2^16 - ln K1).
__global__ __launch_bounds__(256) void finalize_T(float* __restrict__ Tout,
                                                  int write_T)
{
    const size_t e0 = ((size_t)blockIdx.x * 4096) + (size_t)threadIdx.x * 16;
    const int i = (int)(e0 >> 13);
    const float ai = g_a[i] * INV_SCALE_F;
    float cs = 0.f;

    #pragma unroll
    for (int g = 0; g < 4; ++g) {
        const size_t e = e0 + g * 4;
        const int j = (int)(e & 8191);
        uint2 kv2 = *reinterpret_cast<const uint2*>(g_K1 + e);
        __half2 h0 = *reinterpret_cast<__half2*>(&kv2.x);
        __half2 h1 = *reinterpret_cast<__half2*>(&kv2.y);
        float2 f0 = __half22float2(h0);
        float2 f1 = __half22float2(h1);
        const float4 bv = *reinterpret_cast<const float4*>(g_b + j);

        float t0 = ai * f0.x * bv.x;
        float t1 = ai * f0.y * bv.y;
        float t2 = ai * f1.x * bv.z;
        float t3 = ai * f1.y * bv.w;

        if (f0.x > 0.f) cs = fmaf(t0, EPSV * (LOG_SCALE_F - __logf(f0.x)), cs);
        if (f0.y > 0.f) cs = fmaf(t1, EPSV * (LOG_SCALE_F - __logf(f0.y)), cs);
        if (f1.x > 0.f) cs = fmaf(t2, EPSV * (LOG_SCALE_F - __logf(f1.x)), cs);
        if (f1.y > 0.f) cs = fmaf(t3, EPSV * (LOG_SCALE_F - __logf(f1.y)), cs);

        if (write_T) {
            if ((((uintptr_t)Tout) & 15) == 0) {
                *reinterpret_cast<float4*>(Tout + e) = make_float4(t0, t1, t2, t3);
            } else {
                Tout[e + 0] = t0;
                Tout[e + 1] = t1;
                Tout[e + 2] = t2;
                Tout[e + 3] = t3;
            }
        }
    }

    __shared__ float sd[256];
    sd[threadIdx.x] = cs;
    __syncthreads();
    for (int o = 128; o; o >>= 1) {
        if (threadIdx.x < o) sd[threadIdx.x] += sd[threadIdx.x + o];
        __syncthreads();
    }
    if (threadIdx.x == 0) g_part[blockIdx.x] = sd[0];
}

__global__ __launch_bounds__(256) void reduce_cost(float* __restrict__ cost_out)
{
    __shared__ double sd[256];
    double s = 0.0;
    for (int i = threadIdx.x; i < 16384; i += 256) s += (double)g_part[i];
    sd[threadIdx.x] = s;
    __syncthreads();
    for (int o = 128; o; o >>= 1) {
        if (threadIdx.x < o) sd[threadIdx.x] += sd[threadIdx.x + o];
        __syncthreads();
    }
    if (threadIdx.x == 0) cost_out[0] = (float)sd[0];
}

// ---------------------------------------------------------------------------
#define LAUNCH_PDL(func, grid, ...)                                            \
    do {                                                                       \
        cudaLaunchConfig_t cfg_ = {};                                          \
        cfg_.gridDim = dim3(grid);                                             \
        cfg_.blockDim = dim3(256);                                             \
        cfg_.stream = 0;                                                       \
        cudaLaunchAttribute at_[1];                                            \
        at_[0].id = cudaLaunchAttributeProgrammaticStreamSerialization;        \
        at_[0].val.programmaticStreamSerializationAllowed = 1;                 \
        cfg_.attrs = at_;                                                      \
        cfg_.numAttrs = 1;                                                     \
        cudaLaunchKernelEx(&cfg_, func, __VA_ARGS__);                          \
    } while (0)

extern "C" void kernel_launch(void* const* d_in, const int* in_sizes, int n_in,
                              void* d_out, int out_size)
{
    const float* x = (const float*)d_in[0];
    const float* y = (const float*)d_in[1];
    const float* p = (const float*)d_in[2];
    const float* q = (const float*)d_in[3];
    float* out = (float*)d_out;

    void *k1p, *k1tp, *k8p, *k8tp, *ap, *bp, *ahp, *bhp, *pap, *pbp;
    cudaGetSymbolAddress(&k1p, g_K1);
    cudaGetSymbolAddress(&k1tp, g_K1T);
    cudaGetSymbolAddress(&k8p, g_K8);
    cudaGetSymbolAddress(&k8tp, g_K8T);
    cudaGetSymbolAddress(&ap, g_a);
    cudaGetSymbolAddress(&bp, g_b);
    cudaGetSymbolAddress(&ahp, g_ah);
    cudaGetSymbolAddress(&bhp, g_bh);
    cudaGetSymbolAddress(&pap, g_pa);
    cudaGetSymbolAddress(&pbp, g_pb);

    sink_init<<<32, 256>>>();
    dim3 bgrid(MP / 64, NP / 64);
    build_K<<<bgrid, 256>>>(x, y);

    const int grid = NCOMB + (NP / RPB) * CS; // 32 + 4096
    unsigned seq = 0;
    for (int it = 0; it < TOTAL_ITERS; ++it) {
        const bool f8_cur = it < FP8_ITERS;
        const bool f8_prev = (it - 1) < FP8_ITERS;
        // P_a: combine b (prev pass partials, prev-phase scale) + a-matvec
        const float cscale_b = f8_prev ? AH_SCALE : SCALE_F;
        ++seq;
        if (f8_cur)
            LAUNCH_PDL(fused8, grid, (const uint8_t*)k8p, (float*)pap,
                       (const float*)pbp, q, cscale_b, 1.0f, (float*)bp,
                       (__half*)bhp, it > 0 ? 1 : 0, 1, NCOMB * seq);
        else
            LAUNCH_PDL(fused16, grid, (const __half*)k1p, (float*)pap,
                       (const float*)pbp, q, cscale_b, 1.0f, (float*)bp,
                       (__half*)bhp, 1, 1, NCOMB * seq);
        // P_b: combine a (this pass's partials, cur-phase scale) + b-matvec
        const float cscale_a = f8_cur ? 1.0f : SCALE_F;
        ++seq;
        if (f8_cur)
            LAUNCH_PDL(fused8, grid, (const uint8_t*)k8tp, (float*)pbp,
                       (const float*)pap, p, cscale_a, AH_SCALE, (float*)ap,
                       (__half*)ahp, 1, 0, NCOMB * seq);
        else
            LAUNCH_PDL(fused16, grid, (const __half*)k1tp, (float*)pbp,
                       (const float*)pap, p, cscale_a, AH_SCALE, (float*)ap,
                       (__half*)ahp, 1, 0, NCOMB * seq);
    }
    combine_b_final<<<NCOMB, 256>>>(q, SCALE_F);

    const long long total = (long long)NP * MP;
    if ((long long)out_size == total + 1) {
        finalize_T<<<16384, 256>>>(out + 1, 1);
        reduce_cost<<<1, 256>>>(out);
    } else if ((long long)out_size == total) {
        finalize_T<<<16384, 256>>>(out, 1);
    } else if ((long long)out_size > total) {
        finalize_T<<<16384, 256>>>(out + (out_size - total), 1);
        reduce_cost<<<1, 256>>>(out);
    } else {
        finalize_T<<<16384, 256>>>(nullptr, 0);
        reduce_cost<<<1, 256>>>(out);
    }
}

// round 10
// speedup vs baseline: 1.1811x; 1.1811x over previous
#include <cuda_runtime.h>
#include <cuda_fp16.h>
#include <cuda_fp8.h>
#include <math.h>
#include <stdint.h>

#define NP 8192
#define MP 8192
#define DIMS 32
#define EPSV 10.0f
#define THRESH2 (1e-5f * 1e-5f)
#define FP8_ITERS 24
#define TOTAL_ITERS 30 /* 24 fp8 + 6 fp16 polish (validated by R9 numerics) */
#define SCALE_F 65536.0f
#define INV_SCALE_F (1.0f / 65536.0f)
#define LOG_SCALE_F 11.090354888959125f /* ln(65536) */
#define CS 16
#define CHUNK (MP / CS) /* 512 */
#define RPB 32
#define AH_SCALE 1024.0f

// PDL: allow dependents to launch early; wait gates on predecessor completion.
#define PDL_TOP()                                                              \
    do {                                                                       \
        asm volatile("griddepcontrol.launch_dependents;" ::: "memory");        \
        asm volatile("griddepcontrol.wait;" ::: "memory");                     \
    } while (0)

__device__ __half   g_K1[(size_t)NP * MP];
__device__ __half   g_K1T[(size_t)NP * MP];
__device__ uint8_t  g_K8[(size_t)NP * MP];
__device__ uint8_t  g_K8T[(size_t)NP * MP];
__device__ float  g_a[NP];
__device__ float  g_b[MP];
__device__ __half g_ah[NP]; // a * 1024 in half (fp8 passB input)
__device__ __half g_bh[MP]; // b in half (fp8 passA input)
__device__ float  g_pa[NP * CS]; // partials, layout [row][cs]
__device__ float  g_pb[MP * CS];
__device__ float  g_errp[32]; // per-block err^2 partials (sticky freeze)
__device__ float  g_part[16384];

// Sticky freeze: err of the last completed b-update, summed deterministically.
__device__ __forceinline__ bool frozen()
{
    float v = g_errp[threadIdx.x & 31];
    #pragma unroll
    for (int o = 16; o; o >>= 1) v += __shfl_xor_sync(0xffffffffu, v, o);
    return v < THRESH2;
}

// ---------------------------------------------------------------------------
__global__ void sink_init()
{
    int i = blockIdx.x * 256 + threadIdx.x;
    if (i < MP) { g_b[i] = 1.0f; g_bh[i] = __float2half_rn(1.0f); }
    if (i < 32) g_errp[i] = 1e30f;
}

// ---------------------------------------------------------------------------
// Build: e = exp(-max(C,0)/EPS). Store e*2^16 as fp16 (K1 + K1T) and e*2^8
// as fp8 e4m3 (K8 + K8T). 64x64 tile per block.
__global__ __launch_bounds__(256) void build_K(const float* __restrict__ x,
                                               const float* __restrict__ y)
{
    __shared__ float sx[64][DIMS + 1];
    __shared__ float sy[64][DIMS + 1];
    __shared__ float sx2[64];
    __shared__ float sy2[64];
    __shared__ __half  stile[64][65];
    __shared__ uint8_t s8tile[64][68];

    const int tid = threadIdx.x;
    const int I0 = blockIdx.y * 64;
    const int J0 = blockIdx.x * 64;

    for (int idx = tid; idx < 64 * DIMS; idx += 256) {
        int r = idx >> 5, k = idx & 31;
        sx[r][k] = x[(I0 + r) * DIMS + k];
        sy[r][k] = y[(J0 + r) * DIMS + k];
    }
    __syncthreads();
    if (tid < 64) {
        float s = 0.f;
        #pragma unroll
        for (int k = 0; k < DIMS; k++) { float v = sx[tid][k]; s = fmaf(v, v, s); }
        sx2[tid] = s;
    } else if (tid < 128) {
        int r = tid - 64;
        float s = 0.f;
        #pragma unroll
        for (int k = 0; k < DIMS; k++) { float v = sy[r][k]; s = fmaf(v, v, s); }
        sy2[r] = s;
    }
    __syncthreads();

    const int ty = tid >> 4, tx = tid & 15;
    const int r0 = ty * 4, c0 = tx * 4;
    float acc[4][4];
    #pragma unroll
    for (int i = 0; i < 4; i++)
        #pragma unroll
        for (int j = 0; j < 4; j++) acc[i][j] = 0.f;

    #pragma unroll
    for (int k = 0; k < DIMS; k++) {
        float a0 = sx[r0 + 0][k], a1 = sx[r0 + 1][k];
        float a2 = sx[r0 + 2][k], a3 = sx[r0 + 3][k];
        float b0 = sy[c0 + 0][k], b1 = sy[c0 + 1][k];
        float b2 = sy[c0 + 2][k], b3 = sy[c0 + 3][k];
        acc[0][0] = fmaf(a0, b0, acc[0][0]); acc[0][1] = fmaf(a0, b1, acc[0][1]);
        acc[0][2] = fmaf(a0, b2, acc[0][2]); acc[0][3] = fmaf(a0, b3, acc[0][3]);
        acc[1][0] = fmaf(a1, b0, acc[1][0]); acc[1][1] = fmaf(a1, b1, acc[1][1]);
        acc[1][2] = fmaf(a1, b2, acc[1][2]); acc[1][3] = fmaf(a1, b3, acc[1][3]);
        acc[2][0] = fmaf(a2, b0, acc[2][0]); acc[2][1] = fmaf(a2, b1, acc[2][1]);
        acc[2][2] = fmaf(a2, b2, acc[2][2]); acc[2][3] = fmaf(a2, b3, acc[2][3]);
        acc[3][0] = fmaf(a3, b0, acc[3][0]); acc[3][1] = fmaf(a3, b1, acc[3][1]);
        acc[3][2] = fmaf(a3, b2, acc[3][2]); acc[3][3] = fmaf(a3, b3, acc[3][3]);
    }

    #pragma unroll
    for (int i = 0; i < 4; i++) {
        #pragma unroll
        for (int j = 0; j < 4; j++) {
            float C = sx2[r0 + i] + sy2[c0 + j] - 2.f * acc[i][j];
            C = fmaxf(C, 0.f);
            float e16 = exp2f(fmaf(C, -0.14426950408889634f, 16.0f));
            stile[r0 + i][c0 + j] = __float2half_rn(fminf(e16, 65504.f));
            s8tile[r0 + i][c0 + j] = (uint8_t)__nv_cvt_float_to_fp8(
                e16 * 0.00390625f, __NV_SATFINITE, __NV_E4M3);
        }
    }
    __syncthreads();

    for (int idx = tid; idx < 4096; idx += 256) {
        int r = idx >> 6, c = idx & 63;
        g_K1[(size_t)(I0 + r) * MP + (J0 + c)] = stile[r][c];
        g_K1T[(size_t)(J0 + r) * NP + (I0 + c)] = stile[c][r];
    }
    for (int idx = tid; idx < 1024; idx += 256) {
        int r = idx >> 4, c4 = (idx & 15) * 4;
        uchar4 v;
        v.x = s8tile[r][c4 + 0]; v.y = s8tile[r][c4 + 1];
        v.z = s8tile[r][c4 + 2]; v.w = s8tile[r][c4 + 3];
        *(uchar4*)(g_K8 + (size_t)(I0 + r) * MP + (J0 + c4)) = v;
        uchar4 t;
        t.x = s8tile[c4 + 0][r]; t.y = s8tile[c4 + 1][r];
        t.z = s8tile[c4 + 2][r]; t.w = s8tile[c4 + 3][r];
        *(uchar4*)(g_K8T + (size_t)(J0 + r) * NP + (I0 + c4)) = t;
    }
}

// ---------------------------------------------------------------------------
// ALU-side e4m3 -> fp16 decode (non-negative values; exact 2^-8 scale folded
// into the combine scale; exact for subnormals).
__device__ __forceinline__ __half2 dec8(uint32_t w, uint32_t sel)
{
    uint32_t r = (__byte_perm(w, 0u, sel) >> 1) & 0x7F807F80u;
    return *reinterpret_cast<__half2*>(&r);
}

__device__ __forceinline__ float row16_fp8(uint4 u, uint4 bA, uint4 bB)
{
    const __half2* ba = reinterpret_cast<const __half2*>(&bA);
    const __half2* bb = reinterpret_cast<const __half2*>(&bB);
    __half2 acc = __hmul2(dec8(u.x, 0x1404u), ba[0]);
    acc = __hfma2(dec8(u.x, 0x3424u), ba[1], acc);
    acc = __hfma2(dec8(u.y, 0x1404u), ba[2], acc);
    acc = __hfma2(dec8(u.y, 0x3424u), ba[3], acc);
    acc = __hfma2(dec8(u.z, 0x1404u), bb[0], acc);
    acc = __hfma2(dec8(u.z, 0x3424u), bb[1], acc);
    acc = __hfma2(dec8(u.w, 0x1404u), bb[2], acc);
    acc = __hfma2(dec8(u.w, 0x3424u), bb[3], acc);
    float2 f = __half22float2(acc);
    return f.x + f.y;
}

// fp8 GEMV partial: tile = 32 rows x 512 cols (16KB). warp = 4 rows,
// lane = 16 cols. Partials stored transposed: part[row*CS + cs].
__global__ __launch_bounds__(256) void sink_pass8(
    const uint8_t* __restrict__ K8, const __half* __restrict__ vin_h,
    float* __restrict__ part_out)
{
    PDL_TOP();
    if (frozen()) return;
    const int cs = blockIdx.x & (CS - 1);
    const int rb = blockIdx.x / CS;
    const int warp = threadIdx.x >> 5;
    const int lane = threadIdx.x & 31;
    const int rbase = rb * RPB + warp * 4;
    const int col0 = cs * CHUNK + lane * 16;

    const uint4* bhp = (const uint4*)(vin_h + col0);
    uint4 bA = bhp[0], bB = bhp[1];

    const size_t base = (size_t)rbase * MP + col0;
    uint4 u0 = __ldcg((const uint4*)(K8 + base));
    uint4 u1 = __ldcg((const uint4*)(K8 + base + MP));
    uint4 u2 = __ldcg((const uint4*)(K8 + base + 2 * MP));
    uint4 u3 = __ldcg((const uint4*)(K8 + base + 3 * MP));

    float a0 = row16_fp8(u0, bA, bB);
    float a1 = row16_fp8(u1, bA, bB);
    float a2 = row16_fp8(u2, bA, bB);
    float a3 = row16_fp8(u3, bA, bB);

    #pragma unroll
    for (int o = 16; o; o >>= 1) {
        a0 += __shfl_xor_sync(0xffffffffu, a0, o);
        a1 += __shfl_xor_sync(0xffffffffu, a1, o);
        a2 += __shfl_xor_sync(0xffffffffu, a2, o);
        a3 += __shfl_xor_sync(0xffffffffu, a3, o);
    }
    if (lane == 0) {
        part_out[(rbase + 0) * CS + cs] = a0;
        part_out[(rbase + 1) * CS + cs] = a1;
        part_out[(rbase + 2) * CS + cs] = a2;
        part_out[(rbase + 3) * CS + cs] = a3;
    }
}

// ---------------------------------------------------------------------------
// fp16 GEMV partial (polish). Same tiling, f32 input vector.
#define HQ_FMA(u, bA, bB, acc)                                                 \
    {                                                                          \
        float2 f0_ = __half22float2(*reinterpret_cast<__half2*>(&(u).x));      \
        float2 f1_ = __half22float2(*reinterpret_cast<__half2*>(&(u).y));      \
        float2 f2_ = __half22float2(*reinterpret_cast<__half2*>(&(u).z));      \
        float2 f3_ = __half22float2(*reinterpret_cast<__half2*>(&(u).w));      \
        acc = fmaf(f0_.x, (bA).x, acc); acc = fmaf(f0_.y, (bA).y, acc);        \
        acc = fmaf(f1_.x, (bA).z, acc); acc = fmaf(f1_.y, (bA).w, acc);        \
        acc = fmaf(f2_.x, (bB).x, acc); acc = fmaf(f2_.y, (bB).y, acc);        \
        acc = fmaf(f3_.x, (bB).z, acc); acc = fmaf(f3_.y, (bB).w, acc);        \
    }

__global__ __launch_bounds__(256) void sink_pass16(
    const __half* __restrict__ K, const float* __restrict__ vin,
    float* __restrict__ part_out)
{
    PDL_TOP();
    if (frozen()) return;
    const int cs = blockIdx.x & (CS - 1);
    const int rb = blockIdx.x / CS;
    const int warp = threadIdx.x >> 5;
    const int lane = threadIdx.x & 31;
    const int rbase = rb * RPB + warp * 4;
    const int col0 = cs * CHUNK + lane * 16;

    const float4* bv = (const float4*)(vin + col0);
    float4 b0 = bv[0], b1 = bv[1], b2 = bv[2], b3 = bv[3];

    const __half* kr = K + (size_t)rbase * MP + col0;
    float a0 = 0.f, a1 = 0.f, a2 = 0.f, a3 = 0.f;
    {
        uint4 u0 = __ldcg((const uint4*)kr);
        uint4 u1 = __ldcg((const uint4*)kr + 1);
        HQ_FMA(u0, b0, b1, a0); HQ_FMA(u1, b2, b3, a0);
    }
    {
        uint4 u0 = __ldcg((const uint4*)(kr + MP));
        uint4 u1 = __ldcg((const uint4*)(kr + MP) + 1);
        HQ_FMA(u0, b0, b1, a1); HQ_FMA(u1, b2, b3, a1);
    }
    {
        uint4 u0 = __ldcg((const uint4*)(kr + 2 * MP));
        uint4 u1 = __ldcg((const uint4*)(kr + 2 * MP) + 1);
        HQ_FMA(u0, b0, b1, a2); HQ_FMA(u1, b2, b3, a2);
    }
    {
        uint4 u0 = __ldcg((const uint4*)(kr + 3 * MP));
        uint4 u1 = __ldcg((const uint4*)(kr + 3 * MP) + 1);
        HQ_FMA(u0, b0, b1, a3); HQ_FMA(u1, b2, b3, a3);
    }

    #pragma unroll
    for (int o = 16; o; o >>= 1) {
        a0 += __shfl_xor_sync(0xffffffffu, a0, o);
        a1 += __shfl_xor_sync(0xffffffffu, a1, o);
        a2 += __shfl_xor_sync(0xffffffffu, a2, o);
        a3 += __shfl_xor_sync(0xffffffffu, a3, o);
    }
    if (lane == 0) {
        part_out[(rbase + 0) * CS + cs] = a0;
        part_out[(rbase + 1) * CS + cs] = a1;
        part_out[(rbase + 2) * CS + cs] = a2;
        part_out[(rbase + 3) * CS + cs] = a3;
    }
}

// ---------------------------------------------------------------------------
__device__ __forceinline__ float combine16(const float* __restrict__ part,
                                           int i)
{
    const float4* p4 = (const float4*)(part + i * CS);
    float4 q0 = p4[0], q1 = p4[1], q2 = p4[2], q3 = p4[3];
    return ((q0.x + q0.y) + (q0.z + q0.w)) + ((q1.x + q1.y) + (q1.z + q1.w)) +
           ((q2.x + q2.y) + (q2.z + q2.w)) + ((q3.x + q3.y) + (q3.z + q3.w));
}

__global__ __launch_bounds__(256) void sink_combine_a(
    const float* __restrict__ p, float scale, float hscale)
{
    PDL_TOP();
    if (frozen()) return;
    const int i = blockIdx.x * 256 + threadIdx.x;
    float s = combine16(g_pa, i);
    float av = __fdividef(p[i] * scale, s);
    g_a[i] = av;
    g_ah[i] = __float2half_rn(av * hscale);
}

// 32-block b combine: update b (+half copy) and write per-block err^2 partial.
__global__ __launch_bounds__(256) void sink_combine_b(
    const float* __restrict__ q, float scale)
{
    PDL_TOP();
    if (frozen()) return;
    const int i = blockIdx.x * 256 + threadIdx.x;
    float s = combine16(g_pb, i);
    float bn = __fdividef(q[i] * scale, s);
    float d = bn - g_b[i];
    g_b[i] = bn;
    g_bh[i] = __float2half_rn(bn);

    __shared__ float sd[256];
    sd[threadIdx.x] = d * d;
    __syncthreads();
    for (int o = 128; o; o >>= 1) {
        if (threadIdx.x < o) sd[threadIdx.x] += sd[threadIdx.x + o];
        __syncthreads();
    }
    if (threadIdx.x == 0) g_errp[blockIdx.x] = sd[0];
}

// ---------------------------------------------------------------------------
// T = a * (K1/2^16) * b; cost term = T * C with C = EPS*(ln 2^16 - ln K1).
__global__ __launch_bounds__(256) void finalize_T(float* __restrict__ Tout,
                                                  int write_T)
{
    const size_t e0 = ((size_t)blockIdx.x * 4096) + (size_t)threadIdx.x * 16;
    const int i = (int)(e0 >> 13);
    const float ai = g_a[i] * INV_SCALE_F;
    float cs = 0.f;

    #pragma unroll
    for (int g = 0; g < 4; ++g) {
        const size_t e = e0 + g * 4;
        const int j = (int)(e & 8191);
        uint2 kv2 = *reinterpret_cast<const uint2*>(g_K1 + e);
        __half2 h0 = *reinterpret_cast<__half2*>(&kv2.x);
        __half2 h1 = *reinterpret_cast<__half2*>(&kv2.y);
        float2 f0 = __half22float2(h0);
        float2 f1 = __half22float2(h1);
        const float4 bv = *reinterpret_cast<const float4*>(g_b + j);

        float t0 = ai * f0.x * bv.x;
        float t1 = ai * f0.y * bv.y;
        float t2 = ai * f1.x * bv.z;
        float t3 = ai * f1.y * bv.w;

        if (f0.x > 0.f) cs = fmaf(t0, EPSV * (LOG_SCALE_F - __logf(f0.x)), cs);
        if (f0.y > 0.f) cs = fmaf(t1, EPSV * (LOG_SCALE_F - __logf(f0.y)), cs);
        if (f1.x > 0.f) cs = fmaf(t2, EPSV * (LOG_SCALE_F - __logf(f1.x)), cs);
        if (f1.y > 0.f) cs = fmaf(t3, EPSV * (LOG_SCALE_F - __logf(f1.y)), cs);

        if (write_T) {
            if ((((uintptr_t)Tout) & 15) == 0) {
                *reinterpret_cast<float4*>(Tout + e) = make_float4(t0, t1, t2, t3);
            } else {
                Tout[e + 0] = t0;
                Tout[e + 1] = t1;
                Tout[e + 2] = t2;
                Tout[e + 3] = t3;
            }
        }
    }

    __shared__ float sd[256];
    sd[threadIdx.x] = cs;
    __syncthreads();
    for (int o = 128; o; o >>= 1) {
        if (threadIdx.x < o) sd[threadIdx.x] += sd[threadIdx.x + o];
        __syncthreads();
    }
    if (threadIdx.x == 0) g_part[blockIdx.x] = sd[0];
}

__global__ __launch_bounds__(256) void reduce_cost(float* __restrict__ cost_out)
{
    __shared__ double sd[256];
    double s = 0.0;
    for (int i = threadIdx.x; i < 16384; i += 256) s += (double)g_part[i];
    sd[threadIdx.x] = s;
    __syncthreads();
    for (int o = 128; o; o >>= 1) {
        if (threadIdx.x < o) sd[threadIdx.x] += sd[threadIdx.x + o];
        __syncthreads();
    }
    if (threadIdx.x == 0) cost_out[0] = (float)sd[0];
}

// ---------------------------------------------------------------------------
#define LAUNCH_PDL(func, grid, ...)                                            \
    do {                                                                       \
        cudaLaunchConfig_t cfg_ = {};                                          \
        cfg_.gridDim = dim3(grid);                                             \
        cfg_.blockDim = dim3(256);                                             \
        cfg_.stream = 0;                                                       \
        cudaLaunchAttribute at_[1];                                            \
        at_[0].id = cudaLaunchAttributeProgrammaticStreamSerialization;        \
        at_[0].val.programmaticStreamSerializationAllowed = 1;                 \
        cfg_.attrs = at_;                                                      \
        cfg_.numAttrs = 1;                                                     \
        cudaLaunchKernelEx(&cfg_, func, __VA_ARGS__);                          \
    } while (0)

extern "C" void kernel_launch(void* const* d_in, const int* in_sizes, int n_in,
                              void* d_out, int out_size)
{
    const float* x = (const float*)d_in[0];
    const float* y = (const float*)d_in[1];
    const float* p = (const float*)d_in[2];
    const float* q = (const float*)d_in[3];
    float* out = (float*)d_out;

    void *k1p, *k1tp, *k8p, *k8tp, *ap, *bp, *ahp, *bhp, *pap, *pbp;
    cudaGetSymbolAddress(&k1p, g_K1);
    cudaGetSymbolAddress(&k1tp, g_K1T);
    cudaGetSymbolAddress(&k8p, g_K8);
    cudaGetSymbolAddress(&k8tp, g_K8T);
    cudaGetSymbolAddress(&ap, g_a);
    cudaGetSymbolAddress(&bp, g_b);
    cudaGetSymbolAddress(&ahp, g_ah);
    cudaGetSymbolAddress(&bhp, g_bh);
    cudaGetSymbolAddress(&pap, g_pa);
    cudaGetSymbolAddress(&pbp, g_pb);

    sink_init<<<32, 256>>>();
    dim3 bgrid(MP / 64, NP / 64);
    build_K<<<bgrid, 256>>>(x, y);

    const int mv_grid = (NP / RPB) * CS; // 4096
    for (int it = 0; it < TOTAL_ITERS; ++it) {
        if (it < FP8_ITERS) {
            LAUNCH_PDL(sink_pass8, mv_grid, (const uint8_t*)k8p,
                       (const __half*)bhp, (float*)pap);
            LAUNCH_PDL(sink_combine_a, NP / 256, p, 1.0f, AH_SCALE);
            LAUNCH_PDL(sink_pass8, mv_grid, (const uint8_t*)k8tp,
                       (const __half*)ahp, (float*)pbp);
            LAUNCH_PDL(sink_combine_b, MP / 256, q, 1024.0f);
        } else {
            LAUNCH_PDL(sink_pass16, mv_grid, (const __half*)k1p,
                       (const float*)bp, (float*)pap);
            LAUNCH_PDL(sink_combine_a, NP / 256, p, SCALE_F, AH_SCALE);
            LAUNCH_PDL(sink_pass16, mv_grid, (const __half*)k1tp,
                       (const float*)ap, (float*)pbp);
            LAUNCH_PDL(sink_combine_b, MP / 256, q, SCALE_F);
        }
    }

    const long long total = (long long)NP * MP;
    if ((long long)out_size == total + 1) {
        finalize_T<<<16384, 256>>>(out + 1, 1);
        reduce_cost<<<1, 256>>>(out);
    } else if ((long long)out_size == total) {
        finalize_T<<<16384, 256>>>(out, 1);
    } else if ((long long)out_size > total) {
        finalize_T<<<16384, 256>>>(out + (out_size - total), 1);
        reduce_cost<<<1, 256>>>(out);
    } else {
        finalize_T<<<16384, 256>>>(nullptr, 0);
        reduce_cost<<<1, 256>>>(out);
    }
}

// round 11
// speedup vs baseline: 1.3557x; 1.1478x over previous
#include <cuda_runtime.h>
#include <cuda_fp16.h>
#include <cuda_fp8.h>
#include <math.h>
#include <stdint.h>

#define NP 8192
#define MP 8192
#define DIMS 32
#define EPSV 10.0f
#define THRESH2 (1e-5f * 1e-5f)
#define FP8_ITERS 20
#define TOTAL_ITERS 26 /* 20 fp8 + 6 fp16 polish */
#define SCALE_F 65536.0f
#define INV_SCALE_F (1.0f / 65536.0f)
#define LOG_SCALE_F 11.090354888959125f /* ln(65536) */
#define CS 16
#define CHUNK (MP / CS) /* 512 */
#define RPB 32
#define AH_SCALE 1024.0f

// PDL: allow dependents to launch early; wait gates on predecessor completion.
#define PDL_TOP()                                                              \
    do {                                                                       \
        asm volatile("griddepcontrol.launch_dependents;" ::: "memory");        \
        asm volatile("griddepcontrol.wait;" ::: "memory");                     \
    } while (0)

__device__ __half   g_K1[(size_t)NP * MP];
__device__ __half   g_K1T[(size_t)NP * MP];
__device__ uint8_t  g_K8[(size_t)NP * MP];
__device__ uint8_t  g_K8T[(size_t)NP * MP];
__device__ float  g_a[NP];
__device__ float  g_b[MP];
__device__ __half g_ah[NP]; // a * 1024 in half (fp8 passB input)
__device__ __half g_bh[MP]; // b in half (fp8 passA input)
__device__ float  g_pa[NP * CS]; // partials, layout [row][cs]
__device__ float  g_pb[MP * CS];
__device__ float  g_errp[32]; // per-block err^2 partials (sticky freeze)
__device__ float  g_part[16384];

// Sticky freeze: err of the last completed b-update, summed deterministically.
__device__ __forceinline__ bool frozen()
{
    float v = g_errp[threadIdx.x & 31];
    #pragma unroll
    for (int o = 16; o; o >>= 1) v += __shfl_xor_sync(0xffffffffu, v, o);
    return v < THRESH2;
}

// ---------------------------------------------------------------------------
__global__ void sink_init()
{
    int i = blockIdx.x * 256 + threadIdx.x;
    if (i < MP) { g_b[i] = 1.0f; g_bh[i] = __float2half_rn(1.0f); }
    if (i < 32) g_errp[i] = 1e30f;
}

// ---------------------------------------------------------------------------
// Build: e = exp(-max(C,0)/EPS). Store e*2^16 as fp16 (K1 + K1T) and e*2^8
// as fp8 e4m3 (K8 + K8T). 64x64 tile per block.
__global__ __launch_bounds__(256) void build_K(const float* __restrict__ x,
                                               const float* __restrict__ y)
{
    __shared__ float sx[64][DIMS + 1];
    __shared__ float sy[64][DIMS + 1];
    __shared__ float sx2[64];
    __shared__ float sy2[64];
    __shared__ __half  stile[64][65];
    __shared__ uint8_t s8tile[64][68];

    const int tid = threadIdx.x;
    const int I0 = blockIdx.y * 64;
    const int J0 = blockIdx.x * 64;

    for (int idx = tid; idx < 64 * DIMS; idx += 256) {
        int r = idx >> 5, k = idx & 31;
        sx[r][k] = x[(I0 + r) * DIMS + k];
        sy[r][k] = y[(J0 + r) * DIMS + k];
    }
    __syncthreads();
    if (tid < 64) {
        float s = 0.f;
        #pragma unroll
        for (int k = 0; k < DIMS; k++) { float v = sx[tid][k]; s = fmaf(v, v, s); }
        sx2[tid] = s;
    } else if (tid < 128) {
        int r = tid - 64;
        float s = 0.f;
        #pragma unroll
        for (int k = 0; k < DIMS; k++) { float v = sy[r][k]; s = fmaf(v, v, s); }
        sy2[r] = s;
    }
    __syncthreads();

    const int ty = tid >> 4, tx = tid & 15;
    const int r0 = ty * 4, c0 = tx * 4;
    float acc[4][4];
    #pragma unroll
    for (int i = 0; i < 4; i++)
        #pragma unroll
        for (int j = 0; j < 4; j++) acc[i][j] = 0.f;

    #pragma unroll
    for (int k = 0; k < DIMS; k++) {
        float a0 = sx[r0 + 0][k], a1 = sx[r0 + 1][k];
        float a2 = sx[r0 + 2][k], a3 = sx[r0 + 3][k];
        float b0 = sy[c0 + 0][k], b1 = sy[c0 + 1][k];
        float b2 = sy[c0 + 2][k], b3 = sy[c0 + 3][k];
        acc[0][0] = fmaf(a0, b0, acc[0][0]); acc[0][1] = fmaf(a0, b1, acc[0][1]);
        acc[0][2] = fmaf(a0, b2, acc[0][2]); acc[0][3] = fmaf(a0, b3, acc[0][3]);
        acc[1][0] = fmaf(a1, b0, acc[1][0]); acc[1][1] = fmaf(a1, b1, acc[1][1]);
        acc[1][2] = fmaf(a1, b2, acc[1][2]); acc[1][3] = fmaf(a1, b3, acc[1][3]);
        acc[2][0] = fmaf(a2, b0, acc[2][0]); acc[2][1] = fmaf(a2, b1, acc[2][1]);
        acc[2][2] = fmaf(a2, b2, acc[2][2]); acc[2][3] = fmaf(a2, b3, acc[2][3]);
        acc[3][0] = fmaf(a3, b0, acc[3][0]); acc[3][1] = fmaf(a3, b1, acc[3][1]);
        acc[3][2] = fmaf(a3, b2, acc[3][2]); acc[3][3] = fmaf(a3, b3, acc[3][3]);
    }

    #pragma unroll
    for (int i = 0; i < 4; i++) {
        #pragma unroll
        for (int j = 0; j < 4; j++) {
            float C = sx2[r0 + i] + sy2[c0 + j] - 2.f * acc[i][j];
            C = fmaxf(C, 0.f);
            float e16 = exp2f(fmaf(C, -0.14426950408889634f, 16.0f));
            stile[r0 + i][c0 + j] = __float2half_rn(fminf(e16, 65504.f));
            s8tile[r0 + i][c0 + j] = (uint8_t)__nv_cvt_float_to_fp8(
                e16 * 0.00390625f, __NV_SATFINITE, __NV_E4M3);
        }
    }
    __syncthreads();

    for (int idx = tid; idx < 4096; idx += 256) {
        int r = idx >> 6, c = idx & 63;
        g_K1[(size_t)(I0 + r) * MP + (J0 + c)] = stile[r][c];
        g_K1T[(size_t)(J0 + r) * NP + (I0 + c)] = stile[c][r];
    }
    for (int idx = tid; idx < 1024; idx += 256) {
        int r = idx >> 4, c4 = (idx & 15) * 4;
        uchar4 v;
        v.x = s8tile[r][c4 + 0]; v.y = s8tile[r][c4 + 1];
        v.z = s8tile[r][c4 + 2]; v.w = s8tile[r][c4 + 3];
        *(uchar4*)(g_K8 + (size_t)(I0 + r) * MP + (J0 + c4)) = v;
        uchar4 t;
        t.x = s8tile[c4 + 0][r]; t.y = s8tile[c4 + 1][r];
        t.z = s8tile[c4 + 2][r]; t.w = s8tile[c4 + 3][r];
        *(uchar4*)(g_K8T + (size_t)(J0 + r) * NP + (I0 + c4)) = t;
    }
}

// ---------------------------------------------------------------------------
// ALU-side e4m3 -> fp16 decode (non-negative values; exact 2^-8 scale folded
// into the combine scale; exact for subnormals).
__device__ __forceinline__ __half2 dec8(uint32_t w, uint32_t sel)
{
    uint32_t r = (__byte_perm(w, 0u, sel) >> 1) & 0x7F807F80u;
    return *reinterpret_cast<__half2*>(&r);
}

__device__ __forceinline__ float row16_fp8(uint4 u, uint4 bA, uint4 bB)
{
    const __half2* ba = reinterpret_cast<const __half2*>(&bA);
    const __half2* bb = reinterpret_cast<const __half2*>(&bB);
    __half2 acc = __hmul2(dec8(u.x, 0x1404u), ba[0]);
    acc = __hfma2(dec8(u.x, 0x3424u), ba[1], acc);
    acc = __hfma2(dec8(u.y, 0x1404u), ba[2], acc);
    acc = __hfma2(dec8(u.y, 0x3424u), ba[3], acc);
    acc = __hfma2(dec8(u.z, 0x1404u), bb[0], acc);
    acc = __hfma2(dec8(u.z, 0x3424u), bb[1], acc);
    acc = __hfma2(dec8(u.w, 0x1404u), bb[2], acc);
    acc = __hfma2(dec8(u.w, 0x3424u), bb[3], acc);
    float2 f = __half22float2(acc);
    return f.x + f.y;
}

// fp8 GEMV partial: tile = 32 rows x 512 cols (16KB). warp = 4 rows,
// lane = 16 cols. Partials stored transposed: part[row*CS + cs].
// STREAM=false (a-pass on K8): __ldcg, lines persist in L2 (K8 = 64MB fits).
// STREAM=true (b-pass on K8T): __ldcs evict-first so K8 stays L2-resident.
template <bool STREAM>
__global__ __launch_bounds__(256) void sink_pass8(
    const uint8_t* __restrict__ K8, const __half* __restrict__ vin_h,
    float* __restrict__ part_out)
{
    PDL_TOP();
    if (frozen()) return;
    const int cs = blockIdx.x & (CS - 1);
    const int rb = blockIdx.x / CS;
    const int warp = threadIdx.x >> 5;
    const int lane = threadIdx.x & 31;
    const int rbase = rb * RPB + warp * 4;
    const int col0 = cs * CHUNK + lane * 16;

    const uint4* bhp = (const uint4*)(vin_h + col0);
    uint4 bA = bhp[0], bB = bhp[1];

    const size_t base = (size_t)rbase * MP + col0;
    uint4 u0, u1, u2, u3;
    if (STREAM) {
        u0 = __ldcs((const uint4*)(K8 + base));
        u1 = __ldcs((const uint4*)(K8 + base + MP));
        u2 = __ldcs((const uint4*)(K8 + base + 2 * MP));
        u3 = __ldcs((const uint4*)(K8 + base + 3 * MP));
    } else {
        u0 = __ldcg((const uint4*)(K8 + base));
        u1 = __ldcg((const uint4*)(K8 + base + MP));
        u2 = __ldcg((const uint4*)(K8 + base + 2 * MP));
        u3 = __ldcg((const uint4*)(K8 + base + 3 * MP));
    }

    float a0 = row16_fp8(u0, bA, bB);
    float a1 = row16_fp8(u1, bA, bB);
    float a2 = row16_fp8(u2, bA, bB);
    float a3 = row16_fp8(u3, bA, bB);

    #pragma unroll
    for (int o = 16; o; o >>= 1) {
        a0 += __shfl_xor_sync(0xffffffffu, a0, o);
        a1 += __shfl_xor_sync(0xffffffffu, a1, o);
        a2 += __shfl_xor_sync(0xffffffffu, a2, o);
        a3 += __shfl_xor_sync(0xffffffffu, a3, o);
    }
    if (lane == 0) {
        part_out[(rbase + 0) * CS + cs] = a0;
        part_out[(rbase + 1) * CS + cs] = a1;
        part_out[(rbase + 2) * CS + cs] = a2;
        part_out[(rbase + 3) * CS + cs] = a3;
    }
}

// ---------------------------------------------------------------------------
// fp16 GEMV partial (polish). Same tiling, f32 input vector. __ldcs: K1/K1T
// are 128MB each, no reuse possible, keep them out of L2.
#define HQ_FMA(u, bA, bB, acc)                                                 \
    {                                                                          \
        float2 f0_ = __half22float2(*reinterpret_cast<__half2*>(&(u).x));      \
        float2 f1_ = __half22float2(*reinterpret_cast<__half2*>(&(u).y));      \
        float2 f2_ = __half22float2(*reinterpret_cast<__half2*>(&(u).z));      \
        float2 f3_ = __half22float2(*reinterpret_cast<__half2*>(&(u).w));      \
        acc = fmaf(f0_.x, (bA).x, acc); acc = fmaf(f0_.y, (bA).y, acc);        \
        acc = fmaf(f1_.x, (bA).z, acc); acc = fmaf(f1_.y, (bA).w, acc);        \
        acc = fmaf(f2_.x, (bB).x, acc); acc = fmaf(f2_.y, (bB).y, acc);        \
        acc = fmaf(f3_.x, (bB).z, acc); acc = fmaf(f3_.y, (bB).w, acc);        \
    }

__global__ __launch_bounds__(256) void sink_pass16(
    const __half* __restrict__ K, const float* __restrict__ vin,
    float* __restrict__ part_out)
{
    PDL_TOP();
    if (frozen()) return;
    const int cs = blockIdx.x & (CS - 1);
    const int rb = blockIdx.x / CS;
    const int warp = threadIdx.x >> 5;
    const int lane = threadIdx.x & 31;
    const int rbase = rb * RPB + warp * 4;
    const int col0 = cs * CHUNK + lane * 16;

    const float4* bv = (const float4*)(vin + col0);
    float4 b0 = bv[0], b1 = bv[1], b2 = bv[2], b3 = bv[3];

    const __half* kr = K + (size_t)rbase * MP + col0;
    float a0 = 0.f, a1 = 0.f, a2 = 0.f, a3 = 0.f;
    {
        uint4 u0 = __ldcs((const uint4*)kr);
        uint4 u1 = __ldcs((const uint4*)kr + 1);
        HQ_FMA(u0, b0, b1, a0); HQ_FMA(u1, b2, b3, a0);
    }
    {
        uint4 u0 = __ldcs((const uint4*)(kr + MP));
        uint4 u1 = __ldcs((const uint4*)(kr + MP) + 1);
        HQ_FMA(u0, b0, b1, a1); HQ_FMA(u1, b2, b3, a1);
    }
    {
        uint4 u0 = __ldcs((const uint4*)(kr + 2 * MP));
        uint4 u1 = __ldcs((const uint4*)(kr + 2 * MP) + 1);
        HQ_FMA(u0, b0, b1, a2); HQ_FMA(u1, b2, b3, a2);
    }
    {
        uint4 u0 = __ldcs((const uint4*)(kr + 3 * MP));
        uint4 u1 = __ldcs((const uint4*)(kr + 3 * MP) + 1);
        HQ_FMA(u0, b0, b1, a3); HQ_FMA(u1, b2, b3, a3);
    }

    #pragma unroll
    for (int o = 16; o; o >>= 1) {
        a0 += __shfl_xor_sync(0xffffffffu, a0, o);
        a1 += __shfl_xor_sync(0xffffffffu, a1, o);
        a2 += __shfl_xor_sync(0xffffffffu, a2, o);
        a3 += __shfl_xor_sync(0xffffffffu, a3, o);
    }
    if (lane == 0) {
        part_out[(rbase + 0) * CS + cs] = a0;
        part_out[(rbase + 1) * CS + cs] = a1;
        part_out[(rbase + 2) * CS + cs] = a2;
        part_out[(rbase + 3) * CS + cs] = a3;
    }
}

// ---------------------------------------------------------------------------
__device__ __forceinline__ float combine16(const float* __restrict__ part,
                                           int i)
{
    const float4* p4 = (const float4*)(part + i * CS);
    float4 q0 = p4[0], q1 = p4[1], q2 = p4[2], q3 = p4[3];
    return ((q0.x + q0.y) + (q0.z + q0.w)) + ((q1.x + q1.y) + (q1.z + q1.w)) +
           ((q2.x + q2.y) + (q2.z + q2.w)) + ((q3.x + q3.y) + (q3.z + q3.w));
}

__global__ __launch_bounds__(256) void sink_combine_a(
    const float* __restrict__ p, float scale, float hscale)
{
    PDL_TOP();
    if (frozen()) return;
    const int i = blockIdx.x * 256 + threadIdx.x;
    float s = combine16(g_pa, i);
    float av = __fdividef(p[i] * scale, s);
    g_a[i] = av;
    g_ah[i] = __float2half_rn(av * hscale);
}

// 32-block b combine: update b (+half copy) and write per-block err^2 partial.
__global__ __launch_bounds__(256) void sink_combine_b(
    const float* __restrict__ q, float scale)
{
    PDL_TOP();
    if (frozen()) return;
    const int i = blockIdx.x * 256 + threadIdx.x;
    float s = combine16(g_pb, i);
    float bn = __fdividef(q[i] * scale, s);
    float d = bn - g_b[i];
    g_b[i] = bn;
    g_bh[i] = __float2half_rn(bn);

    __shared__ float sd[256];
    sd[threadIdx.x] = d * d;
    __syncthreads();
    for (int o = 128; o; o >>= 1) {
        if (threadIdx.x < o) sd[threadIdx.x] += sd[threadIdx.x + o];
        __syncthreads();
    }
    if (threadIdx.x == 0) g_errp[blockIdx.x] = sd[0];
}

// ---------------------------------------------------------------------------
// T = a * (K1/2^16) * b; cost term = T * C with C = EPS*(ln 2^16 - ln K1).
__global__ __launch_bounds__(256) void finalize_T(float* __restrict__ Tout,
                                                  int write_T)
{
    const size_t e0 = ((size_t)blockIdx.x * 4096) + (size_t)threadIdx.x * 16;
    const int i = (int)(e0 >> 13);
    const float ai = g_a[i] * INV_SCALE_F;
    float cs = 0.f;

    #pragma unroll
    for (int g = 0; g < 4; ++g) {
        const size_t e = e0 + g * 4;
        const int j = (int)(e & 8191);
        uint2 kv2 = *reinterpret_cast<const uint2*>(g_K1 + e);
        __half2 h0 = *reinterpret_cast<__half2*>(&kv2.x);
        __half2 h1 = *reinterpret_cast<__half2*>(&kv2.y);
        float2 f0 = __half22float2(h0);
        float2 f1 = __half22float2(h1);
        const float4 bv = *reinterpret_cast<const float4*>(g_b + j);

        float t0 = ai * f0.x * bv.x;
        float t1 = ai * f0.y * bv.y;
        float t2 = ai * f1.x * bv.z;
        float t3 = ai * f1.y * bv.w;

        if (f0.x > 0.f) cs = fmaf(t0, EPSV * (LOG_SCALE_F - __logf(f0.x)), cs);
        if (f0.y > 0.f) cs = fmaf(t1, EPSV * (LOG_SCALE_F - __logf(f0.y)), cs);
        if (f1.x > 0.f) cs = fmaf(t2, EPSV * (LOG_SCALE_F - __logf(f1.x)), cs);
        if (f1.y > 0.f) cs = fmaf(t3, EPSV * (LOG_SCALE_F - __logf(f1.y)), cs);

        if (write_T) {
            if ((((uintptr_t)Tout) & 15) == 0) {
                *reinterpret_cast<float4*>(Tout + e) = make_float4(t0, t1, t2, t3);
            } else {
                Tout[e + 0] = t0;
                Tout[e + 1] = t1;
                Tout[e + 2] = t2;
                Tout[e + 3] = t3;
            }
        }
    }

    __shared__ float sd[256];
    sd[threadIdx.x] = cs;
    __syncthreads();
    for (int o = 128; o; o >>= 1) {
        if (threadIdx.x < o) sd[threadIdx.x] += sd[threadIdx.x + o];
        __syncthreads();
    }
    if (threadIdx.x == 0) g_part[blockIdx.x] = sd[0];
}

__global__ __launch_bounds__(256) void reduce_cost(float* __restrict__ cost_out)
{
    __shared__ double sd[256];
    double s = 0.0;
    for (int i = threadIdx.x; i < 16384; i += 256) s += (double)g_part[i];
    sd[threadIdx.x] = s;
    __syncthreads();
    for (int o = 128; o; o >>= 1) {
        if (threadIdx.x < o) sd[threadIdx.x] += sd[threadIdx.x + o];
        __syncthreads();
    }
    if (threadIdx.x == 0) cost_out[0] = (float)sd[0];
}

// ---------------------------------------------------------------------------
#define LAUNCH_PDL(func, grid, ...)                                            \
    do {                                                                       \
        cudaLaunchConfig_t cfg_ = {};                                          \
        cfg_.gridDim = dim3(grid);                                             \
        cfg_.blockDim = dim3(256);                                             \
        cfg_.stream = 0;                                                       \
        cudaLaunchAttribute at_[1];                                            \
        at_[0].id = cudaLaunchAttributeProgrammaticStreamSerialization;        \
        at_[0].val.programmaticStreamSerializationAllowed = 1;                 \
        cfg_.attrs = at_;                                                      \
        cfg_.numAttrs = 1;                                                     \
        cudaLaunchKernelEx(&cfg_, func, __VA_ARGS__);                          \
    } while (0)

extern "C" void kernel_launch(void* const* d_in, const int* in_sizes, int n_in,
                              void* d_out, int out_size)
{
    const float* x = (const float*)d_in[0];
    const float* y = (const float*)d_in[1];
    const float* p = (const float*)d_in[2];
    const float* q = (const float*)d_in[3];
    float* out = (float*)d_out;

    void *k1p, *k1tp, *k8p, *k8tp, *ap, *bp, *ahp, *bhp, *pap, *pbp;
    cudaGetSymbolAddress(&k1p, g_K1);
    cudaGetSymbolAddress(&k1tp, g_K1T);
    cudaGetSymbolAddress(&k8p, g_K8);
    cudaGetSymbolAddress(&k8tp, g_K8T);
    cudaGetSymbolAddress(&ap, g_a);
    cudaGetSymbolAddress(&bp, g_b);
    cudaGetSymbolAddress(&ahp, g_ah);
    cudaGetSymbolAddress(&bhp, g_bh);
    cudaGetSymbolAddress(&pap, g_pa);
    cudaGetSymbolAddress(&pbp, g_pb);

    sink_init<<<32, 256>>>();
    dim3 bgrid(MP / 64, NP / 64);
    build_K<<<bgrid, 256>>>(x, y);

    const int mv_grid = (NP / RPB) * CS; // 4096
    for (int it = 0; it < TOTAL_ITERS; ++it) {
        if (it < FP8_ITERS) {
            LAUNCH_PDL(sink_pass8<false>, mv_grid, (const uint8_t*)k8p,
                       (const __half*)bhp, (float*)pap);
            LAUNCH_PDL(sink_combine_a, NP / 256, p, 1.0f, AH_SCALE);
            LAUNCH_PDL(sink_pass8<true>, mv_grid, (const uint8_t*)k8tp,
                       (const __half*)ahp, (float*)pbp);
            LAUNCH_PDL(sink_combine_b, MP / 256, q, 1024.0f);
        } else {
            LAUNCH_PDL(sink_pass16, mv_grid, (const __half*)k1p,
                       (const float*)bp, (float*)pap);
            LAUNCH_PDL(sink_combine_a, NP / 256, p, SCALE_F, AH_SCALE);
            LAUNCH_PDL(sink_pass16, mv_grid, (const __half*)k1tp,
                       (const float*)ap, (float*)pbp);
            LAUNCH_PDL(sink_combine_b, MP / 256, q, SCALE_F);
        }
    }

    const long long total = (long long)NP * MP;
    if ((long long)out_size == total + 1) {
        finalize_T<<<16384, 256>>>(out + 1, 1);
        reduce_cost<<<1, 256>>>(out);
    } else if ((long long)out_size == total) {
        finalize_T<<<16384, 256>>>(out, 1);
    } else if ((long long)out_size > total) {
        finalize_T<<<16384, 256>>>(out + (out_size - total), 1);
        reduce_cost<<<1, 256>>>(out);
    } else {
        finalize_T<<<16384, 256>>>(nullptr, 0);
        reduce_cost<<<1, 256>>>(out);
    }
}

// round 12
// speedup vs baseline: 1.4821x; 1.0933x over previous
#include <cuda_runtime.h>
#include <cuda_fp16.h>
#include <cuda_fp8.h>
#include <math.h>
#include <stdint.h>

#define NP 8192
#define MP 8192
#define DIMS 32
#define EPSV 10.0f
#define THRESH2 (1e-5f * 1e-5f)
#define FP8_ITERS 20
#define TOTAL_ITERS 24 /* 20 fp8 + 4 fp16 polish */
#define SCALE_F 65536.0f
#define INV_SCALE_F (1.0f / 65536.0f)
#define LOG_SCALE_F 11.090354888959125f /* ln(65536) */
#define CS 16
#define CHUNK (MP / CS) /* 512 */
#define RPB 32
#define AH_SCALE 1024.0f

// PDL: allow dependents to launch early; wait gates on predecessor completion.
#define PDL_TOP()                                                              \
    do {                                                                       \
        asm volatile("griddepcontrol.launch_dependents;" ::: "memory");        \
        asm volatile("griddepcontrol.wait;" ::: "memory");                     \
    } while (0)

__device__ __half   g_K1[(size_t)NP * MP];
__device__ __half   g_K1T[(size_t)NP * MP];
__device__ uint8_t  g_K8[(size_t)NP * MP];
__device__ uint8_t  g_K8T[(size_t)NP * MP];
__device__ float  g_a[NP];
__device__ float  g_b[MP];
__device__ __half g_ah[NP]; // a * 1024 in half (fp8 passB input)
__device__ __half g_bh[MP]; // b in half (fp8 passA input)
__device__ float  g_pa[NP * CS]; // partials, layout [row][cs]
__device__ float  g_pb[MP * CS];
__device__ float  g_errp[32]; // per-block err^2 partials (sticky freeze)
__device__ float  g_part[16384];

// Sticky freeze: err of the last completed b-update, summed deterministically.
__device__ __forceinline__ bool frozen()
{
    float v = g_errp[threadIdx.x & 31];
    #pragma unroll
    for (int o = 16; o; o >>= 1) v += __shfl_xor_sync(0xffffffffu, v, o);
    return v < THRESH2;
}

// ---------------------------------------------------------------------------
__global__ void sink_init()
{
    int i = blockIdx.x * 256 + threadIdx.x;
    if (i < MP) { g_b[i] = 1.0f; g_bh[i] = __float2half_rn(1.0f); }
    if (i < 32) g_errp[i] = 1e30f;
}

// ---------------------------------------------------------------------------
// Build: e = exp(-max(C,0)/EPS). K1/K8 written directly from the register
// micro-tile (vector STG); K1T/K8T transposed through padded shared tiles
// and written as STG.128.
__global__ __launch_bounds__(256) void build_K(const float* __restrict__ x,
                                               const float* __restrict__ y)
{
    __shared__ float sx[64][DIMS + 1];
    __shared__ float sy[64][DIMS + 1];
    __shared__ float sx2[64];
    __shared__ float sy2[64];
    __shared__ __half  stile[64][72];  // 144B rows (16B aligned)
    __shared__ uint8_t s8tile[64][80]; // 80B rows (16B aligned)

    const int tid = threadIdx.x;
    const int I0 = blockIdx.y * 64;
    const int J0 = blockIdx.x * 64;

    for (int idx = tid; idx < 64 * DIMS; idx += 256) {
        int r = idx >> 5, k = idx & 31;
        sx[r][k] = x[(I0 + r) * DIMS + k];
        sy[r][k] = y[(J0 + r) * DIMS + k];
    }
    __syncthreads();
    if (tid < 64) {
        float s = 0.f;
        #pragma unroll
        for (int k = 0; k < DIMS; k++) { float v = sx[tid][k]; s = fmaf(v, v, s); }
        sx2[tid] = s;
    } else if (tid < 128) {
        int r = tid - 64;
        float s = 0.f;
        #pragma unroll
        for (int k = 0; k < DIMS; k++) { float v = sy[r][k]; s = fmaf(v, v, s); }
        sy2[r] = s;
    }
    __syncthreads();

    const int ty = tid >> 4, tx = tid & 15;
    const int r0 = ty * 4, c0 = tx * 4;
    float acc[4][4];
    #pragma unroll
    for (int i = 0; i < 4; i++)
        #pragma unroll
        for (int j = 0; j < 4; j++) acc[i][j] = 0.f;

    #pragma unroll
    for (int k = 0; k < DIMS; k++) {
        float a0 = sx[r0 + 0][k], a1 = sx[r0 + 1][k];
        float a2 = sx[r0 + 2][k], a3 = sx[r0 + 3][k];
        float b0 = sy[c0 + 0][k], b1 = sy[c0 + 1][k];
        float b2 = sy[c0 + 2][k], b3 = sy[c0 + 3][k];
        acc[0][0] = fmaf(a0, b0, acc[0][0]); acc[0][1] = fmaf(a0, b1, acc[0][1]);
        acc[0][2] = fmaf(a0, b2, acc[0][2]); acc[0][3] = fmaf(a0, b3, acc[0][3]);
        acc[1][0] = fmaf(a1, b0, acc[1][0]); acc[1][1] = fmaf(a1, b1, acc[1][1]);
        acc[1][2] = fmaf(a1, b2, acc[1][2]); acc[1][3] = fmaf(a1, b3, acc[1][3]);
        acc[2][0] = fmaf(a2, b0, acc[2][0]); acc[2][1] = fmaf(a2, b1, acc[2][1]);
        acc[2][2] = fmaf(a2, b2, acc[2][2]); acc[2][3] = fmaf(a2, b3, acc[2][3]);
        acc[3][0] = fmaf(a3, b0, acc[3][0]); acc[3][1] = fmaf(a3, b1, acc[3][1]);
        acc[3][2] = fmaf(a3, b2, acc[3][2]); acc[3][3] = fmaf(a3, b3, acc[3][3]);
    }

    #pragma unroll
    for (int i = 0; i < 4; i++) {
        __half hrow[4];
        uint8_t brow[4];
        #pragma unroll
        for (int j = 0; j < 4; j++) {
            float C = sx2[r0 + i] + sy2[c0 + j] - 2.f * acc[i][j];
            C = fmaxf(C, 0.f);
            float e16 = exp2f(fmaf(C, -0.14426950408889634f, 16.0f));
            __half h = __float2half_rn(fminf(e16, 65504.f));
            uint8_t b8 = (uint8_t)__nv_cvt_float_to_fp8(
                e16 * 0.00390625f, __NV_SATFINITE, __NV_E4M3);
            hrow[j] = h;
            brow[j] = b8;
            stile[r0 + i][c0 + j] = h;
            s8tile[r0 + i][c0 + j] = b8;
        }
        // Direct row-major stores from registers (8B / 4B vector STG)
        uint2 hw;
        __half2* hwp = reinterpret_cast<__half2*>(&hw);
        hwp[0] = __halves2half2(hrow[0], hrow[1]);
        hwp[1] = __halves2half2(hrow[2], hrow[3]);
        *(uint2*)(g_K1 + (size_t)(I0 + r0 + i) * MP + J0 + c0) = hw;
        uchar4 bw;
        bw.x = brow[0]; bw.y = brow[1]; bw.z = brow[2]; bw.w = brow[3];
        *(uchar4*)(g_K8 + (size_t)(I0 + r0 + i) * MP + J0 + c0) = bw;
    }
    __syncthreads();

    // K1T: each group = 8 contiguous halves (16B) of one transposed row.
    for (int idx = tid; idx < 512; idx += 256) {
        int c = idx >> 3, r8 = (idx & 7) * 8;
        uint4 w;
        __half* hp = reinterpret_cast<__half*>(&w);
        #pragma unroll
        for (int k = 0; k < 8; k++) hp[k] = stile[r8 + k][c];
        *(uint4*)(g_K1T + (size_t)(J0 + c) * NP + I0 + r8) = w;
    }
    // K8T: each group = 16 contiguous bytes of one transposed row.
    {
        int idx = tid;
        if (idx < 256) {
            int c = idx >> 2, r16 = (idx & 3) * 16;
            uint4 w;
            uint8_t* bp = reinterpret_cast<uint8_t*>(&w);
            #pragma unroll
            for (int k = 0; k < 16; k++) bp[k] = s8tile[r16 + k][c];
            *(uint4*)(g_K8T + (size_t)(J0 + c) * NP + I0 + r16) = w;
        }
    }
}

// ---------------------------------------------------------------------------
// ALU-side e4m3 -> fp16 decode (non-negative values; exact 2^-8 scale folded
// into the combine scale; exact for subnormals).
__device__ __forceinline__ __half2 dec8(uint32_t w, uint32_t sel)
{
    uint32_t r = (__byte_perm(w, 0u, sel) >> 1) & 0x7F807F80u;
    return *reinterpret_cast<__half2*>(&r);
}

__device__ __forceinline__ float row16_fp8(uint4 u, uint4 bA, uint4 bB)
{
    const __half2* ba = reinterpret_cast<const __half2*>(&bA);
    const __half2* bb = reinterpret_cast<const __half2*>(&bB);
    __half2 acc = __hmul2(dec8(u.x, 0x1404u), ba[0]);
    acc = __hfma2(dec8(u.x, 0x3424u), ba[1], acc);
    acc = __hfma2(dec8(u.y, 0x1404u), ba[2], acc);
    acc = __hfma2(dec8(u.y, 0x3424u), ba[3], acc);
    acc = __hfma2(dec8(u.z, 0x1404u), bb[0], acc);
    acc = __hfma2(dec8(u.z, 0x3424u), bb[1], acc);
    acc = __hfma2(dec8(u.w, 0x1404u), bb[2], acc);
    acc = __hfma2(dec8(u.w, 0x3424u), bb[3], acc);
    float2 f = __half22float2(acc);
    return f.x + f.y;
}

// fp8 GEMV partial: tile = 32 rows x 512 cols (16KB). warp = 4 rows,
// lane = 16 cols. Partials stored transposed: part[row*CS + cs].
// STREAM=false (a-pass on K8): __ldcg, lines persist in L2 (K8 = 64MB fits).
// STREAM=true (b-pass on K8T): __ldcs evict-first so K8 stays L2-resident.
template <bool STREAM>
__global__ __launch_bounds__(256) void sink_pass8(
    const uint8_t* __restrict__ K8, const __half* __restrict__ vin_h,
    float* __restrict__ part_out)
{
    PDL_TOP();
    if (frozen()) return;
    const int cs = blockIdx.x & (CS - 1);
    const int rb = blockIdx.x / CS;
    const int warp = threadIdx.x >> 5;
    const int lane = threadIdx.x & 31;
    const int rbase = rb * RPB + warp * 4;
    const int col0 = cs * CHUNK + lane * 16;

    const uint4* bhp = (const uint4*)(vin_h + col0);
    uint4 bA = bhp[0], bB = bhp[1];

    const size_t base = (size_t)rbase * MP + col0;
    uint4 u0, u1, u2, u3;
    if (STREAM) {
        u0 = __ldcs((const uint4*)(K8 + base));
        u1 = __ldcs((const uint4*)(K8 + base + MP));
        u2 = __ldcs((const uint4*)(K8 + base + 2 * MP));
        u3 = __ldcs((const uint4*)(K8 + base + 3 * MP));
    } else {
        u0 = __ldcg((const uint4*)(K8 + base));
        u1 = __ldcg((const uint4*)(K8 + base + MP));
        u2 = __ldcg((const uint4*)(K8 + base + 2 * MP));
        u3 = __ldcg((const uint4*)(K8 + base + 3 * MP));
    }

    float a0 = row16_fp8(u0, bA, bB);
    float a1 = row16_fp8(u1, bA, bB);
    float a2 = row16_fp8(u2, bA, bB);
    float a3 = row16_fp8(u3, bA, bB);

    #pragma unroll
    for (int o = 16; o; o >>= 1) {
        a0 += __shfl_xor_sync(0xffffffffu, a0, o);
        a1 += __shfl_xor_sync(0xffffffffu, a1, o);
        a2 += __shfl_xor_sync(0xffffffffu, a2, o);
        a3 += __shfl_xor_sync(0xffffffffu, a3, o);
    }
    if (lane == 0) {
        part_out[(rbase + 0) * CS + cs] = a0;
        part_out[(rbase + 1) * CS + cs] = a1;
        part_out[(rbase + 2) * CS + cs] = a2;
        part_out[(rbase + 3) * CS + cs] = a3;
    }
}

// ---------------------------------------------------------------------------
// fp16 GEMV partial (polish). Same tiling, f32 input vector. __ldcs: K1/K1T
// are 128MB each, no reuse possible, keep them out of L2.
#define HQ_FMA(u, bA, bB, acc)                                                 \
    {                                                                          \
        float2 f0_ = __half22float2(*reinterpret_cast<__half2*>(&(u).x));      \
        float2 f1_ = __half22float2(*reinterpret_cast<__half2*>(&(u).y));      \
        float2 f2_ = __half22float2(*reinterpret_cast<__half2*>(&(u).z));      \
        float2 f3_ = __half22float2(*reinterpret_cast<__half2*>(&(u).w));      \
        acc = fmaf(f0_.x, (bA).x, acc); acc = fmaf(f0_.y, (bA).y, acc);        \
        acc = fmaf(f1_.x, (bA).z, acc); acc = fmaf(f1_.y, (bA).w, acc);        \
        acc = fmaf(f2_.x, (bB).x, acc); acc = fmaf(f2_.y, (bB).y, acc);        \
        acc = fmaf(f3_.x, (bB).z, acc); acc = fmaf(f3_.y, (bB).w, acc);        \
    }

__global__ __launch_bounds__(256) void sink_pass16(
    const __half* __restrict__ K, const float* __restrict__ vin,
    float* __restrict__ part_out)
{
    PDL_TOP();
    if (frozen()) return;
    const int cs = blockIdx.x & (CS - 1);
    const int rb = blockIdx.x / CS;
    const int warp = threadIdx.x >> 5;
    const int lane = threadIdx.x & 31;
    const int rbase = rb * RPB + warp * 4;
    const int col0 = cs * CHUNK + lane * 16;

    const float4* bv = (const float4*)(vin + col0);
    float4 b0 = bv[0], b1 = bv[1], b2 = bv[2], b3 = bv[3];

    const __half* kr = K + (size_t)rbase * MP + col0;
    float a0 = 0.f, a1 = 0.f, a2 = 0.f, a3 = 0.f;
    {
        uint4 u0 = __ldcs((const uint4*)kr);
        uint4 u1 = __ldcs((const uint4*)kr + 1);
        HQ_FMA(u0, b0, b1, a0); HQ_FMA(u1, b2, b3, a0);
    }
    {
        uint4 u0 = __ldcs((const uint4*)(kr + MP));
        uint4 u1 = __ldcs((const uint4*)(kr + MP) + 1);
        HQ_FMA(u0, b0, b1, a1); HQ_FMA(u1, b2, b3, a1);
    }
    {
        uint4 u0 = __ldcs((const uint4*)(kr + 2 * MP));
        uint4 u1 = __ldcs((const uint4*)(kr + 2 * MP) + 1);
        HQ_FMA(u0, b0, b1, a2); HQ_FMA(u1, b2, b3, a2);
    }
    {
        uint4 u0 = __ldcs((const uint4*)(kr + 3 * MP));
        uint4 u1 = __ldcs((const uint4*)(kr + 3 * MP) + 1);
        HQ_FMA(u0, b0, b1, a3); HQ_FMA(u1, b2, b3, a3);
    }

    #pragma unroll
    for (int o = 16; o; o >>= 1) {
        a0 += __shfl_xor_sync(0xffffffffu, a0, o);
        a1 += __shfl_xor_sync(0xffffffffu, a1, o);
        a2 += __shfl_xor_sync(0xffffffffu, a2, o);
        a3 += __shfl_xor_sync(0xffffffffu, a3, o);
    }
    if (lane == 0) {
        part_out[(rbase + 0) * CS + cs] = a0;
        part_out[(rbase + 1) * CS + cs] = a1;
        part_out[(rbase + 2) * CS + cs] = a2;
        part_out[(rbase + 3) * CS + cs] = a3;
    }
}

// ---------------------------------------------------------------------------
__device__ __forceinline__ float combine16(const float* __restrict__ part,
                                           int i)
{
    const float4* p4 = (const float4*)(part + i * CS);
    float4 q0 = p4[0], q1 = p4[1], q2 = p4[2], q3 = p4[3];
    return ((q0.x + q0.y) + (q0.z + q0.w)) + ((q1.x + q1.y) + (q1.z + q1.w)) +
           ((q2.x + q2.y) + (q2.z + q2.w)) + ((q3.x + q3.y) + (q3.z + q3.w));
}

__global__ __launch_bounds__(256) void sink_combine_a(
    const float* __restrict__ p, float scale, float hscale)
{
    PDL_TOP();
    if (frozen()) return;
    const int i = blockIdx.x * 256 + threadIdx.x;
    float s = combine16(g_pa, i);
    float av = __fdividef(p[i] * scale, s);
    g_a[i] = av;
    g_ah[i] = __float2half_rn(av * hscale);
}

// 32-block b combine: update b (+half copy) and write per-block err^2 partial.
__global__ __launch_bounds__(256) void sink_combine_b(
    const float* __restrict__ q, float scale)
{
    PDL_TOP();
    if (frozen()) return;
    const int i = blockIdx.x * 256 + threadIdx.x;
    float s = combine16(g_pb, i);
    float bn = __fdividef(q[i] * scale, s);
    float d = bn - g_b[i];
    g_b[i] = bn;
    g_bh[i] = __float2half_rn(bn);

    __shared__ float sd[256];
    sd[threadIdx.x] = d * d;
    __syncthreads();
    for (int o = 128; o; o >>= 1) {
        if (threadIdx.x < o) sd[threadIdx.x] += sd[threadIdx.x + o];
        __syncthreads();
    }
    if (threadIdx.x == 0) g_errp[blockIdx.x] = sd[0];
}

// ---------------------------------------------------------------------------
// T = a * (K1/2^16) * b; cost term = T * C with C = EPS*(ln 2^16 - ln K1).
__global__ __launch_bounds__(256) void finalize_T(float* __restrict__ Tout,
                                                  int write_T)
{
    const size_t e0 = ((size_t)blockIdx.x * 4096) + (size_t)threadIdx.x * 16;
    const int i = (int)(e0 >> 13);
    const float ai = g_a[i] * INV_SCALE_F;
    float cs = 0.f;

    #pragma unroll
    for (int g = 0; g < 4; ++g) {
        const size_t e = e0 + g * 4;
        const int j = (int)(e & 8191);
        uint2 kv2 = *reinterpret_cast<const uint2*>(g_K1 + e);
        __half2 h0 = *reinterpret_cast<__half2*>(&kv2.x);
        __half2 h1 = *reinterpret_cast<__half2*>(&kv2.y);
        float2 f0 = __half22float2(h0);
        float2 f1 = __half22float2(h1);
        const float4 bv = *reinterpret_cast<const float4*>(g_b + j);

        float t0 = ai * f0.x * bv.x;
        float t1 = ai * f0.y * bv.y;
        float t2 = ai * f1.x * bv.z;
        float t3 = ai * f1.y * bv.w;

        if (f0.x > 0.f) cs = fmaf(t0, EPSV * (LOG_SCALE_F - __logf(f0.x)), cs);
        if (f0.y > 0.f) cs = fmaf(t1, EPSV * (LOG_SCALE_F - __logf(f0.y)), cs);
        if (f1.x > 0.f) cs = fmaf(t2, EPSV * (LOG_SCALE_F - __logf(f1.x)), cs);
        if (f1.y > 0.f) cs = fmaf(t3, EPSV * (LOG_SCALE_F - __logf(f1.y)), cs);

        if (write_T) {
            if ((((uintptr_t)Tout) & 15) == 0) {
                *reinterpret_cast<float4*>(Tout + e) = make_float4(t0, t1, t2, t3);
            } else {
                Tout[e + 0] = t0;
                Tout[e + 1] = t1;
                Tout[e + 2] = t2;
                Tout[e + 3] = t3;
            }
        }
    }

    __shared__ float sd[256];
    sd[threadIdx.x] = cs;
    __syncthreads();
    for (int o = 128; o; o >>= 1) {
        if (threadIdx.x < o) sd[threadIdx.x] += sd[threadIdx.x + o];
        __syncthreads();
    }
    if (threadIdx.x == 0) g_part[blockIdx.x] = sd[0];
}

__global__ __launch_bounds__(256) void reduce_cost(float* __restrict__ cost_out)
{
    __shared__ double sd[256];
    double s = 0.0;
    for (int i = threadIdx.x; i < 16384; i += 256) s += (double)g_part[i];
    sd[threadIdx.x] = s;
    __syncthreads();
    for (int o = 128; o; o >>= 1) {
        if (threadIdx.x < o) sd[threadIdx.x] += sd[threadIdx.x + o];
        __syncthreads();
    }
    if (threadIdx.x == 0) cost_out[0] = (float)sd[0];
}

// ---------------------------------------------------------------------------
#define LAUNCH_PDL(func, grid, ...)                                            \
    do {                                                                       \
        cudaLaunchConfig_t cfg_ = {};                                          \
        cfg_.gridDim = dim3(grid);                                             \
        cfg_.blockDim = dim3(256);                                             \
        cfg_.stream = 0;                                                       \
        cudaLaunchAttribute at_[1];                                            \
        at_[0].id = cudaLaunchAttributeProgrammaticStreamSerialization;        \
        at_[0].val.programmaticStreamSerializationAllowed = 1;                 \
        cfg_.attrs = at_;                                                      \
        cfg_.numAttrs = 1;                                                     \
        cudaLaunchKernelEx(&cfg_, func, __VA_ARGS__);                          \
    } while (0)

extern "C" void kernel_launch(void* const* d_in, const int* in_sizes, int n_in,
                              void* d_out, int out_size)
{
    const float* x = (const float*)d_in[0];
    const float* y = (const float*)d_in[1];
    const float* p = (const float*)d_in[2];
    const float* q = (const float*)d_in[3];
    float* out = (float*)d_out;

    void *k1p, *k1tp, *k8p, *k8tp, *ap, *bp, *ahp, *bhp, *pap, *pbp;
    cudaGetSymbolAddress(&k1p, g_K1);
    cudaGetSymbolAddress(&k1tp, g_K1T);
    cudaGetSymbolAddress(&k8p, g_K8);
    cudaGetSymbolAddress(&k8tp, g_K8T);
    cudaGetSymbolAddress(&ap, g_a);
    cudaGetSymbolAddress(&bp, g_b);
    cudaGetSymbolAddress(&ahp, g_ah);
    cudaGetSymbolAddress(&bhp, g_bh);
    cudaGetSymbolAddress(&pap, g_pa);
    cudaGetSymbolAddress(&pbp, g_pb);

    sink_init<<<32, 256>>>();
    dim3 bgrid(MP / 64, NP / 64);
    build_K<<<bgrid, 256>>>(x, y);

    const int mv_grid = (NP / RPB) * CS; // 4096
    for (int it = 0; it < TOTAL_ITERS; ++it) {
        if (it < FP8_ITERS) {
            LAUNCH_PDL(sink_pass8<false>, mv_grid, (const uint8_t*)k8p,
                       (const __half*)bhp, (float*)pap);
            LAUNCH_PDL(sink_combine_a, NP / 256, p, 1.0f, AH_SCALE);
            LAUNCH_PDL(sink_pass8<true>, mv_grid, (const uint8_t*)k8tp,
                       (const __half*)ahp, (float*)pbp);
            LAUNCH_PDL(sink_combine_b, MP / 256, q, 1024.0f);
        } else {
            LAUNCH_PDL(sink_pass16, mv_grid, (const __half*)k1p,
                       (const float*)bp, (float*)pap);
            LAUNCH_PDL(sink_combine_a, NP / 256, p, SCALE_F, AH_SCALE);
            LAUNCH_PDL(sink_pass16, mv_grid, (const __half*)k1tp,
                       (const float*)ap, (float*)pbp);
            LAUNCH_PDL(sink_combine_b, MP / 256, q, SCALE_F);
        }
    }

    const long long total = (long long)NP * MP;
    if ((long long)out_size == total + 1) {
        finalize_T<<<16384, 256>>>(out + 1, 1);
        reduce_cost<<<1, 256>>>(out);
    } else if ((long long)out_size == total) {
        finalize_T<<<16384, 256>>>(out, 1);
    } else if ((long long)out_size > total) {
        finalize_T<<<16384, 256>>>(out + (out_size - total), 1);
        reduce_cost<<<1, 256>>>(out);
    } else {
        finalize_T<<<16384, 256>>>(nullptr, 0);
        reduce_cost<<<1, 256>>>(out);
    }
}

// round 13
// speedup vs baseline: 1.6240x; 1.0957x over previous
#include <cuda_runtime.h>
#include <cuda_fp16.h>
#include <cuda_fp8.h>
#include <math.h>
#include <stdint.h>

#define NP 8192
#define MP 8192
#define DIMS 32
#define EPSV 10.0f
#define THRESH2 (1e-5f * 1e-5f)
#define FP8_ITERS 16
#define TOTAL_ITERS 20 /* 16 fp8 + 4 fp16 polish (lambda<=0.51 bound) */
#define SCALE_F 65536.0f
#define INV_SCALE_F (1.0f / 65536.0f)
#define LOG_SCALE_F 11.090354888959125f /* ln(65536) */
#define CS 16
#define CHUNK (MP / CS) /* 512 */
#define RPB 32
#define AH_SCALE 1024.0f

// PDL: allow dependents to launch early; wait gates on predecessor completion.
#define PDL_TOP()                                                              \
    do {                                                                       \
        asm volatile("griddepcontrol.launch_dependents;" ::: "memory");        \
        asm volatile("griddepcontrol.wait;" ::: "memory");                     \
    } while (0)

__device__ __half   g_K1[(size_t)NP * MP];
__device__ __half   g_K1T[(size_t)NP * MP];
__device__ uint8_t  g_K8[(size_t)NP * MP];
__device__ uint8_t  g_K8T[(size_t)NP * MP];
__device__ float  g_a[NP];
__device__ float  g_b[MP];
__device__ __half g_ah[NP]; // a * 1024 in half (fp8 passB input)
__device__ __half g_bh[MP]; // b in half (fp8 passA input)
__device__ float  g_pa[NP * CS]; // partials, layout [row][cs]
__device__ float  g_pb[MP * CS];
__device__ float  g_errp[32]; // per-block err^2 partials (sticky freeze)
__device__ float  g_part[16384];

// Sticky freeze: err of the last completed b-update, summed deterministically.
__device__ __forceinline__ bool frozen()
{
    float v = g_errp[threadIdx.x & 31];
    #pragma unroll
    for (int o = 16; o; o >>= 1) v += __shfl_xor_sync(0xffffffffu, v, o);
    return v < THRESH2;
}

// ---------------------------------------------------------------------------
__global__ void sink_init()
{
    int i = blockIdx.x * 256 + threadIdx.x;
    if (i < MP) { g_b[i] = 1.0f; g_bh[i] = __float2half_rn(1.0f); }
    if (i < 32) g_errp[i] = 1e30f;
}

// ---------------------------------------------------------------------------
// Build: e = exp(-max(C,0)/EPS). K1/K8 written directly from the register
// micro-tile (vector STG); K1T/K8T transposed through padded shared tiles
// and written as STG.128.
__global__ __launch_bounds__(256) void build_K(const float* __restrict__ x,
                                               const float* __restrict__ y)
{
    __shared__ float sx[64][DIMS + 1];
    __shared__ float sy[64][DIMS + 1];
    __shared__ float sx2[64];
    __shared__ float sy2[64];
    __shared__ __half  stile[64][72];  // 144B rows (16B aligned)
    __shared__ uint8_t s8tile[64][80]; // 80B rows (16B aligned)

    const int tid = threadIdx.x;
    const int I0 = blockIdx.y * 64;
    const int J0 = blockIdx.x * 64;

    for (int idx = tid; idx < 64 * DIMS; idx += 256) {
        int r = idx >> 5, k = idx & 31;
        sx[r][k] = x[(I0 + r) * DIMS + k];
        sy[r][k] = y[(J0 + r) * DIMS + k];
    }
    __syncthreads();
    if (tid < 64) {
        float s = 0.f;
        #pragma unroll
        for (int k = 0; k < DIMS; k++) { float v = sx[tid][k]; s = fmaf(v, v, s); }
        sx2[tid] = s;
    } else if (tid < 128) {
        int r = tid - 64;
        float s = 0.f;
        #pragma unroll
        for (int k = 0; k < DIMS; k++) { float v = sy[r][k]; s = fmaf(v, v, s); }
        sy2[r] = s;
    }
    __syncthreads();

    const int ty = tid >> 4, tx = tid & 15;
    const int r0 = ty * 4, c0 = tx * 4;
    float acc[4][4];
    #pragma unroll
    for (int i = 0; i < 4; i++)
        #pragma unroll
        for (int j = 0; j < 4; j++) acc[i][j] = 0.f;

    #pragma unroll
    for (int k = 0; k < DIMS; k++) {
        float a0 = sx[r0 + 0][k], a1 = sx[r0 + 1][k];
        float a2 = sx[r0 + 2][k], a3 = sx[r0 + 3][k];
        float b0 = sy[c0 + 0][k], b1 = sy[c0 + 1][k];
        float b2 = sy[c0 + 2][k], b3 = sy[c0 + 3][k];
        acc[0][0] = fmaf(a0, b0, acc[0][0]); acc[0][1] = fmaf(a0, b1, acc[0][1]);
        acc[0][2] = fmaf(a0, b2, acc[0][2]); acc[0][3] = fmaf(a0, b3, acc[0][3]);
        acc[1][0] = fmaf(a1, b0, acc[1][0]); acc[1][1] = fmaf(a1, b1, acc[1][1]);
        acc[1][2] = fmaf(a1, b2, acc[1][2]); acc[1][3] = fmaf(a1, b3, acc[1][3]);
        acc[2][0] = fmaf(a2, b0, acc[2][0]); acc[2][1] = fmaf(a2, b1, acc[2][1]);
        acc[2][2] = fmaf(a2, b2, acc[2][2]); acc[2][3] = fmaf(a2, b3, acc[2][3]);
        acc[3][0] = fmaf(a3, b0, acc[3][0]); acc[3][1] = fmaf(a3, b1, acc[3][1]);
        acc[3][2] = fmaf(a3, b2, acc[3][2]); acc[3][3] = fmaf(a3, b3, acc[3][3]);
    }

    #pragma unroll
    for (int i = 0; i < 4; i++) {
        __half hrow[4];
        uint8_t brow[4];
        #pragma unroll
        for (int j = 0; j < 4; j++) {
            float C = sx2[r0 + i] + sy2[c0 + j] - 2.f * acc[i][j];
            C = fmaxf(C, 0.f);
            float e16 = exp2f(fmaf(C, -0.14426950408889634f, 16.0f));
            __half h = __float2half_rn(fminf(e16, 65504.f));
            uint8_t b8 = (uint8_t)__nv_cvt_float_to_fp8(
                e16 * 0.00390625f, __NV_SATFINITE, __NV_E4M3);
            hrow[j] = h;
            brow[j] = b8;
            stile[r0 + i][c0 + j] = h;
            s8tile[r0 + i][c0 + j] = b8;
        }
        // Direct row-major stores from registers (8B / 4B vector STG)
        uint2 hw;
        __half2* hwp = reinterpret_cast<__half2*>(&hw);
        hwp[0] = __halves2half2(hrow[0], hrow[1]);
        hwp[1] = __halves2half2(hrow[2], hrow[3]);
        *(uint2*)(g_K1 + (size_t)(I0 + r0 + i) * MP + J0 + c0) = hw;
        uchar4 bw;
        bw.x = brow[0]; bw.y = brow[1]; bw.z = brow[2]; bw.w = brow[3];
        *(uchar4*)(g_K8 + (size_t)(I0 + r0 + i) * MP + J0 + c0) = bw;
    }
    __syncthreads();

    // K1T: each group = 8 contiguous halves (16B) of one transposed row.
    for (int idx = tid; idx < 512; idx += 256) {
        int c = idx >> 3, r8 = (idx & 7) * 8;
        uint4 w;
        __half* hp = reinterpret_cast<__half*>(&w);
        #pragma unroll
        for (int k = 0; k < 8; k++) hp[k] = stile[r8 + k][c];
        *(uint4*)(g_K1T + (size_t)(J0 + c) * NP + I0 + r8) = w;
    }
    // K8T: each group = 16 contiguous bytes of one transposed row.
    {
        int idx = tid;
        if (idx < 256) {
            int c = idx >> 2, r16 = (idx & 3) * 16;
            uint4 w;
            uint8_t* bp = reinterpret_cast<uint8_t*>(&w);
            #pragma unroll
            for (int k = 0; k < 16; k++) bp[k] = s8tile[r16 + k][c];
            *(uint4*)(g_K8T + (size_t)(J0 + c) * NP + I0 + r16) = w;
        }
    }
}

// ---------------------------------------------------------------------------
// ALU-side e4m3 -> fp16 decode (non-negative values; exact 2^-8 scale folded
// into the combine scale; exact for subnormals).
__device__ __forceinline__ __half2 dec8(uint32_t w, uint32_t sel)
{
    uint32_t r = (__byte_perm(w, 0u, sel) >> 1) & 0x7F807F80u;
    return *reinterpret_cast<__half2*>(&r);
}

__device__ __forceinline__ float row16_fp8(uint4 u, uint4 bA, uint4 bB)
{
    const __half2* ba = reinterpret_cast<const __half2*>(&bA);
    const __half2* bb = reinterpret_cast<const __half2*>(&bB);
    __half2 acc = __hmul2(dec8(u.x, 0x1404u), ba[0]);
    acc = __hfma2(dec8(u.x, 0x3424u), ba[1], acc);
    acc = __hfma2(dec8(u.y, 0x1404u), ba[2], acc);
    acc = __hfma2(dec8(u.y, 0x3424u), ba[3], acc);
    acc = __hfma2(dec8(u.z, 0x1404u), bb[0], acc);
    acc = __hfma2(dec8(u.z, 0x3424u), bb[1], acc);
    acc = __hfma2(dec8(u.w, 0x1404u), bb[2], acc);
    acc = __hfma2(dec8(u.w, 0x3424u), bb[3], acc);
    float2 f = __half22float2(acc);
    return f.x + f.y;
}

// fp8 GEMV partial: tile = 32 rows x 512 cols (16KB). warp = 4 rows,
// lane = 16 cols. Partials stored transposed: part[row*CS + cs].
// STREAM=false (a-pass on K8): __ldcg, lines persist in L2 (K8 = 64MB fits).
// STREAM=true (b-pass on K8T): __ldcs evict-first so K8 stays L2-resident.
template <bool STREAM>
__global__ __launch_bounds__(256) void sink_pass8(
    const uint8_t* __restrict__ K8, const __half* __restrict__ vin_h,
    float* __restrict__ part_out)
{
    PDL_TOP();
    if (frozen()) return;
    const int cs = blockIdx.x & (CS - 1);
    const int rb = blockIdx.x / CS;
    const int warp = threadIdx.x >> 5;
    const int lane = threadIdx.x & 31;
    const int rbase = rb * RPB + warp * 4;
    const int col0 = cs * CHUNK + lane * 16;

    const uint4* bhp = (const uint4*)(vin_h + col0);
    uint4 bA = bhp[0], bB = bhp[1];

    const size_t base = (size_t)rbase * MP + col0;
    uint4 u0, u1, u2, u3;
    if (STREAM) {
        u0 = __ldcs((const uint4*)(K8 + base));
        u1 = __ldcs((const uint4*)(K8 + base + MP));
        u2 = __ldcs((const uint4*)(K8 + base + 2 * MP));
        u3 = __ldcs((const uint4*)(K8 + base + 3 * MP));
    } else {
        u0 = __ldcg((const uint4*)(K8 + base));
        u1 = __ldcg((const uint4*)(K8 + base + MP));
        u2 = __ldcg((const uint4*)(K8 + base + 2 * MP));
        u3 = __ldcg((const uint4*)(K8 + base + 3 * MP));
    }

    float a0 = row16_fp8(u0, bA, bB);
    float a1 = row16_fp8(u1, bA, bB);
    float a2 = row16_fp8(u2, bA, bB);
    float a3 = row16_fp8(u3, bA, bB);

    #pragma unroll
    for (int o = 16; o; o >>= 1) {
        a0 += __shfl_xor_sync(0xffffffffu, a0, o);
        a1 += __shfl_xor_sync(0xffffffffu, a1, o);
        a2 += __shfl_xor_sync(0xffffffffu, a2, o);
        a3 += __shfl_xor_sync(0xffffffffu, a3, o);
    }
    if (lane == 0) {
        part_out[(rbase + 0) * CS + cs] = a0;
        part_out[(rbase + 1) * CS + cs] = a1;
        part_out[(rbase + 2) * CS + cs] = a2;
        part_out[(rbase + 3) * CS + cs] = a3;
    }
}

// ---------------------------------------------------------------------------
// fp16 GEMV partial (polish). Same tiling, f32 input vector. __ldcs: K1/K1T
// are 128MB each, no reuse possible, keep them out of L2.
#define HQ_FMA(u, bA, bB, acc)                                                 \
    {                                                                          \
        float2 f0_ = __half22float2(*reinterpret_cast<__half2*>(&(u).x));      \
        float2 f1_ = __half22float2(*reinterpret_cast<__half2*>(&(u).y));      \
        float2 f2_ = __half22float2(*reinterpret_cast<__half2*>(&(u).z));      \
        float2 f3_ = __half22float2(*reinterpret_cast<__half2*>(&(u).w));      \
        acc = fmaf(f0_.x, (bA).x, acc); acc = fmaf(f0_.y, (bA).y, acc);        \
        acc = fmaf(f1_.x, (bA).z, acc); acc = fmaf(f1_.y, (bA).w, acc);        \
        acc = fmaf(f2_.x, (bB).x, acc); acc = fmaf(f2_.y, (bB).y, acc);        \
        acc = fmaf(f3_.x, (bB).z, acc); acc = fmaf(f3_.y, (bB).w, acc);        \
    }

__global__ __launch_bounds__(256) void sink_pass16(
    const __half* __restrict__ K, const float* __restrict__ vin,
    float* __restrict__ part_out)
{
    PDL_TOP();
    if (frozen()) return;
    const int cs = blockIdx.x & (CS - 1);
    const int rb = blockIdx.x / CS;
    const int warp = threadIdx.x >> 5;
    const int lane = threadIdx.x & 31;
    const int rbase = rb * RPB + warp * 4;
    const int col0 = cs * CHUNK + lane * 16;

    const float4* bv = (const float4*)(vin + col0);
    float4 b0 = bv[0], b1 = bv[1], b2 = bv[2], b3 = bv[3];

    const __half* kr = K + (size_t)rbase * MP + col0;
    float a0 = 0.f, a1 = 0.f, a2 = 0.f, a3 = 0.f;
    {
        uint4 u0 = __ldcs((const uint4*)kr);
        uint4 u1 = __ldcs((const uint4*)kr + 1);
        HQ_FMA(u0, b0, b1, a0); HQ_FMA(u1, b2, b3, a0);
    }
    {
        uint4 u0 = __ldcs((const uint4*)(kr + MP));
        uint4 u1 = __ldcs((const uint4*)(kr + MP) + 1);
        HQ_FMA(u0, b0, b1, a1); HQ_FMA(u1, b2, b3, a1);
    }
    {
        uint4 u0 = __ldcs((const uint4*)(kr + 2 * MP));
        uint4 u1 = __ldcs((const uint4*)(kr + 2 * MP) + 1);
        HQ_FMA(u0, b0, b1, a2); HQ_FMA(u1, b2, b3, a2);
    }
    {
        uint4 u0 = __ldcs((const uint4*)(kr + 3 * MP));
        uint4 u1 = __ldcs((const uint4*)(kr + 3 * MP) + 1);
        HQ_FMA(u0, b0, b1, a3); HQ_FMA(u1, b2, b3, a3);
    }

    #pragma unroll
    for (int o = 16; o; o >>= 1) {
        a0 += __shfl_xor_sync(0xffffffffu, a0, o);
        a1 += __shfl_xor_sync(0xffffffffu, a1, o);
        a2 += __shfl_xor_sync(0xffffffffu, a2, o);
        a3 += __shfl_xor_sync(0xffffffffu, a3, o);
    }
    if (lane == 0) {
        part_out[(rbase + 0) * CS + cs] = a0;
        part_out[(rbase + 1) * CS + cs] = a1;
        part_out[(rbase + 2) * CS + cs] = a2;
        part_out[(rbase + 3) * CS + cs] = a3;
    }
}

// ---------------------------------------------------------------------------
__device__ __forceinline__ float combine16(const float* __restrict__ part,
                                           int i)
{
    const float4* p4 = (const float4*)(part + i * CS);
    float4 q0 = p4[0], q1 = p4[1], q2 = p4[2], q3 = p4[3];
    return ((q0.x + q0.y) + (q0.z + q0.w)) + ((q1.x + q1.y) + (q1.z + q1.w)) +
           ((q2.x + q2.y) + (q2.z + q2.w)) + ((q3.x + q3.y) + (q3.z + q3.w));
}

__global__ __launch_bounds__(256) void sink_combine_a(
    const float* __restrict__ p, float scale, float hscale)
{
    PDL_TOP();
    if (frozen()) return;
    const int i = blockIdx.x * 256 + threadIdx.x;
    float s = combine16(g_pa, i);
    float av = __fdividef(p[i] * scale, s);
    g_a[i] = av;
    g_ah[i] = __float2half_rn(av * hscale);
}

// 32-block b combine: update b (+half copy) and write per-block err^2 partial.
__global__ __launch_bounds__(256) void sink_combine_b(
    const float* __restrict__ q, float scale)
{
    PDL_TOP();
    if (frozen()) return;
    const int i = blockIdx.x * 256 + threadIdx.x;
    float s = combine16(g_pb, i);
    float bn = __fdividef(q[i] * scale, s);
    float d = bn - g_b[i];
    g_b[i] = bn;
    g_bh[i] = __float2half_rn(bn);

    __shared__ float sd[256];
    sd[threadIdx.x] = d * d;
    __syncthreads();
    for (int o = 128; o; o >>= 1) {
        if (threadIdx.x < o) sd[threadIdx.x] += sd[threadIdx.x + o];
        __syncthreads();
    }
    if (threadIdx.x == 0) g_errp[blockIdx.x] = sd[0];
}

// ---------------------------------------------------------------------------
// T = a * (K1/2^16) * b; cost term = T * C with C = EPS*(ln 2^16 - ln K1).
__global__ __launch_bounds__(256) void finalize_T(float* __restrict__ Tout,
                                                  int write_T)
{
    const size_t e0 = ((size_t)blockIdx.x * 4096) + (size_t)threadIdx.x * 16;
    const int i = (int)(e0 >> 13);
    const float ai = g_a[i] * INV_SCALE_F;
    float cs = 0.f;

    #pragma unroll
    for (int g = 0; g < 4; ++g) {
        const size_t e = e0 + g * 4;
        const int j = (int)(e & 8191);
        uint2 kv2 = *reinterpret_cast<const uint2*>(g_K1 + e);
        __half2 h0 = *reinterpret_cast<__half2*>(&kv2.x);
        __half2 h1 = *reinterpret_cast<__half2*>(&kv2.y);
        float2 f0 = __half22float2(h0);
        float2 f1 = __half22float2(h1);
        const float4 bv = *reinterpret_cast<const float4*>(g_b + j);

        float t0 = ai * f0.x * bv.x;
        float t1 = ai * f0.y * bv.y;
        float t2 = ai * f1.x * bv.z;
        float t3 = ai * f1.y * bv.w;

        if (f0.x > 0.f) cs = fmaf(t0, EPSV * (LOG_SCALE_F - __logf(f0.x)), cs);
        if (f0.y > 0.f) cs = fmaf(t1, EPSV * (LOG_SCALE_F - __logf(f0.y)), cs);
        if (f1.x > 0.f) cs = fmaf(t2, EPSV * (LOG_SCALE_F - __logf(f1.x)), cs);
        if (f1.y > 0.f) cs = fmaf(t3, EPSV * (LOG_SCALE_F - __logf(f1.y)), cs);

        if (write_T) {
            if ((((uintptr_t)Tout) & 15) == 0) {
                *reinterpret_cast<float4*>(Tout + e) = make_float4(t0, t1, t2, t3);
            } else {
                Tout[e + 0] = t0;
                Tout[e + 1] = t1;
                Tout[e + 2] = t2;
                Tout[e + 3] = t3;
            }
        }
    }

    __shared__ float sd[256];
    sd[threadIdx.x] = cs;
    __syncthreads();
    for (int o = 128; o; o >>= 1) {
        if (threadIdx.x < o) sd[threadIdx.x] += sd[threadIdx.x + o];
        __syncthreads();
    }
    if (threadIdx.x == 0) g_part[blockIdx.x] = sd[0];
}

__global__ __launch_bounds__(256) void reduce_cost(float* __restrict__ cost_out)
{
    __shared__ double sd[256];
    double s = 0.0;
    for (int i = threadIdx.x; i < 16384; i += 256) s += (double)g_part[i];
    sd[threadIdx.x] = s;
    __syncthreads();
    for (int o = 128; o; o >>= 1) {
        if (threadIdx.x < o) sd[threadIdx.x] += sd[threadIdx.x + o];
        __syncthreads();
    }
    if (threadIdx.x == 0) cost_out[0] = (float)sd[0];
}

// ---------------------------------------------------------------------------
#define LAUNCH_PDL(func, grid, ...)                                            \
    do {                                                                       \
        cudaLaunchConfig_t cfg_ = {};                                          \
        cfg_.gridDim = dim3(grid);                                             \
        cfg_.blockDim = dim3(256);                                             \
        cfg_.stream = 0;                                                       \
        cudaLaunchAttribute at_[1];                                            \
        at_[0].id = cudaLaunchAttributeProgrammaticStreamSerialization;        \
        at_[0].val.programmaticStreamSerializationAllowed = 1;                 \
        cfg_.attrs = at_;                                                      \
        cfg_.numAttrs = 1;                                                     \
        cudaLaunchKernelEx(&cfg_, func, __VA_ARGS__);                          \
    } while (0)

extern "C" void kernel_launch(void* const* d_in, const int* in_sizes, int n_in,
                              void* d_out, int out_size)
{
    const float* x = (const float*)d_in[0];
    const float* y = (const float*)d_in[1];
    const float* p = (const float*)d_in[2];
    const float* q = (const float*)d_in[3];
    float* out = (float*)d_out;

    void *k1p, *k1tp, *k8p, *k8tp, *ap, *bp, *ahp, *bhp, *pap, *pbp;
    cudaGetSymbolAddress(&k1p, g_K1);
    cudaGetSymbolAddress(&k1tp, g_K1T);
    cudaGetSymbolAddress(&k8p, g_K8);
    cudaGetSymbolAddress(&k8tp, g_K8T);
    cudaGetSymbolAddress(&ap, g_a);
    cudaGetSymbolAddress(&bp, g_b);
    cudaGetSymbolAddress(&ahp, g_ah);
    cudaGetSymbolAddress(&bhp, g_bh);
    cudaGetSymbolAddress(&pap, g_pa);
    cudaGetSymbolAddress(&pbp, g_pb);

    sink_init<<<32, 256>>>();
    dim3 bgrid(MP / 64, NP / 64);
    build_K<<<bgrid, 256>>>(x, y);

    const int mv_grid = (NP / RPB) * CS; // 4096
    for (int it = 0; it < TOTAL_ITERS; ++it) {
        if (it < FP8_ITERS) {
            LAUNCH_PDL(sink_pass8<false>, mv_grid, (const uint8_t*)k8p,
                       (const __half*)bhp, (float*)pap);
            LAUNCH_PDL(sink_combine_a, NP / 256, p, 1.0f, AH_SCALE);
            LAUNCH_PDL(sink_pass8<true>, mv_grid, (const uint8_t*)k8tp,
                       (const __half*)ahp, (float*)pbp);
            LAUNCH_PDL(sink_combine_b, MP / 256, q, 1024.0f);
        } else {
            LAUNCH_PDL(sink_pass16, mv_grid, (const __half*)k1p,
                       (const float*)bp, (float*)pap);
            LAUNCH_PDL(sink_combine_a, NP / 256, p, SCALE_F, AH_SCALE);
            LAUNCH_PDL(sink_pass16, mv_grid, (const __half*)k1tp,
                       (const float*)ap, (float*)pbp);
            LAUNCH_PDL(sink_combine_b, MP / 256, q, SCALE_F);
        }
    }

    const long long total = (long long)NP * MP;
    if ((long long)out_size == total + 1) {
        finalize_T<<<16384, 256>>>(out + 1, 1);
        reduce_cost<<<1, 256>>>(out);
    } else if ((long long)out_size == total) {
        finalize_T<<<16384, 256>>>(out, 1);
    } else if ((long long)out_size > total) {
        finalize_T<<<16384, 256>>>(out + (out_size - total), 1);
        reduce_cost<<<1, 256>>>(out);
    } else {
        finalize_T<<<16384, 256>>>(nullptr, 0);
        reduce_cost<<<1, 256>>>(out);
    }
}

// round 14
// speedup vs baseline: 1.8785x; 1.1567x over previous
#include <cuda_runtime.h>
#include <cuda_fp16.h>
#include <cuda_fp8.h>
#include <math.h>
#include <stdint.h>

#define NP 8192
#define MP 8192
#define DIMS 32
#define EPSV 10.0f
#define THRESH2 (1e-5f * 1e-5f)
#define FP8_ITERS 12
#define TOTAL_ITERS 15 /* 12 fp8 + 3 fp16 polish (lambda<=0.45 bound) */
#define SCALE_F 65536.0f
#define INV_SCALE_F (1.0f / 65536.0f)
#define LOG_SCALE_F 11.090354888959125f /* ln(65536) */
#define CS 16
#define CHUNK (MP / CS) /* 512 */
#define RPB 32
#define AH_SCALE 1024.0f

// PDL: allow dependents to launch early; wait gates on predecessor completion.
#define PDL_TOP()                                                              \
    do {                                                                       \
        asm volatile("griddepcontrol.launch_dependents;" ::: "memory");        \
        asm volatile("griddepcontrol.wait;" ::: "memory");                     \
    } while (0)

__device__ __half   g_K1[(size_t)NP * MP];
__device__ __half   g_K1T[(size_t)NP * MP];
__device__ uint8_t  g_K8[(size_t)NP * MP];
__device__ uint8_t  g_K8T[(size_t)NP * MP];
__device__ float  g_a[NP];
__device__ float  g_b[MP];
__device__ __half g_ah[NP]; // a * 1024 in half (fp8 passB input)
__device__ __half g_bh[MP]; // b in half (fp8 passA input)
__device__ float  g_pa[NP * CS]; // partials, layout [row][cs]
__device__ float  g_pb[MP * CS];
__device__ float  g_errp[32]; // per-block err^2 partials (sticky freeze)
__device__ float  g_part[16384];

// Sticky freeze: err of the last completed b-update, summed deterministically.
__device__ __forceinline__ bool frozen()
{
    float v = g_errp[threadIdx.x & 31];
    #pragma unroll
    for (int o = 16; o; o >>= 1) v += __shfl_xor_sync(0xffffffffu, v, o);
    return v < THRESH2;
}

// ---------------------------------------------------------------------------
__global__ void sink_init()
{
    int i = blockIdx.x * 256 + threadIdx.x;
    if (i < MP) { g_b[i] = 1.0f; g_bh[i] = __float2half_rn(1.0f); }
    if (i < 32) g_errp[i] = 1e30f;
}

// ---------------------------------------------------------------------------
// Build: e = exp(-max(C,0)/EPS). K1/K8 written directly from the register
// micro-tile (vector STG); K1T/K8T transposed through padded shared tiles
// and written as STG.128.
__global__ __launch_bounds__(256) void build_K(const float* __restrict__ x,
                                               const float* __restrict__ y)
{
    __shared__ float sx[64][DIMS + 1];
    __shared__ float sy[64][DIMS + 1];
    __shared__ float sx2[64];
    __shared__ float sy2[64];
    __shared__ __half  stile[64][72];  // 144B rows (16B aligned)
    __shared__ uint8_t s8tile[64][80]; // 80B rows (16B aligned)

    const int tid = threadIdx.x;
    const int I0 = blockIdx.y * 64;
    const int J0 = blockIdx.x * 64;

    for (int idx = tid; idx < 64 * DIMS; idx += 256) {
        int r = idx >> 5, k = idx & 31;
        sx[r][k] = x[(I0 + r) * DIMS + k];
        sy[r][k] = y[(J0 + r) * DIMS + k];
    }
    __syncthreads();
    if (tid < 64) {
        float s = 0.f;
        #pragma unroll
        for (int k = 0; k < DIMS; k++) { float v = sx[tid][k]; s = fmaf(v, v, s); }
        sx2[tid] = s;
    } else if (tid < 128) {
        int r = tid - 64;
        float s = 0.f;
        #pragma unroll
        for (int k = 0; k < DIMS; k++) { float v = sy[r][k]; s = fmaf(v, v, s); }
        sy2[r] = s;
    }
    __syncthreads();

    const int ty = tid >> 4, tx = tid & 15;
    const int r0 = ty * 4, c0 = tx * 4;
    float acc[4][4];
    #pragma unroll
    for (int i = 0; i < 4; i++)
        #pragma unroll
        for (int j = 0; j < 4; j++) acc[i][j] = 0.f;

    #pragma unroll
    for (int k = 0; k < DIMS; k++) {
        float a0 = sx[r0 + 0][k], a1 = sx[r0 + 1][k];
        float a2 = sx[r0 + 2][k], a3 = sx[r0 + 3][k];
        float b0 = sy[c0 + 0][k], b1 = sy[c0 + 1][k];
        float b2 = sy[c0 + 2][k], b3 = sy[c0 + 3][k];
        acc[0][0] = fmaf(a0, b0, acc[0][0]); acc[0][1] = fmaf(a0, b1, acc[0][1]);
        acc[0][2] = fmaf(a0, b2, acc[0][2]); acc[0][3] = fmaf(a0, b3, acc[0][3]);
        acc[1][0] = fmaf(a1, b0, acc[1][0]); acc[1][1] = fmaf(a1, b1, acc[1][1]);
        acc[1][2] = fmaf(a1, b2, acc[1][2]); acc[1][3] = fmaf(a1, b3, acc[1][3]);
        acc[2][0] = fmaf(a2, b0, acc[2][0]); acc[2][1] = fmaf(a2, b1, acc[2][1]);
        acc[2][2] = fmaf(a2, b2, acc[2][2]); acc[2][3] = fmaf(a2, b3, acc[2][3]);
        acc[3][0] = fmaf(a3, b0, acc[3][0]); acc[3][1] = fmaf(a3, b1, acc[3][1]);
        acc[3][2] = fmaf(a3, b2, acc[3][2]); acc[3][3] = fmaf(a3, b3, acc[3][3]);
    }

    #pragma unroll
    for (int i = 0; i < 4; i++) {
        __half hrow[4];
        uint8_t brow[4];
        #pragma unroll
        for (int j = 0; j < 4; j++) {
            float C = sx2[r0 + i] + sy2[c0 + j] - 2.f * acc[i][j];
            C = fmaxf(C, 0.f);
            float e16 = exp2f(fmaf(C, -0.14426950408889634f, 16.0f));
            __half h = __float2half_rn(fminf(e16, 65504.f));
            uint8_t b8 = (uint8_t)__nv_cvt_float_to_fp8(
                e16 * 0.00390625f, __NV_SATFINITE, __NV_E4M3);
            hrow[j] = h;
            brow[j] = b8;
            stile[r0 + i][c0 + j] = h;
            s8tile[r0 + i][c0 + j] = b8;
        }
        // Direct row-major stores from registers (8B / 4B vector STG)
        uint2 hw;
        __half2* hwp = reinterpret_cast<__half2*>(&hw);
        hwp[0] = __halves2half2(hrow[0], hrow[1]);
        hwp[1] = __halves2half2(hrow[2], hrow[3]);
        *(uint2*)(g_K1 + (size_t)(I0 + r0 + i) * MP + J0 + c0) = hw;
        uchar4 bw;
        bw.x = brow[0]; bw.y = brow[1]; bw.z = brow[2]; bw.w = brow[3];
        *(uchar4*)(g_K8 + (size_t)(I0 + r0 + i) * MP + J0 + c0) = bw;
    }
    __syncthreads();

    // K1T: each group = 8 contiguous halves (16B) of one transposed row.
    for (int idx = tid; idx < 512; idx += 256) {
        int c = idx >> 3, r8 = (idx & 7) * 8;
        uint4 w;
        __half* hp = reinterpret_cast<__half*>(&w);
        #pragma unroll
        for (int k = 0; k < 8; k++) hp[k] = stile[r8 + k][c];
        *(uint4*)(g_K1T + (size_t)(J0 + c) * NP + I0 + r8) = w;
    }
    // K8T: each group = 16 contiguous bytes of one transposed row.
    {
        int idx = tid;
        if (idx < 256) {
            int c = idx >> 2, r16 = (idx & 3) * 16;
            uint4 w;
            uint8_t* bp = reinterpret_cast<uint8_t*>(&w);
            #pragma unroll
            for (int k = 0; k < 16; k++) bp[k] = s8tile[r16 + k][c];
            *(uint4*)(g_K8T + (size_t)(J0 + c) * NP + I0 + r16) = w;
        }
    }
}

// ---------------------------------------------------------------------------
// ALU-side e4m3 -> fp16 decode (non-negative values; exact 2^-8 scale folded
// into the combine scale; exact for subnormals).
__device__ __forceinline__ __half2 dec8(uint32_t w, uint32_t sel)
{
    uint32_t r = (__byte_perm(w, 0u, sel) >> 1) & 0x7F807F80u;
    return *reinterpret_cast<__half2*>(&r);
}

__device__ __forceinline__ float row16_fp8(uint4 u, uint4 bA, uint4 bB)
{
    const __half2* ba = reinterpret_cast<const __half2*>(&bA);
    const __half2* bb = reinterpret_cast<const __half2*>(&bB);
    __half2 acc = __hmul2(dec8(u.x, 0x1404u), ba[0]);
    acc = __hfma2(dec8(u.x, 0x3424u), ba[1], acc);
    acc = __hfma2(dec8(u.y, 0x1404u), ba[2], acc);
    acc = __hfma2(dec8(u.y, 0x3424u), ba[3], acc);
    acc = __hfma2(dec8(u.z, 0x1404u), bb[0], acc);
    acc = __hfma2(dec8(u.z, 0x3424u), bb[1], acc);
    acc = __hfma2(dec8(u.w, 0x1404u), bb[2], acc);
    acc = __hfma2(dec8(u.w, 0x3424u), bb[3], acc);
    float2 f = __half22float2(acc);
    return f.x + f.y;
}

// fp8 GEMV partial: tile = 32 rows x 512 cols (16KB). warp = 4 rows,
// lane = 16 cols. Partials stored transposed: part[row*CS + cs].
// STREAM=false (a-pass on K8): __ldcg, lines persist in L2 (K8 = 64MB fits).
// STREAM=true (b-pass on K8T): __ldcs evict-first so K8 stays L2-resident.
template <bool STREAM>
__global__ __launch_bounds__(256) void sink_pass8(
    const uint8_t* __restrict__ K8, const __half* __restrict__ vin_h,
    float* __restrict__ part_out)
{
    PDL_TOP();
    if (frozen()) return;
    const int cs = blockIdx.x & (CS - 1);
    const int rb = blockIdx.x / CS;
    const int warp = threadIdx.x >> 5;
    const int lane = threadIdx.x & 31;
    const int rbase = rb * RPB + warp * 4;
    const int col0 = cs * CHUNK + lane * 16;

    const uint4* bhp = (const uint4*)(vin_h + col0);
    uint4 bA = bhp[0], bB = bhp[1];

    const size_t base = (size_t)rbase * MP + col0;
    uint4 u0, u1, u2, u3;
    if (STREAM) {
        u0 = __ldcs((const uint4*)(K8 + base));
        u1 = __ldcs((const uint4*)(K8 + base + MP));
        u2 = __ldcs((const uint4*)(K8 + base + 2 * MP));
        u3 = __ldcs((const uint4*)(K8 + base + 3 * MP));
    } else {
        u0 = __ldcg((const uint4*)(K8 + base));
        u1 = __ldcg((const uint4*)(K8 + base + MP));
        u2 = __ldcg((const uint4*)(K8 + base + 2 * MP));
        u3 = __ldcg((const uint4*)(K8 + base + 3 * MP));
    }

    float a0 = row16_fp8(u0, bA, bB);
    float a1 = row16_fp8(u1, bA, bB);
    float a2 = row16_fp8(u2, bA, bB);
    float a3 = row16_fp8(u3, bA, bB);

    #pragma unroll
    for (int o = 16; o; o >>= 1) {
        a0 += __shfl_xor_sync(0xffffffffu, a0, o);
        a1 += __shfl_xor_sync(0xffffffffu, a1, o);
        a2 += __shfl_xor_sync(0xffffffffu, a2, o);
        a3 += __shfl_xor_sync(0xffffffffu, a3, o);
    }
    if (lane == 0) {
        part_out[(rbase + 0) * CS + cs] = a0;
        part_out[(rbase + 1) * CS + cs] = a1;
        part_out[(rbase + 2) * CS + cs] = a2;
        part_out[(rbase + 3) * CS + cs] = a3;
    }
}

// ---------------------------------------------------------------------------
// fp16 GEMV partial (polish). Same tiling, f32 input vector. __ldcs: K1/K1T
// are 128MB each, no reuse possible, keep them out of L2.
#define HQ_FMA(u, bA, bB, acc)                                                 \
    {                                                                          \
        float2 f0_ = __half22float2(*reinterpret_cast<__half2*>(&(u).x));      \
        float2 f1_ = __half22float2(*reinterpret_cast<__half2*>(&(u).y));      \
        float2 f2_ = __half22float2(*reinterpret_cast<__half2*>(&(u).z));      \
        float2 f3_ = __half22float2(*reinterpret_cast<__half2*>(&(u).w));      \
        acc = fmaf(f0_.x, (bA).x, acc); acc = fmaf(f0_.y, (bA).y, acc);        \
        acc = fmaf(f1_.x, (bA).z, acc); acc = fmaf(f1_.y, (bA).w, acc);        \
        acc = fmaf(f2_.x, (bB).x, acc); acc = fmaf(f2_.y, (bB).y, acc);        \
        acc = fmaf(f3_.x, (bB).z, acc); acc = fmaf(f3_.y, (bB).w, acc);        \
    }

__global__ __launch_bounds__(256) void sink_pass16(
    const __half* __restrict__ K, const float* __restrict__ vin,
    float* __restrict__ part_out)
{
    PDL_TOP();
    if (frozen()) return;
    const int cs = blockIdx.x & (CS - 1);
    const int rb = blockIdx.x / CS;
    const int warp = threadIdx.x >> 5;
    const int lane = threadIdx.x & 31;
    const int rbase = rb * RPB + warp * 4;
    const int col0 = cs * CHUNK + lane * 16;

    const float4* bv = (const float4*)(vin + col0);
    float4 b0 = bv[0], b1 = bv[1], b2 = bv[2], b3 = bv[3];

    const __half* kr = K + (size_t)rbase * MP + col0;
    float a0 = 0.f, a1 = 0.f, a2 = 0.f, a3 = 0.f;
    {
        uint4 u0 = __ldcs((const uint4*)kr);
        uint4 u1 = __ldcs((const uint4*)kr + 1);
        HQ_FMA(u0, b0, b1, a0); HQ_FMA(u1, b2, b3, a0);
    }
    {
        uint4 u0 = __ldcs((const uint4*)(kr + MP));
        uint4 u1 = __ldcs((const uint4*)(kr + MP) + 1);
        HQ_FMA(u0, b0, b1, a1); HQ_FMA(u1, b2, b3, a1);
    }
    {
        uint4 u0 = __ldcs((const uint4*)(kr + 2 * MP));
        uint4 u1 = __ldcs((const uint4*)(kr + 2 * MP) + 1);
        HQ_FMA(u0, b0, b1, a2); HQ_FMA(u1, b2, b3, a2);
    }
    {
        uint4 u0 = __ldcs((const uint4*)(kr + 3 * MP));
        uint4 u1 = __ldcs((const uint4*)(kr + 3 * MP) + 1);
        HQ_FMA(u0, b0, b1, a3); HQ_FMA(u1, b2, b3, a3);
    }

    #pragma unroll
    for (int o = 16; o; o >>= 1) {
        a0 += __shfl_xor_sync(0xffffffffu, a0, o);
        a1 += __shfl_xor_sync(0xffffffffu, a1, o);
        a2 += __shfl_xor_sync(0xffffffffu, a2, o);
        a3 += __shfl_xor_sync(0xffffffffu, a3, o);
    }
    if (lane == 0) {
        part_out[(rbase + 0) * CS + cs] = a0;
        part_out[(rbase + 1) * CS + cs] = a1;
        part_out[(rbase + 2) * CS + cs] = a2;
        part_out[(rbase + 3) * CS + cs] = a3;
    }
}

// ---------------------------------------------------------------------------
__device__ __forceinline__ float combine16(const float* __restrict__ part,
                                           int i)
{
    const float4* p4 = (const float4*)(part + i * CS);
    float4 q0 = p4[0], q1 = p4[1], q2 = p4[2], q3 = p4[3];
    return ((q0.x + q0.y) + (q0.z + q0.w)) + ((q1.x + q1.y) + (q1.z + q1.w)) +
           ((q2.x + q2.y) + (q2.z + q2.w)) + ((q3.x + q3.y) + (q3.z + q3.w));
}

__global__ __launch_bounds__(256) void sink_combine_a(
    const float* __restrict__ p, float scale, float hscale)
{
    PDL_TOP();
    if (frozen()) return;
    const int i = blockIdx.x * 256 + threadIdx.x;
    float s = combine16(g_pa, i);
    float av = __fdividef(p[i] * scale, s);
    g_a[i] = av;
    g_ah[i] = __float2half_rn(av * hscale);
}

// 32-block b combine: update b (+half copy) and write per-block err^2 partial.
__global__ __launch_bounds__(256) void sink_combine_b(
    const float* __restrict__ q, float scale)
{
    PDL_TOP();
    if (frozen()) return;
    const int i = blockIdx.x * 256 + threadIdx.x;
    float s = combine16(g_pb, i);
    float bn = __fdividef(q[i] * scale, s);
    float d = bn - g_b[i];
    g_b[i] = bn;
    g_bh[i] = __float2half_rn(bn);

    __shared__ float sd[256];
    sd[threadIdx.x] = d * d;
    __syncthreads();
    for (int o = 128; o; o >>= 1) {
        if (threadIdx.x < o) sd[threadIdx.x] += sd[threadIdx.x + o];
        __syncthreads();
    }
    if (threadIdx.x == 0) g_errp[blockIdx.x] = sd[0];
}

// ---------------------------------------------------------------------------
// T = a * (K1/2^16) * b; cost term = T * C with C = EPS*(ln 2^16 - ln K1).
__global__ __launch_bounds__(256) void finalize_T(float* __restrict__ Tout,
                                                  int write_T)
{
    PDL_TOP();
    const size_t e0 = ((size_t)blockIdx.x * 4096) + (size_t)threadIdx.x * 16;
    const int i = (int)(e0 >> 13);
    const float ai = g_a[i] * INV_SCALE_F;
    float cs = 0.f;

    #pragma unroll
    for (int g = 0; g < 4; ++g) {
        const size_t e = e0 + g * 4;
        const int j = (int)(e & 8191);
        uint2 kv2 = *reinterpret_cast<const uint2*>(g_K1 + e);
        __half2 h0 = *reinterpret_cast<__half2*>(&kv2.x);
        __half2 h1 = *reinterpret_cast<__half2*>(&kv2.y);
        float2 f0 = __half22float2(h0);
        float2 f1 = __half22float2(h1);
        const float4 bv = *reinterpret_cast<const float4*>(g_b + j);

        float t0 = ai * f0.x * bv.x;
        float t1 = ai * f0.y * bv.y;
        float t2 = ai * f1.x * bv.z;
        float t3 = ai * f1.y * bv.w;

        if (f0.x > 0.f) cs = fmaf(t0, EPSV * (LOG_SCALE_F - __logf(f0.x)), cs);
        if (f0.y > 0.f) cs = fmaf(t1, EPSV * (LOG_SCALE_F - __logf(f0.y)), cs);
        if (f1.x > 0.f) cs = fmaf(t2, EPSV * (LOG_SCALE_F - __logf(f1.x)), cs);
        if (f1.y > 0.f) cs = fmaf(t3, EPSV * (LOG_SCALE_F - __logf(f1.y)), cs);

        if (write_T) {
            if ((((uintptr_t)Tout) & 15) == 0) {
                *reinterpret_cast<float4*>(Tout + e) = make_float4(t0, t1, t2, t3);
            } else {
                Tout[e + 0] = t0;
                Tout[e + 1] = t1;
                Tout[e + 2] = t2;
                Tout[e + 3] = t3;
            }
        }
    }

    __shared__ float sd[256];
    sd[threadIdx.x] = cs;
    __syncthreads();
    for (int o = 128; o; o >>= 1) {
        if (threadIdx.x < o) sd[threadIdx.x] += sd[threadIdx.x + o];
        __syncthreads();
    }
    if (threadIdx.x == 0) g_part[blockIdx.x] = sd[0];
}

__global__ __launch_bounds__(256) void reduce_cost(float* __restrict__ cost_out)
{
    PDL_TOP();
    __shared__ double sd[256];
    double s = 0.0;
    for (int i = threadIdx.x; i < 16384; i += 256) s += (double)g_part[i];
    sd[threadIdx.x] = s;
    __syncthreads();
    for (int o = 128; o; o >>= 1) {
        if (threadIdx.x < o) sd[threadIdx.x] += sd[threadIdx.x + o];
        __syncthreads();
    }
    if (threadIdx.x == 0) cost_out[0] = (float)sd[0];
}

// ---------------------------------------------------------------------------
#define LAUNCH_PDL(func, grid, ...)                                            \
    do {                                                                       \
        cudaLaunchConfig_t cfg_ = {};                                          \
        cfg_.gridDim = dim3(grid);                                             \
        cfg_.blockDim = dim3(256);                                             \
        cfg_.stream = 0;                                                       \
        cudaLaunchAttribute at_[1];                                            \
        at_[0].id = cudaLaunchAttributeProgrammaticStreamSerialization;        \
        at_[0].val.programmaticStreamSerializationAllowed = 1;                 \
        cfg_.attrs = at_;                                                      \
        cfg_.numAttrs = 1;                                                     \
        cudaLaunchKernelEx(&cfg_, func, __VA_ARGS__);                          \
    } while (0)

extern "C" void kernel_launch(void* const* d_in, const int* in_sizes, int n_in,
                              void* d_out, int out_size)
{
    const float* x = (const float*)d_in[0];
    const float* y = (const float*)d_in[1];
    const float* p = (const float*)d_in[2];
    const float* q = (const float*)d_in[3];
    float* out = (float*)d_out;

    void *k1p, *k1tp, *k8p, *k8tp, *ap, *bp, *ahp, *bhp, *pap, *pbp;
    cudaGetSymbolAddress(&k1p, g_K1);
    cudaGetSymbolAddress(&k1tp, g_K1T);
    cudaGetSymbolAddress(&k8p, g_K8);
    cudaGetSymbolAddress(&k8tp, g_K8T);
    cudaGetSymbolAddress(&ap, g_a);
    cudaGetSymbolAddress(&bp, g_b);
    cudaGetSymbolAddress(&ahp, g_ah);
    cudaGetSymbolAddress(&bhp, g_bh);
    cudaGetSymbolAddress(&pap, g_pa);
    cudaGetSymbolAddress(&pbp, g_pb);

    sink_init<<<32, 256>>>();
    dim3 bgrid(MP / 64, NP / 64);
    build_K<<<bgrid, 256>>>(x, y);

    const int mv_grid = (NP / RPB) * CS; // 4096
    for (int it = 0; it < TOTAL_ITERS; ++it) {
        if (it < FP8_ITERS) {
            LAUNCH_PDL(sink_pass8<false>, mv_grid, (const uint8_t*)k8p,
                       (const __half*)bhp, (float*)pap);
            LAUNCH_PDL(sink_combine_a, NP / 256, p, 1.0f, AH_SCALE);
            LAUNCH_PDL(sink_pass8<true>, mv_grid, (const uint8_t*)k8tp,
                       (const __half*)ahp, (float*)pbp);
            LAUNCH_PDL(sink_combine_b, MP / 256, q, 1024.0f);
        } else {
            LAUNCH_PDL(sink_pass16, mv_grid, (const __half*)k1p,
                       (const float*)bp, (float*)pap);
            LAUNCH_PDL(sink_combine_a, NP / 256, p, SCALE_F, AH_SCALE);
            LAUNCH_PDL(sink_pass16, mv_grid, (const __half*)k1tp,
                       (const float*)ap, (float*)pbp);
            LAUNCH_PDL(sink_combine_b, MP / 256, q, SCALE_F);
        }
    }

    const long long total = (long long)NP * MP;
    if ((long long)out_size == total + 1) {
        LAUNCH_PDL(finalize_T, 16384, out + 1, 1);
        LAUNCH_PDL(reduce_cost, 1, out);
    } else if ((long long)out_size == total) {
        LAUNCH_PDL(finalize_T, 16384, out, 1);
    } else if ((long long)out_size > total) {
        LAUNCH_PDL(finalize_T, 16384, out + (out_size - total), 1);
        LAUNCH_PDL(reduce_cost, 1, out);
    } else {
        LAUNCH_PDL(finalize_T, 16384, (float*)nullptr, 0);
        LAUNCH_PDL(reduce_cost, 1, out);
    }
}

// round 15
// speedup vs baseline: 1.9088x; 1.0161x over previous
#include <cuda_runtime.h>
#include <cuda_fp16.h>
#include <cuda_fp8.h>
#include <math.h>
#include <stdint.h>

#define NP 8192
#define MP 8192
#define DIMS 32
#define EPSV 10.0f
#define THRESH2 (1e-5f * 1e-5f)
#define FP8_ITERS 9
#define TOTAL_ITERS 12 /* 9 fp8 + 3 fp16 polish (lambda<=0.34 bound) */
#define SCALE_F 65536.0f
#define INV_SCALE_F (1.0f / 65536.0f)
#define LOG_SCALE_F 11.090354888959125f /* ln(65536) */
#define CS 16
#define CHUNK (MP / CS) /* 512 */
#define RPB 32
#define AH_SCALE 1024.0f

// PDL: allow dependents to launch early; wait gates on predecessor completion.
#define PDL_TOP()                                                              \
    do {                                                                       \
        asm volatile("griddepcontrol.launch_dependents;" ::: "memory");        \
        asm volatile("griddepcontrol.wait;" ::: "memory");                     \
    } while (0)

__device__ __half   g_K1[(size_t)NP * MP];
__device__ __half   g_K1T[(size_t)NP * MP];
__device__ uint8_t  g_K8[(size_t)NP * MP];
__device__ uint8_t  g_K8T[(size_t)NP * MP];
__device__ float  g_a[NP];
__device__ float  g_b[MP];
__device__ __half g_ah[NP]; // a * 1024 in half (fp8 passB input)
__device__ __half g_bh[MP]; // b in half (fp8 passA input)
__device__ float  g_pa[NP * CS]; // partials, layout [row][cs]
__device__ float  g_pb[MP * CS];
__device__ float  g_errp[32]; // per-block err^2 partials (sticky freeze)
__device__ float  g_part[16384];

// Sticky freeze: err of the last completed b-update, summed deterministically.
__device__ __forceinline__ bool frozen()
{
    float v = g_errp[threadIdx.x & 31];
    #pragma unroll
    for (int o = 16; o; o >>= 1) v += __shfl_xor_sync(0xffffffffu, v, o);
    return v < THRESH2;
}

// ---------------------------------------------------------------------------
__global__ void sink_init()
{
    int i = blockIdx.x * 256 + threadIdx.x;
    if (i < MP) { g_b[i] = 1.0f; g_bh[i] = __float2half_rn(1.0f); }
    if (i < 32) g_errp[i] = 1e30f;
}

// ---------------------------------------------------------------------------
// Build: e = exp(-max(C,0)/EPS). K1/K8 written directly from the register
// micro-tile (vector STG); K1T/K8T transposed through padded shared tiles
// and written as STG.128.
__global__ __launch_bounds__(256) void build_K(const float* __restrict__ x,
                                               const float* __restrict__ y)
{
    __shared__ float sx[64][DIMS + 1];
    __shared__ float sy[64][DIMS + 1];
    __shared__ float sx2[64];
    __shared__ float sy2[64];
    __shared__ __half  stile[64][72];  // 144B rows (16B aligned)
    __shared__ uint8_t s8tile[64][80]; // 80B rows (16B aligned)

    const int tid = threadIdx.x;
    const int I0 = blockIdx.y * 64;
    const int J0 = blockIdx.x * 64;

    for (int idx = tid; idx < 64 * DIMS; idx += 256) {
        int r = idx >> 5, k = idx & 31;
        sx[r][k] = x[(I0 + r) * DIMS + k];
        sy[r][k] = y[(J0 + r) * DIMS + k];
    }
    __syncthreads();
    if (tid < 64) {
        float s = 0.f;
        #pragma unroll
        for (int k = 0; k < DIMS; k++) { float v = sx[tid][k]; s = fmaf(v, v, s); }
        sx2[tid] = s;
    } else if (tid < 128) {
        int r = tid - 64;
        float s = 0.f;
        #pragma unroll
        for (int k = 0; k < DIMS; k++) { float v = sy[r][k]; s = fmaf(v, v, s); }
        sy2[r] = s;
    }
    __syncthreads();

    const int ty = tid >> 4, tx = tid & 15;
    const int r0 = ty * 4, c0 = tx * 4;
    float acc[4][4];
    #pragma unroll
    for (int i = 0; i < 4; i++)
        #pragma unroll
        for (int j = 0; j < 4; j++) acc[i][j] = 0.f;

    #pragma unroll
    for (int k = 0; k < DIMS; k++) {
        float a0 = sx[r0 + 0][k], a1 = sx[r0 + 1][k];
        float a2 = sx[r0 + 2][k], a3 = sx[r0 + 3][k];
        float b0 = sy[c0 + 0][k], b1 = sy[c0 + 1][k];
        float b2 = sy[c0 + 2][k], b3 = sy[c0 + 3][k];
        acc[0][0] = fmaf(a0, b0, acc[0][0]); acc[0][1] = fmaf(a0, b1, acc[0][1]);
        acc[0][2] = fmaf(a0, b2, acc[0][2]); acc[0][3] = fmaf(a0, b3, acc[0][3]);
        acc[1][0] = fmaf(a1, b0, acc[1][0]); acc[1][1] = fmaf(a1, b1, acc[1][1]);
        acc[1][2] = fmaf(a1, b2, acc[1][2]); acc[1][3] = fmaf(a1, b3, acc[1][3]);
        acc[2][0] = fmaf(a2, b0, acc[2][0]); acc[2][1] = fmaf(a2, b1, acc[2][1]);
        acc[2][2] = fmaf(a2, b2, acc[2][2]); acc[2][3] = fmaf(a2, b3, acc[2][3]);
        acc[3][0] = fmaf(a3, b0, acc[3][0]); acc[3][1] = fmaf(a3, b1, acc[3][1]);
        acc[3][2] = fmaf(a3, b2, acc[3][2]); acc[3][3] = fmaf(a3, b3, acc[3][3]);
    }

    #pragma unroll
    for (int i = 0; i < 4; i++) {
        __half hrow[4];
        uint8_t brow[4];
        #pragma unroll
        for (int j = 0; j < 4; j++) {
            float C = sx2[r0 + i] + sy2[c0 + j] - 2.f * acc[i][j];
            C = fmaxf(C, 0.f);
            float e16 = exp2f(fmaf(C, -0.14426950408889634f, 16.0f));
            __half h = __float2half_rn(fminf(e16, 65504.f));
            uint8_t b8 = (uint8_t)__nv_cvt_float_to_fp8(
                e16 * 0.00390625f, __NV_SATFINITE, __NV_E4M3);
            hrow[j] = h;
            brow[j] = b8;
            stile[r0 + i][c0 + j] = h;
            s8tile[r0 + i][c0 + j] = b8;
        }
        // Direct row-major stores from registers (8B / 4B vector STG)
        uint2 hw;
        __half2* hwp = reinterpret_cast<__half2*>(&hw);
        hwp[0] = __halves2half2(hrow[0], hrow[1]);
        hwp[1] = __halves2half2(hrow[2], hrow[3]);
        *(uint2*)(g_K1 + (size_t)(I0 + r0 + i) * MP + J0 + c0) = hw;
        uchar4 bw;
        bw.x = brow[0]; bw.y = brow[1]; bw.z = brow[2]; bw.w = brow[3];
        *(uchar4*)(g_K8 + (size_t)(I0 + r0 + i) * MP + J0 + c0) = bw;
    }
    __syncthreads();

    // K1T: each group = 8 contiguous halves (16B) of one transposed row.
    for (int idx = tid; idx < 512; idx += 256) {
        int c = idx >> 3, r8 = (idx & 7) * 8;
        uint4 w;
        __half* hp = reinterpret_cast<__half*>(&w);
        #pragma unroll
        for (int k = 0; k < 8; k++) hp[k] = stile[r8 + k][c];
        *(uint4*)(g_K1T + (size_t)(J0 + c) * NP + I0 + r8) = w;
    }
    // K8T: each group = 16 contiguous bytes of one transposed row.
    {
        int idx = tid;
        if (idx < 256) {
            int c = idx >> 2, r16 = (idx & 3) * 16;
            uint4 w;
            uint8_t* bp = reinterpret_cast<uint8_t*>(&w);
            #pragma unroll
            for (int k = 0; k < 16; k++) bp[k] = s8tile[r16 + k][c];
            *(uint4*)(g_K8T + (size_t)(J0 + c) * NP + I0 + r16) = w;
        }
    }
}

// ---------------------------------------------------------------------------
// ALU-side e4m3 -> fp16 decode (non-negative values; exact 2^-8 scale folded
// into the combine scale; exact for subnormals).
__device__ __forceinline__ __half2 dec8(uint32_t w, uint32_t sel)
{
    uint32_t r = (__byte_perm(w, 0u, sel) >> 1) & 0x7F807F80u;
    return *reinterpret_cast<__half2*>(&r);
}

__device__ __forceinline__ float row16_fp8(uint4 u, uint4 bA, uint4 bB)
{
    const __half2* ba = reinterpret_cast<const __half2*>(&bA);
    const __half2* bb = reinterpret_cast<const __half2*>(&bB);
    __half2 acc = __hmul2(dec8(u.x, 0x1404u), ba[0]);
    acc = __hfma2(dec8(u.x, 0x3424u), ba[1], acc);
    acc = __hfma2(dec8(u.y, 0x1404u), ba[2], acc);
    acc = __hfma2(dec8(u.y, 0x3424u), ba[3], acc);
    acc = __hfma2(dec8(u.z, 0x1404u), bb[0], acc);
    acc = __hfma2(dec8(u.z, 0x3424u), bb[1], acc);
    acc = __hfma2(dec8(u.w, 0x1404u), bb[2], acc);
    acc = __hfma2(dec8(u.w, 0x3424u), bb[3], acc);
    float2 f = __half22float2(acc);
    return f.x + f.y;
}

// fp8 GEMV partial: tile = 32 rows x 512 cols (16KB). warp = 4 rows,
// lane = 16 cols. Partials stored transposed: part[row*CS + cs].
// STREAM=false (a-pass on K8): __ldcg, lines persist in L2 (K8 = 64MB fits).
// STREAM=true (b-pass on K8T): __ldcs evict-first so K8 stays L2-resident.
template <bool STREAM>
__global__ __launch_bounds__(256) void sink_pass8(
    const uint8_t* __restrict__ K8, const __half* __restrict__ vin_h,
    float* __restrict__ part_out)
{
    PDL_TOP();
    if (frozen()) return;
    const int cs = blockIdx.x & (CS - 1);
    const int rb = blockIdx.x / CS;
    const int warp = threadIdx.x >> 5;
    const int lane = threadIdx.x & 31;
    const int rbase = rb * RPB + warp * 4;
    const int col0 = cs * CHUNK + lane * 16;

    const uint4* bhp = (const uint4*)(vin_h + col0);
    uint4 bA = bhp[0], bB = bhp[1];

    const size_t base = (size_t)rbase * MP + col0;
    uint4 u0, u1, u2, u3;
    if (STREAM) {
        u0 = __ldcs((const uint4*)(K8 + base));
        u1 = __ldcs((const uint4*)(K8 + base + MP));
        u2 = __ldcs((const uint4*)(K8 + base + 2 * MP));
        u3 = __ldcs((const uint4*)(K8 + base + 3 * MP));
    } else {
        u0 = __ldcg((const uint4*)(K8 + base));
        u1 = __ldcg((const uint4*)(K8 + base + MP));
        u2 = __ldcg((const uint4*)(K8 + base + 2 * MP));
        u3 = __ldcg((const uint4*)(K8 + base + 3 * MP));
    }

    float a0 = row16_fp8(u0, bA, bB);
    float a1 = row16_fp8(u1, bA, bB);
    float a2 = row16_fp8(u2, bA, bB);
    float a3 = row16_fp8(u3, bA, bB);

    #pragma unroll
    for (int o = 16; o; o >>= 1) {
        a0 += __shfl_xor_sync(0xffffffffu, a0, o);
        a1 += __shfl_xor_sync(0xffffffffu, a1, o);
        a2 += __shfl_xor_sync(0xffffffffu, a2, o);
        a3 += __shfl_xor_sync(0xffffffffu, a3, o);
    }
    if (lane == 0) {
        part_out[(rbase + 0) * CS + cs] = a0;
        part_out[(rbase + 1) * CS + cs] = a1;
        part_out[(rbase + 2) * CS + cs] = a2;
        part_out[(rbase + 3) * CS + cs] = a3;
    }
}

// ---------------------------------------------------------------------------
// fp16 GEMV partial (polish). Same tiling, f32 input vector. __ldcs: K1/K1T
// are 128MB each, no reuse possible, keep them out of L2.
#define HQ_FMA(u, bA, bB, acc)                                                 \
    {                                                                          \
        float2 f0_ = __half22float2(*reinterpret_cast<__half2*>(&(u).x));      \
        float2 f1_ = __half22float2(*reinterpret_cast<__half2*>(&(u).y));      \
        float2 f2_ = __half22float2(*reinterpret_cast<__half2*>(&(u).z));      \
        float2 f3_ = __half22float2(*reinterpret_cast<__half2*>(&(u).w));      \
        acc = fmaf(f0_.x, (bA).x, acc); acc = fmaf(f0_.y, (bA).y, acc);        \
        acc = fmaf(f1_.x, (bA).z, acc); acc = fmaf(f1_.y, (bA).w, acc);        \
        acc = fmaf(f2_.x, (bB).x, acc); acc = fmaf(f2_.y, (bB).y, acc);        \
        acc = fmaf(f3_.x, (bB).z, acc); acc = fmaf(f3_.y, (bB).w, acc);        \
    }

__global__ __launch_bounds__(256) void sink_pass16(
    const __half* __restrict__ K, const float* __restrict__ vin,
    float* __restrict__ part_out)
{
    PDL_TOP();
    if (frozen()) return;
    const int cs = blockIdx.x & (CS - 1);
    const int rb = blockIdx.x / CS;
    const int warp = threadIdx.x >> 5;
    const int lane = threadIdx.x & 31;
    const int rbase = rb * RPB + warp * 4;
    const int col0 = cs * CHUNK + lane * 16;

    const float4* bv = (const float4*)(vin + col0);
    float4 b0 = bv[0], b1 = bv[1], b2 = bv[2], b3 = bv[3];

    const __half* kr = K + (size_t)rbase * MP + col0;
    float a0 = 0.f, a1 = 0.f, a2 = 0.f, a3 = 0.f;
    {
        uint4 u0 = __ldcs((const uint4*)kr);
        uint4 u1 = __ldcs((const uint4*)kr + 1);
        HQ_FMA(u0, b0, b1, a0); HQ_FMA(u1, b2, b3, a0);
    }
    {
        uint4 u0 = __ldcs((const uint4*)(kr + MP));
        uint4 u1 = __ldcs((const uint4*)(kr + MP) + 1);
        HQ_FMA(u0, b0, b1, a1); HQ_FMA(u1, b2, b3, a1);
    }
    {
        uint4 u0 = __ldcs((const uint4*)(kr + 2 * MP));
        uint4 u1 = __ldcs((const uint4*)(kr + 2 * MP) + 1);
        HQ_FMA(u0, b0, b1, a2); HQ_FMA(u1, b2, b3, a2);
    }
    {
        uint4 u0 = __ldcs((const uint4*)(kr + 3 * MP));
        uint4 u1 = __ldcs((const uint4*)(kr + 3 * MP) + 1);
        HQ_FMA(u0, b0, b1, a3); HQ_FMA(u1, b2, b3, a3);
    }

    #pragma unroll
    for (int o = 16; o; o >>= 1) {
        a0 += __shfl_xor_sync(0xffffffffu, a0, o);
        a1 += __shfl_xor_sync(0xffffffffu, a1, o);
        a2 += __shfl_xor_sync(0xffffffffu, a2, o);
        a3 += __shfl_xor_sync(0xffffffffu, a3, o);
    }
    if (lane == 0) {
        part_out[(rbase + 0) * CS + cs] = a0;
        part_out[(rbase + 1) * CS + cs] = a1;
        part_out[(rbase + 2) * CS + cs] = a2;
        part_out[(rbase + 3) * CS + cs] = a3;
    }
}

// ---------------------------------------------------------------------------
__device__ __forceinline__ float combine16(const float* __restrict__ part,
                                           int i)
{
    const float4* p4 = (const float4*)(part + i * CS);
    float4 q0 = p4[0], q1 = p4[1], q2 = p4[2], q3 = p4[3];
    return ((q0.x + q0.y) + (q0.z + q0.w)) + ((q1.x + q1.y) + (q1.z + q1.w)) +
           ((q2.x + q2.y) + (q2.z + q2.w)) + ((q3.x + q3.y) + (q3.z + q3.w));
}

__global__ __launch_bounds__(256) void sink_combine_a(
    const float* __restrict__ p, float scale, float hscale)
{
    PDL_TOP();
    if (frozen()) return;
    const int i = blockIdx.x * 256 + threadIdx.x;
    float s = combine16(g_pa, i);
    float av = __fdividef(p[i] * scale, s);
    g_a[i] = av;
    g_ah[i] = __float2half_rn(av * hscale);
}

// 32-block b combine: update b (+half copy) and write per-block err^2 partial.
__global__ __launch_bounds__(256) void sink_combine_b(
    const float* __restrict__ q, float scale)
{
    PDL_TOP();
    if (frozen()) return;
    const int i = blockIdx.x * 256 + threadIdx.x;
    float s = combine16(g_pb, i);
    float bn = __fdividef(q[i] * scale, s);
    float d = bn - g_b[i];
    g_b[i] = bn;
    g_bh[i] = __float2half_rn(bn);

    __shared__ float sd[256];
    sd[threadIdx.x] = d * d;
    __syncthreads();
    for (int o = 128; o; o >>= 1) {
        if (threadIdx.x < o) sd[threadIdx.x] += sd[threadIdx.x + o];
        __syncthreads();
    }
    if (threadIdx.x == 0) g_errp[blockIdx.x] = sd[0];
}

// ---------------------------------------------------------------------------
// T = a * (K1/2^16) * b; cost term = T * C with C = EPS*(ln 2^16 - ln K1).
__global__ __launch_bounds__(256) void finalize_T(float* __restrict__ Tout,
                                                  int write_T)
{
    PDL_TOP();
    const size_t e0 = ((size_t)blockIdx.x * 4096) + (size_t)threadIdx.x * 16;
    const int i = (int)(e0 >> 13);
    const float ai = g_a[i] * INV_SCALE_F;
    float cs = 0.f;

    #pragma unroll
    for (int g = 0; g < 4; ++g) {
        const size_t e = e0 + g * 4;
        const int j = (int)(e & 8191);
        uint2 kv2 = *reinterpret_cast<const uint2*>(g_K1 + e);
        __half2 h0 = *reinterpret_cast<__half2*>(&kv2.x);
        __half2 h1 = *reinterpret_cast<__half2*>(&kv2.y);
        float2 f0 = __half22float2(h0);
        float2 f1 = __half22float2(h1);
        const float4 bv = *reinterpret_cast<const float4*>(g_b + j);

        float t0 = ai * f0.x * bv.x;
        float t1 = ai * f0.y * bv.y;
        float t2 = ai * f1.x * bv.z;
        float t3 = ai * f1.y * bv.w;

        if (f0.x > 0.f) cs = fmaf(t0, EPSV * (LOG_SCALE_F - __logf(f0.x)), cs);
        if (f0.y > 0.f) cs = fmaf(t1, EPSV * (LOG_SCALE_F - __logf(f0.y)), cs);
        if (f1.x > 0.f) cs = fmaf(t2, EPSV * (LOG_SCALE_F - __logf(f1.x)), cs);
        if (f1.y > 0.f) cs = fmaf(t3, EPSV * (LOG_SCALE_F - __logf(f1.y)), cs);

        if (write_T) {
            if ((((uintptr_t)Tout) & 15) == 0) {
                *reinterpret_cast<float4*>(Tout + e) = make_float4(t0, t1, t2, t3);
            } else {
                Tout[e + 0] = t0;
                Tout[e + 1] = t1;
                Tout[e + 2] = t2;
                Tout[e + 3] = t3;
            }
        }
    }

    __shared__ float sd[256];
    sd[threadIdx.x] = cs;
    __syncthreads();
    for (int o = 128; o; o >>= 1) {
        if (threadIdx.x < o) sd[threadIdx.x] += sd[threadIdx.x + o];
        __syncthreads();
    }
    if (threadIdx.x == 0) g_part[blockIdx.x] = sd[0];
}

__global__ __launch_bounds__(256) void reduce_cost(float* __restrict__ cost_out)
{
    PDL_TOP();
    __shared__ double sd[256];
    double s = 0.0;
    for (int i = threadIdx.x; i < 16384; i += 256) s += (double)g_part[i];
    sd[threadIdx.x] = s;
    __syncthreads();
    for (int o = 128; o; o >>= 1) {
        if (threadIdx.x < o) sd[threadIdx.x] += sd[threadIdx.x + o];
        __syncthreads();
    }
    if (threadIdx.x == 0) cost_out[0] = (float)sd[0];
}

// ---------------------------------------------------------------------------
#define LAUNCH_PDL(func, grid, ...)                                            \
    do {                                                                       \
        cudaLaunchConfig_t cfg_ = {};                                          \
        cfg_.gridDim = dim3(grid);                                             \
        cfg_.blockDim = dim3(256);                                             \
        cfg_.stream = 0;                                                       \
        cudaLaunchAttribute at_[1];                                            \
        at_[0].id = cudaLaunchAttributeProgrammaticStreamSerialization;        \
        at_[0].val.programmaticStreamSerializationAllowed = 1;                 \
        cfg_.attrs = at_;                                                      \
        cfg_.numAttrs = 1;                                                     \
        cudaLaunchKernelEx(&cfg_, func, __VA_ARGS__);                          \
    } while (0)

extern "C" void kernel_launch(void* const* d_in, const int* in_sizes, int n_in,
                              void* d_out, int out_size)
{
    const float* x = (const float*)d_in[0];
    const float* y = (const float*)d_in[1];
    const float* p = (const float*)d_in[2];
    const float* q = (const float*)d_in[3];
    float* out = (float*)d_out;

    void *k1p, *k1tp, *k8p, *k8tp, *ap, *bp, *ahp, *bhp, *pap, *pbp;
    cudaGetSymbolAddress(&k1p, g_K1);
    cudaGetSymbolAddress(&k1tp, g_K1T);
    cudaGetSymbolAddress(&k8p, g_K8);
    cudaGetSymbolAddress(&k8tp, g_K8T);
    cudaGetSymbolAddress(&ap, g_a);
    cudaGetSymbolAddress(&bp, g_b);
    cudaGetSymbolAddress(&ahp, g_ah);
    cudaGetSymbolAddress(&bhp, g_bh);
    cudaGetSymbolAddress(&pap, g_pa);
    cudaGetSymbolAddress(&pbp, g_pb);

    sink_init<<<32, 256>>>();
    dim3 bgrid(MP / 64, NP / 64);
    build_K<<<bgrid, 256>>>(x, y);

    const int mv_grid = (NP / RPB) * CS; // 4096
    for (int it = 0; it < TOTAL_ITERS; ++it) {
        if (it < FP8_ITERS) {
            LAUNCH_PDL(sink_pass8<false>, mv_grid, (const uint8_t*)k8p,
                       (const __half*)bhp, (float*)pap);
            LAUNCH_PDL(sink_combine_a, NP / 256, p, 1.0f, AH_SCALE);
            LAUNCH_PDL(sink_pass8<true>, mv_grid, (const uint8_t*)k8tp,
                       (const __half*)ahp, (float*)pbp);
            LAUNCH_PDL(sink_combine_b, MP / 256, q, 1024.0f);
        } else {
            LAUNCH_PDL(sink_pass16, mv_grid, (const __half*)k1p,
                       (const float*)bp, (float*)pap);
            LAUNCH_PDL(sink_combine_a, NP / 256, p, SCALE_F, AH_SCALE);
            LAUNCH_PDL(sink_pass16, mv_grid, (const __half*)k1tp,
                       (const float*)ap, (float*)pbp);
            LAUNCH_PDL(sink_combine_b, MP / 256, q, SCALE_F);
        }
    }

    const long long total = (long long)NP * MP;
    if ((long long)out_size == total + 1) {
        LAUNCH_PDL(finalize_T, 16384, out + 1, 1);
        LAUNCH_PDL(reduce_cost, 1, out);
    } else if ((long long)out_size == total) {
        LAUNCH_PDL(finalize_T, 16384, out, 1);
    } else if ((long long)out_size > total) {
        LAUNCH_PDL(finalize_T, 16384, out + (out_size - total), 1);
        LAUNCH_PDL(reduce_cost, 1, out);
    } else {
        LAUNCH_PDL(finalize_T, 16384, (float*)nullptr, 0);
        LAUNCH_PDL(reduce_cost, 1, out);
    }
}

// round 16
// speedup vs baseline: 2.2179x; 1.1619x over previous
#include <cuda_runtime.h>
#include <cuda_fp16.h>
#include <cuda_fp8.h>
#include <math.h>
#include <stdint.h>

#define NP 8192
#define MP 8192
#define DIMS 32
#define EPSV 10.0f
#define THRESH2 (1e-5f * 1e-5f)
#define FP8_ITERS 8
#define TOTAL_ITERS 10 /* 8 fp8 + 2 fp16 polish (lambda<=0.34 bound) */
#define SCALE_F 65536.0f
#define INV_SCALE_F (1.0f / 65536.0f)
#define LOG_SCALE_F 11.090354888959125f /* ln(65536) */
#define CS 16
#define CHUNK (MP / CS) /* 512 */
#define RPB 32
#define AH_SCALE 1024.0f

// PDL: allow dependents to launch early; wait gates on predecessor completion.
#define PDL_TOP()                                                              \
    do {                                                                       \
        asm volatile("griddepcontrol.launch_dependents;" ::: "memory");        \
        asm volatile("griddepcontrol.wait;" ::: "memory");                     \
    } while (0)

__device__ __half   g_K1[(size_t)NP * MP];
__device__ __half   g_K1T[(size_t)NP * MP];
__device__ uint8_t  g_K8[(size_t)NP * MP];
__device__ uint8_t  g_K8T[(size_t)NP * MP];
__device__ float  g_a[NP];
__device__ float  g_b[MP];
__device__ __half g_ah[NP]; // a * 1024 in half (fp8 passB input)
__device__ __half g_bh[MP]; // b in half (fp8 passA input)
__device__ float  g_pa[NP * CS]; // partials, layout [row][cs]
__device__ float  g_pb[MP * CS];
__device__ float  g_errp[32]; // per-block err^2 partials (sticky freeze)
__device__ float  g_part[16384];

// Sticky freeze: err of the last completed b-update, summed deterministically.
__device__ __forceinline__ bool frozen()
{
    float v = g_errp[threadIdx.x & 31];
    #pragma unroll
    for (int o = 16; o; o >>= 1) v += __shfl_xor_sync(0xffffffffu, v, o);
    return v < THRESH2;
}

// ---------------------------------------------------------------------------
__global__ void sink_init()
{
    int i = blockIdx.x * 256 + threadIdx.x;
    if (i < MP) { g_b[i] = 1.0f; g_bh[i] = __float2half_rn(1.0f); }
    if (i < 32) g_errp[i] = 1e30f;
}

// ---------------------------------------------------------------------------
// Build: e = exp(-max(C,0)/EPS). K1/K8 written directly from the register
// micro-tile (vector STG); K1T/K8T transposed through padded shared tiles
// and written as STG.128.
__global__ __launch_bounds__(256) void build_K(const float* __restrict__ x,
                                               const float* __restrict__ y)
{
    __shared__ float sx[64][DIMS + 1];
    __shared__ float sy[64][DIMS + 1];
    __shared__ float sx2[64];
    __shared__ float sy2[64];
    __shared__ __half  stile[64][72];  // 144B rows (16B aligned)
    __shared__ uint8_t s8tile[64][80]; // 80B rows (16B aligned)

    const int tid = threadIdx.x;
    const int I0 = blockIdx.y * 64;
    const int J0 = blockIdx.x * 64;

    for (int idx = tid; idx < 64 * DIMS; idx += 256) {
        int r = idx >> 5, k = idx & 31;
        sx[r][k] = x[(I0 + r) * DIMS + k];
        sy[r][k] = y[(J0 + r) * DIMS + k];
    }
    __syncthreads();
    if (tid < 64) {
        float s = 0.f;
        #pragma unroll
        for (int k = 0; k < DIMS; k++) { float v = sx[tid][k]; s = fmaf(v, v, s); }
        sx2[tid] = s;
    } else if (tid < 128) {
        int r = tid - 64;
        float s = 0.f;
        #pragma unroll
        for (int k = 0; k < DIMS; k++) { float v = sy[r][k]; s = fmaf(v, v, s); }
        sy2[r] = s;
    }
    __syncthreads();

    const int ty = tid >> 4, tx = tid & 15;
    const int r0 = ty * 4, c0 = tx * 4;
    float acc[4][4];
    #pragma unroll
    for (int i = 0; i < 4; i++)
        #pragma unroll
        for (int j = 0; j < 4; j++) acc[i][j] = 0.f;

    #pragma unroll
    for (int k = 0; k < DIMS; k++) {
        float a0 = sx[r0 + 0][k], a1 = sx[r0 + 1][k];
        float a2 = sx[r0 + 2][k], a3 = sx[r0 + 3][k];
        float b0 = sy[c0 + 0][k], b1 = sy[c0 + 1][k];
        float b2 = sy[c0 + 2][k], b3 = sy[c0 + 3][k];
        acc[0][0] = fmaf(a0, b0, acc[0][0]); acc[0][1] = fmaf(a0, b1, acc[0][1]);
        acc[0][2] = fmaf(a0, b2, acc[0][2]); acc[0][3] = fmaf(a0, b3, acc[0][3]);
        acc[1][0] = fmaf(a1, b0, acc[1][0]); acc[1][1] = fmaf(a1, b1, acc[1][1]);
        acc[1][2] = fmaf(a1, b2, acc[1][2]); acc[1][3] = fmaf(a1, b3, acc[1][3]);
        acc[2][0] = fmaf(a2, b0, acc[2][0]); acc[2][1] = fmaf(a2, b1, acc[2][1]);
        acc[2][2] = fmaf(a2, b2, acc[2][2]); acc[2][3] = fmaf(a2, b3, acc[2][3]);
        acc[3][0] = fmaf(a3, b0, acc[3][0]); acc[3][1] = fmaf(a3, b1, acc[3][1]);
        acc[3][2] = fmaf(a3, b2, acc[3][2]); acc[3][3] = fmaf(a3, b3, acc[3][3]);
    }

    #pragma unroll
    for (int i = 0; i < 4; i++) {
        __half hrow[4];
        uint8_t brow[4];
        #pragma unroll
        for (int j = 0; j < 4; j++) {
            float C = sx2[r0 + i] + sy2[c0 + j] - 2.f * acc[i][j];
            C = fmaxf(C, 0.f);
            float e16 = exp2f(fmaf(C, -0.14426950408889634f, 16.0f));
            __half h = __float2half_rn(fminf(e16, 65504.f));
            uint8_t b8 = (uint8_t)__nv_cvt_float_to_fp8(
                e16 * 0.00390625f, __NV_SATFINITE, __NV_E4M3);
            hrow[j] = h;
            brow[j] = b8;
            stile[r0 + i][c0 + j] = h;
            s8tile[r0 + i][c0 + j] = b8;
        }
        // Direct row-major stores from registers (8B / 4B vector STG)
        uint2 hw;
        __half2* hwp = reinterpret_cast<__half2*>(&hw);
        hwp[0] = __halves2half2(hrow[0], hrow[1]);
        hwp[1] = __halves2half2(hrow[2], hrow[3]);
        *(uint2*)(g_K1 + (size_t)(I0 + r0 + i) * MP + J0 + c0) = hw;
        uchar4 bw;
        bw.x = brow[0]; bw.y = brow[1]; bw.z = brow[2]; bw.w = brow[3];
        *(uchar4*)(g_K8 + (size_t)(I0 + r0 + i) * MP + J0 + c0) = bw;
    }
    __syncthreads();

    // K1T: each group = 8 contiguous halves (16B) of one transposed row.
    for (int idx = tid; idx < 512; idx += 256) {
        int c = idx >> 3, r8 = (idx & 7) * 8;
        uint4 w;
        __half* hp = reinterpret_cast<__half*>(&w);
        #pragma unroll
        for (int k = 0; k < 8; k++) hp[k] = stile[r8 + k][c];
        *(uint4*)(g_K1T + (size_t)(J0 + c) * NP + I0 + r8) = w;
    }
    // K8T: each group = 16 contiguous bytes of one transposed row.
    {
        int idx = tid;
        if (idx < 256) {
            int c = idx >> 2, r16 = (idx & 3) * 16;
            uint4 w;
            uint8_t* bp = reinterpret_cast<uint8_t*>(&w);
            #pragma unroll
            for (int k = 0; k < 16; k++) bp[k] = s8tile[r16 + k][c];
            *(uint4*)(g_K8T + (size_t)(J0 + c) * NP + I0 + r16) = w;
        }
    }
}

// ---------------------------------------------------------------------------
// ALU-side e4m3 -> fp16 decode (non-negative values; exact 2^-8 scale folded
// into the combine scale; exact for subnormals).
__device__ __forceinline__ __half2 dec8(uint32_t w, uint32_t sel)
{
    uint32_t r = (__byte_perm(w, 0u, sel) >> 1) & 0x7F807F80u;
    return *reinterpret_cast<__half2*>(&r);
}

__device__ __forceinline__ float row16_fp8(uint4 u, uint4 bA, uint4 bB)
{
    const __half2* ba = reinterpret_cast<const __half2*>(&bA);
    const __half2* bb = reinterpret_cast<const __half2*>(&bB);
    __half2 acc = __hmul2(dec8(u.x, 0x1404u), ba[0]);
    acc = __hfma2(dec8(u.x, 0x3424u), ba[1], acc);
    acc = __hfma2(dec8(u.y, 0x1404u), ba[2], acc);
    acc = __hfma2(dec8(u.y, 0x3424u), ba[3], acc);
    acc = __hfma2(dec8(u.z, 0x1404u), bb[0], acc);
    acc = __hfma2(dec8(u.z, 0x3424u), bb[1], acc);
    acc = __hfma2(dec8(u.w, 0x1404u), bb[2], acc);
    acc = __hfma2(dec8(u.w, 0x3424u), bb[3], acc);
    float2 f = __half22float2(acc);
    return f.x + f.y;
}

// fp8 GEMV partial: tile = 32 rows x 512 cols (16KB). warp = 4 rows,
// lane = 16 cols. Partials stored transposed: part[row*CS + cs].
// STREAM=false (a-pass on K8): __ldcg, lines persist in L2 (K8 = 64MB fits).
// STREAM=true (b-pass on K8T): __ldcs evict-first so K8 stays L2-resident.
template <bool STREAM>
__global__ __launch_bounds__(256) void sink_pass8(
    const uint8_t* __restrict__ K8, const __half* __restrict__ vin_h,
    float* __restrict__ part_out)
{
    PDL_TOP();
    if (frozen()) return;
    const int cs = blockIdx.x & (CS - 1);
    const int rb = blockIdx.x / CS;
    const int warp = threadIdx.x >> 5;
    const int lane = threadIdx.x & 31;
    const int rbase = rb * RPB + warp * 4;
    const int col0 = cs * CHUNK + lane * 16;

    const uint4* bhp = (const uint4*)(vin_h + col0);
    uint4 bA = bhp[0], bB = bhp[1];

    const size_t base = (size_t)rbase * MP + col0;
    uint4 u0, u1, u2, u3;
    if (STREAM) {
        u0 = __ldcs((const uint4*)(K8 + base));
        u1 = __ldcs((const uint4*)(K8 + base + MP));
        u2 = __ldcs((const uint4*)(K8 + base + 2 * MP));
        u3 = __ldcs((const uint4*)(K8 + base + 3 * MP));
    } else {
        u0 = __ldcg((const uint4*)(K8 + base));
        u1 = __ldcg((const uint4*)(K8 + base + MP));
        u2 = __ldcg((const uint4*)(K8 + base + 2 * MP));
        u3 = __ldcg((const uint4*)(K8 + base + 3 * MP));
    }

    float a0 = row16_fp8(u0, bA, bB);
    float a1 = row16_fp8(u1, bA, bB);
    float a2 = row16_fp8(u2, bA, bB);
    float a3 = row16_fp8(u3, bA, bB);

    #pragma unroll
    for (int o = 16; o; o >>= 1) {
        a0 += __shfl_xor_sync(0xffffffffu, a0, o);
        a1 += __shfl_xor_sync(0xffffffffu, a1, o);
        a2 += __shfl_xor_sync(0xffffffffu, a2, o);
        a3 += __shfl_xor_sync(0xffffffffu, a3, o);
    }
    if (lane == 0) {
        part_out[(rbase + 0) * CS + cs] = a0;
        part_out[(rbase + 1) * CS + cs] = a1;
        part_out[(rbase + 2) * CS + cs] = a2;
        part_out[(rbase + 3) * CS + cs] = a3;
    }
}

// ---------------------------------------------------------------------------
// fp16 GEMV partial (polish). Same tiling, f32 input vector. __ldcs: K1/K1T
// are 128MB each, no reuse possible, keep them out of L2.
#define HQ_FMA(u, bA, bB, acc)                                                 \
    {                                                                          \
        float2 f0_ = __half22float2(*reinterpret_cast<__half2*>(&(u).x));      \
        float2 f1_ = __half22float2(*reinterpret_cast<__half2*>(&(u).y));      \
        float2 f2_ = __half22float2(*reinterpret_cast<__half2*>(&(u).z));      \
        float2 f3_ = __half22float2(*reinterpret_cast<__half2*>(&(u).w));      \
        acc = fmaf(f0_.x, (bA).x, acc); acc = fmaf(f0_.y, (bA).y, acc);        \
        acc = fmaf(f1_.x, (bA).z, acc); acc = fmaf(f1_.y, (bA).w, acc);        \
        acc = fmaf(f2_.x, (bB).x, acc); acc = fmaf(f2_.y, (bB).y, acc);        \
        acc = fmaf(f3_.x, (bB).z, acc); acc = fmaf(f3_.y, (bB).w, acc);        \
    }

__global__ __launch_bounds__(256) void sink_pass16(
    const __half* __restrict__ K, const float* __restrict__ vin,
    float* __restrict__ part_out)
{
    PDL_TOP();
    if (frozen()) return;
    const int cs = blockIdx.x & (CS - 1);
    const int rb = blockIdx.x / CS;
    const int warp = threadIdx.x >> 5;
    const int lane = threadIdx.x & 31;
    const int rbase = rb * RPB + warp * 4;
    const int col0 = cs * CHUNK + lane * 16;

    const float4* bv = (const float4*)(vin + col0);
    float4 b0 = bv[0], b1 = bv[1], b2 = bv[2], b3 = bv[3];

    const __half* kr = K + (size_t)rbase * MP + col0;
    float a0 = 0.f, a1 = 0.f, a2 = 0.f, a3 = 0.f;
    {
        uint4 u0 = __ldcs((const uint4*)kr);
        uint4 u1 = __ldcs((const uint4*)kr + 1);
        HQ_FMA(u0, b0, b1, a0); HQ_FMA(u1, b2, b3, a0);
    }
    {
        uint4 u0 = __ldcs((const uint4*)(kr + MP));
        uint4 u1 = __ldcs((const uint4*)(kr + MP) + 1);
        HQ_FMA(u0, b0, b1, a1); HQ_FMA(u1, b2, b3, a1);
    }
    {
        uint4 u0 = __ldcs((const uint4*)(kr + 2 * MP));
        uint4 u1 = __ldcs((const uint4*)(kr + 2 * MP) + 1);
        HQ_FMA(u0, b0, b1, a2); HQ_FMA(u1, b2, b3, a2);
    }
    {
        uint4 u0 = __ldcs((const uint4*)(kr + 3 * MP));
        uint4 u1 = __ldcs((const uint4*)(kr + 3 * MP) + 1);
        HQ_FMA(u0, b0, b1, a3); HQ_FMA(u1, b2, b3, a3);
    }

    #pragma unroll
    for (int o = 16; o; o >>= 1) {
        a0 += __shfl_xor_sync(0xffffffffu, a0, o);
        a1 += __shfl_xor_sync(0xffffffffu, a1, o);
        a2 += __shfl_xor_sync(0xffffffffu, a2, o);
        a3 += __shfl_xor_sync(0xffffffffu, a3, o);
    }
    if (lane == 0) {
        part_out[(rbase + 0) * CS + cs] = a0;
        part_out[(rbase + 1) * CS + cs] = a1;
        part_out[(rbase + 2) * CS + cs] = a2;
        part_out[(rbase + 3) * CS + cs] = a3;
    }
}

// ---------------------------------------------------------------------------
__device__ __forceinline__ float combine16(const float* __restrict__ part,
                                           int i)
{
    const float4* p4 = (const float4*)(part + i * CS);
    float4 q0 = p4[0], q1 = p4[1], q2 = p4[2], q3 = p4[3];
    return ((q0.x + q0.y) + (q0.z + q0.w)) + ((q1.x + q1.y) + (q1.z + q1.w)) +
           ((q2.x + q2.y) + (q2.z + q2.w)) + ((q3.x + q3.y) + (q3.z + q3.w));
}

__global__ __launch_bounds__(256) void sink_combine_a(
    const float* __restrict__ p, float scale, float hscale)
{
    PDL_TOP();
    if (frozen()) return;
    const int i = blockIdx.x * 256 + threadIdx.x;
    float s = combine16(g_pa, i);
    float av = __fdividef(p[i] * scale, s);
    g_a[i] = av;
    g_ah[i] = __float2half_rn(av * hscale);
}

// 32-block b combine: update b (+half copy) and write per-block err^2 partial.
__global__ __launch_bounds__(256) void sink_combine_b(
    const float* __restrict__ q, float scale)
{
    PDL_TOP();
    if (frozen()) return;
    const int i = blockIdx.x * 256 + threadIdx.x;
    float s = combine16(g_pb, i);
    float bn = __fdividef(q[i] * scale, s);
    float d = bn - g_b[i];
    g_b[i] = bn;
    g_bh[i] = __float2half_rn(bn);

    __shared__ float sd[256];
    sd[threadIdx.x] = d * d;
    __syncthreads();
    for (int o = 128; o; o >>= 1) {
        if (threadIdx.x < o) sd[threadIdx.x] += sd[threadIdx.x + o];
        __syncthreads();
    }
    if (threadIdx.x == 0) g_errp[blockIdx.x] = sd[0];
}

// ---------------------------------------------------------------------------
// T = a * (K1/2^16) * b; cost term = T * C with C = EPS*(ln 2^16 - ln K1).
__global__ __launch_bounds__(256) void finalize_T(float* __restrict__ Tout,
                                                  int write_T)
{
    PDL_TOP();
    const size_t e0 = ((size_t)blockIdx.x * 4096) + (size_t)threadIdx.x * 16;
    const int i = (int)(e0 >> 13);
    const float ai = g_a[i] * INV_SCALE_F;
    float cs = 0.f;

    #pragma unroll
    for (int g = 0; g < 4; ++g) {
        const size_t e = e0 + g * 4;
        const int j = (int)(e & 8191);
        uint2 kv2 = __ldcs(reinterpret_cast<const uint2*>(g_K1 + e));
        __half2 h0 = *reinterpret_cast<__half2*>(&kv2.x);
        __half2 h1 = *reinterpret_cast<__half2*>(&kv2.y);
        float2 f0 = __half22float2(h0);
        float2 f1 = __half22float2(h1);
        const float4 bv = *reinterpret_cast<const float4*>(g_b + j);

        float t0 = ai * f0.x * bv.x;
        float t1 = ai * f0.y * bv.y;
        float t2 = ai * f1.x * bv.z;
        float t3 = ai * f1.y * bv.w;

        if (f0.x > 0.f) cs = fmaf(t0, EPSV * (LOG_SCALE_F - __logf(f0.x)), cs);
        if (f0.y > 0.f) cs = fmaf(t1, EPSV * (LOG_SCALE_F - __logf(f0.y)), cs);
        if (f1.x > 0.f) cs = fmaf(t2, EPSV * (LOG_SCALE_F - __logf(f1.x)), cs);
        if (f1.y > 0.f) cs = fmaf(t3, EPSV * (LOG_SCALE_F - __logf(f1.y)), cs);

        if (write_T) {
            if ((((uintptr_t)Tout) & 15) == 0) {
                *reinterpret_cast<float4*>(Tout + e) = make_float4(t0, t1, t2, t3);
            } else {
                Tout[e + 0] = t0;
                Tout[e + 1] = t1;
                Tout[e + 2] = t2;
                Tout[e + 3] = t3;
            }
        }
    }

    __shared__ float sd[256];
    sd[threadIdx.x] = cs;
    __syncthreads();
    for (int o = 128; o; o >>= 1) {
        if (threadIdx.x < o) sd[threadIdx.x] += sd[threadIdx.x + o];
        __syncthreads();
    }
    if (threadIdx.x == 0) g_part[blockIdx.x] = sd[0];
}

__global__ __launch_bounds__(256) void reduce_cost(float* __restrict__ cost_out)
{
    PDL_TOP();
    __shared__ double sd[256];
    double s = 0.0;
    for (int i = threadIdx.x; i < 16384; i += 256) s += (double)g_part[i];
    sd[threadIdx.x] = s;
    __syncthreads();
    for (int o = 128; o; o >>= 1) {
        if (threadIdx.x < o) sd[threadIdx.x] += sd[threadIdx.x + o];
        __syncthreads();
    }
    if (threadIdx.x == 0) cost_out[0] = (float)sd[0];
}

// ---------------------------------------------------------------------------
#define LAUNCH_PDL(func, grid, ...)                                            \
    do {                                                                       \
        cudaLaunchConfig_t cfg_ = {};                                          \
        cfg_.gridDim = dim3(grid);                                             \
        cfg_.blockDim = dim3(256);                                             \
        cfg_.stream = 0;                                                       \
        cudaLaunchAttribute at_[1];                                            \
        at_[0].id = cudaLaunchAttributeProgrammaticStreamSerialization;        \
        at_[0].val.programmaticStreamSerializationAllowed = 1;                 \
        cfg_.attrs = at_;                                                      \
        cfg_.numAttrs = 1;                                                     \
        cudaLaunchKernelEx(&cfg_, func, __VA_ARGS__);                          \
    } while (0)

extern "C" void kernel_launch(void* const* d_in, const int* in_sizes, int n_in,
                              void* d_out, int out_size)
{
    const float* x = (const float*)d_in[0];
    const float* y = (const float*)d_in[1];
    const float* p = (const float*)d_in[2];
    const float* q = (const float*)d_in[3];
    float* out = (float*)d_out;

    void *k1p, *k1tp, *k8p, *k8tp, *ap, *bp, *ahp, *bhp, *pap, *pbp;
    cudaGetSymbolAddress(&k1p, g_K1);
    cudaGetSymbolAddress(&k1tp, g_K1T);
    cudaGetSymbolAddress(&k8p, g_K8);
    cudaGetSymbolAddress(&k8tp, g_K8T);
    cudaGetSymbolAddress(&ap, g_a);
    cudaGetSymbolAddress(&bp, g_b);
    cudaGetSymbolAddress(&ahp, g_ah);
    cudaGetSymbolAddress(&bhp, g_bh);
    cudaGetSymbolAddress(&pap, g_pa);
    cudaGetSymbolAddress(&pbp, g_pb);

    sink_init<<<32, 256>>>();
    dim3 bgrid(MP / 64, NP / 64);
    build_K<<<bgrid, 256>>>(x, y);

    const int mv_grid = (NP / RPB) * CS; // 4096
    for (int it = 0; it < TOTAL_ITERS; ++it) {
        if (it < FP8_ITERS) {
            LAUNCH_PDL(sink_pass8<false>, mv_grid, (const uint8_t*)k8p,
                       (const __half*)bhp, (float*)pap);
            LAUNCH_PDL(sink_combine_a, NP / 256, p, 1.0f, AH_SCALE);
            LAUNCH_PDL(sink_pass8<true>, mv_grid, (const uint8_t*)k8tp,
                       (const __half*)ahp, (float*)pbp);
            LAUNCH_PDL(sink_combine_b, MP / 256, q, 1024.0f);
        } else {
            LAUNCH_PDL(sink_pass16, mv_grid, (const __half*)k1p,
                       (const float*)bp, (float*)pap);
            LAUNCH_PDL(sink_combine_a, NP / 256, p, SCALE_F, AH_SCALE);
            LAUNCH_PDL(sink_pass16, mv_grid, (const __half*)k1tp,
                       (const float*)ap, (float*)pbp);
            LAUNCH_PDL(sink_combine_b, MP / 256, q, SCALE_F);
        }
    }

    const long long total = (long long)NP * MP;
    if ((long long)out_size == total + 1) {
        LAUNCH_PDL(finalize_T, 16384, out + 1, 1);
        LAUNCH_PDL(reduce_cost, 1, out);
    } else if ((long long)out_size == total) {
        LAUNCH_PDL(finalize_T, 16384, out, 1);
    } else if ((long long)out_size > total) {
        LAUNCH_PDL(finalize_T, 16384, out + (out_size - total), 1);
        LAUNCH_PDL(reduce_cost, 1, out);
    } else {
        LAUNCH_PDL(finalize_T, 16384, (float*)nullptr, 0);
        LAUNCH_PDL(reduce_cost, 1, out);
    }
}

// round 17
// speedup vs baseline: 2.3659x; 1.0667x over previous
#include <cuda_runtime.h>
#include <cuda_fp16.h>
#include <cuda_fp8.h>
#include <math.h>
#include <stdint.h>

#define NP 8192
#define MP 8192
#define DIMS 32
#define EPSV 10.0f
#define THRESH2 (1e-5f * 1e-5f)
#define FP8_ITERS 6
#define TOTAL_ITERS 8 /* 6 fp8 + 2 fp16 polish (lambda<~0.2, measured) */
#define SCALE_F 65536.0f
#define INV_SCALE_F (1.0f / 65536.0f)
#define LOG_SCALE_F 11.090354888959125f /* ln(65536) */
#define CS 16
#define CHUNK (MP / CS) /* 512 */
#define RPB 32
#define AH_SCALE 1024.0f

// PDL: allow dependents to launch early; wait gates on predecessor completion.
#define PDL_TOP()                                                              \
    do {                                                                       \
        asm volatile("griddepcontrol.launch_dependents;" ::: "memory");        \
        asm volatile("griddepcontrol.wait;" ::: "memory");                     \
    } while (0)

__device__ __half   g_K1[(size_t)NP * MP];
__device__ __half   g_K1T[(size_t)NP * MP];
__device__ uint8_t  g_K8[(size_t)NP * MP];
__device__ uint8_t  g_K8T[(size_t)NP * MP];
__device__ float  g_a[NP];
__device__ float  g_b[MP];
__device__ __half g_ah[NP]; // a * 1024 in half (fp8 passB input)
__device__ __half g_bh[MP]; // b in half (fp8 passA input)
__device__ float  g_pa[NP * CS]; // partials, layout [row][cs]
__device__ float  g_pb[MP * CS];
__device__ float  g_errp[32]; // per-block err^2 partials (sticky freeze)
__device__ float  g_part[16384];

// Sticky freeze: err of the last completed b-update, summed deterministically.
__device__ __forceinline__ bool frozen()
{
    float v = g_errp[threadIdx.x & 31];
    #pragma unroll
    for (int o = 16; o; o >>= 1) v += __shfl_xor_sync(0xffffffffu, v, o);
    return v < THRESH2;
}

// ---------------------------------------------------------------------------
__global__ void sink_init()
{
    int i = blockIdx.x * 256 + threadIdx.x;
    if (i < MP) { g_b[i] = 1.0f; g_bh[i] = __float2half_rn(1.0f); }
    if (i < 32) g_errp[i] = 1e30f;
}

// ---------------------------------------------------------------------------
// Build: e = exp(-max(C,0)/EPS). K1/K8 written directly from the register
// micro-tile (vector STG); K1T/K8T transposed through padded shared tiles
// and written as STG.128.
__global__ __launch_bounds__(256) void build_K(const float* __restrict__ x,
                                               const float* __restrict__ y)
{
    __shared__ float sx[64][DIMS + 1];
    __shared__ float sy[64][DIMS + 1];
    __shared__ float sx2[64];
    __shared__ float sy2[64];
    __shared__ __half  stile[64][72];  // 144B rows (16B aligned)
    __shared__ uint8_t s8tile[64][80]; // 80B rows (16B aligned)

    const int tid = threadIdx.x;
    const int I0 = blockIdx.y * 64;
    const int J0 = blockIdx.x * 64;

    for (int idx = tid; idx < 64 * DIMS; idx += 256) {
        int r = idx >> 5, k = idx & 31;
        sx[r][k] = x[(I0 + r) * DIMS + k];
        sy[r][k] = y[(J0 + r) * DIMS + k];
    }
    __syncthreads();
    if (tid < 64) {
        float s = 0.f;
        #pragma unroll
        for (int k = 0; k < DIMS; k++) { float v = sx[tid][k]; s = fmaf(v, v, s); }
        sx2[tid] = s;
    } else if (tid < 128) {
        int r = tid - 64;
        float s = 0.f;
        #pragma unroll
        for (int k = 0; k < DIMS; k++) { float v = sy[r][k]; s = fmaf(v, v, s); }
        sy2[r] = s;
    }
    __syncthreads();

    const int ty = tid >> 4, tx = tid & 15;
    const int r0 = ty * 4, c0 = tx * 4;
    float acc[4][4];
    #pragma unroll
    for (int i = 0; i < 4; i++)
        #pragma unroll
        for (int j = 0; j < 4; j++) acc[i][j] = 0.f;

    #pragma unroll
    for (int k = 0; k < DIMS; k++) {
        float a0 = sx[r0 + 0][k], a1 = sx[r0 + 1][k];
        float a2 = sx[r0 + 2][k], a3 = sx[r0 + 3][k];
        float b0 = sy[c0 + 0][k], b1 = sy[c0 + 1][k];
        float b2 = sy[c0 + 2][k], b3 = sy[c0 + 3][k];
        acc[0][0] = fmaf(a0, b0, acc[0][0]); acc[0][1] = fmaf(a0, b1, acc[0][1]);
        acc[0][2] = fmaf(a0, b2, acc[0][2]); acc[0][3] = fmaf(a0, b3, acc[0][3]);
        acc[1][0] = fmaf(a1, b0, acc[1][0]); acc[1][1] = fmaf(a1, b1, acc[1][1]);
        acc[1][2] = fmaf(a1, b2, acc[1][2]); acc[1][3] = fmaf(a1, b3, acc[1][3]);
        acc[2][0] = fmaf(a2, b0, acc[2][0]); acc[2][1] = fmaf(a2, b1, acc[2][1]);
        acc[2][2] = fmaf(a2, b2, acc[2][2]); acc[2][3] = fmaf(a2, b3, acc[2][3]);
        acc[3][0] = fmaf(a3, b0, acc[3][0]); acc[3][1] = fmaf(a3, b1, acc[3][1]);
        acc[3][2] = fmaf(a3, b2, acc[3][2]); acc[3][3] = fmaf(a3, b3, acc[3][3]);
    }

    #pragma unroll
    for (int i = 0; i < 4; i++) {
        __half hrow[4];
        uint8_t brow[4];
        #pragma unroll
        for (int j = 0; j < 4; j++) {
            float C = sx2[r0 + i] + sy2[c0 + j] - 2.f * acc[i][j];
            C = fmaxf(C, 0.f);
            float e16 = exp2f(fmaf(C, -0.14426950408889634f, 16.0f));
            __half h = __float2half_rn(fminf(e16, 65504.f));
            uint8_t b8 = (uint8_t)__nv_cvt_float_to_fp8(
                e16 * 0.00390625f, __NV_SATFINITE, __NV_E4M3);
            hrow[j] = h;
            brow[j] = b8;
            stile[r0 + i][c0 + j] = h;
            s8tile[r0 + i][c0 + j] = b8;
        }
        // Direct row-major stores from registers (8B / 4B vector STG)
        uint2 hw;
        __half2* hwp = reinterpret_cast<__half2*>(&hw);
        hwp[0] = __halves2half2(hrow[0], hrow[1]);
        hwp[1] = __halves2half2(hrow[2], hrow[3]);
        *(uint2*)(g_K1 + (size_t)(I0 + r0 + i) * MP + J0 + c0) = hw;
        uchar4 bw;
        bw.x = brow[0]; bw.y = brow[1]; bw.z = brow[2]; bw.w = brow[3];
        *(uchar4*)(g_K8 + (size_t)(I0 + r0 + i) * MP + J0 + c0) = bw;
    }
    __syncthreads();

    // K1T: each group = 8 contiguous halves (16B) of one transposed row.
    for (int idx = tid; idx < 512; idx += 256) {
        int c = idx >> 3, r8 = (idx & 7) * 8;
        uint4 w;
        __half* hp = reinterpret_cast<__half*>(&w);
        #pragma unroll
        for (int k = 0; k < 8; k++) hp[k] = stile[r8 + k][c];
        *(uint4*)(g_K1T + (size_t)(J0 + c) * NP + I0 + r8) = w;
    }
    // K8T: each group = 16 contiguous bytes of one transposed row.
    {
        int idx = tid;
        if (idx < 256) {
            int c = idx >> 2, r16 = (idx & 3) * 16;
            uint4 w;
            uint8_t* bp = reinterpret_cast<uint8_t*>(&w);
            #pragma unroll
            for (int k = 0; k < 16; k++) bp[k] = s8tile[r16 + k][c];
            *(uint4*)(g_K8T + (size_t)(J0 + c) * NP + I0 + r16) = w;
        }
    }
}

// ---------------------------------------------------------------------------
// ALU-side e4m3 -> fp16 decode (non-negative values; exact 2^-8 scale folded
// into the combine scale; exact for subnormals).
__device__ __forceinline__ __half2 dec8(uint32_t w, uint32_t sel)
{
    uint32_t r = (__byte_perm(w, 0u, sel) >> 1) & 0x7F807F80u;
    return *reinterpret_cast<__half2*>(&r);
}

__device__ __forceinline__ float row16_fp8(uint4 u, uint4 bA, uint4 bB)
{
    const __half2* ba = reinterpret_cast<const __half2*>(&bA);
    const __half2* bb = reinterpret_cast<const __half2*>(&bB);
    __half2 acc = __hmul2(dec8(u.x, 0x1404u), ba[0]);
    acc = __hfma2(dec8(u.x, 0x3424u), ba[1], acc);
    acc = __hfma2(dec8(u.y, 0x1404u), ba[2], acc);
    acc = __hfma2(dec8(u.y, 0x3424u), ba[3], acc);
    acc = __hfma2(dec8(u.z, 0x1404u), bb[0], acc);
    acc = __hfma2(dec8(u.z, 0x3424u), bb[1], acc);
    acc = __hfma2(dec8(u.w, 0x1404u), bb[2], acc);
    acc = __hfma2(dec8(u.w, 0x3424u), bb[3], acc);
    float2 f = __half22float2(acc);
    return f.x + f.y;
}

// fp8 GEMV partial: tile = 32 rows x 512 cols (16KB). warp = 4 rows,
// lane = 16 cols. Partials stored transposed: part[row*CS + cs].
// STREAM=false (a-pass on K8): __ldcg, lines persist in L2 (K8 = 64MB fits).
// STREAM=true (b-pass on K8T): __ldcs evict-first so K8 stays L2-resident.
template <bool STREAM>
__global__ __launch_bounds__(256) void sink_pass8(
    const uint8_t* __restrict__ K8, const __half* __restrict__ vin_h,
    float* __restrict__ part_out)
{
    PDL_TOP();
    if (frozen()) return;
    const int cs = blockIdx.x & (CS - 1);
    const int rb = blockIdx.x / CS;
    const int warp = threadIdx.x >> 5;
    const int lane = threadIdx.x & 31;
    const int rbase = rb * RPB + warp * 4;
    const int col0 = cs * CHUNK + lane * 16;

    const uint4* bhp = (const uint4*)(vin_h + col0);
    uint4 bA = bhp[0], bB = bhp[1];

    const size_t base = (size_t)rbase * MP + col0;
    uint4 u0, u1, u2, u3;
    if (STREAM) {
        u0 = __ldcs((const uint4*)(K8 + base));
        u1 = __ldcs((const uint4*)(K8 + base + MP));
        u2 = __ldcs((const uint4*)(K8 + base + 2 * MP));
        u3 = __ldcs((const uint4*)(K8 + base + 3 * MP));
    } else {
        u0 = __ldcg((const uint4*)(K8 + base));
        u1 = __ldcg((const uint4*)(K8 + base + MP));
        u2 = __ldcg((const uint4*)(K8 + base + 2 * MP));
        u3 = __ldcg((const uint4*)(K8 + base + 3 * MP));
    }

    float a0 = row16_fp8(u0, bA, bB);
    float a1 = row16_fp8(u1, bA, bB);
    float a2 = row16_fp8(u2, bA, bB);
    float a3 = row16_fp8(u3, bA, bB);

    #pragma unroll
    for (int o = 16; o; o >>= 1) {
        a0 += __shfl_xor_sync(0xffffffffu, a0, o);
        a1 += __shfl_xor_sync(0xffffffffu, a1, o);
        a2 += __shfl_xor_sync(0xffffffffu, a2, o);
        a3 += __shfl_xor_sync(0xffffffffu, a3, o);
    }
    if (lane == 0) {
        part_out[(rbase + 0) * CS + cs] = a0;
        part_out[(rbase + 1) * CS + cs] = a1;
        part_out[(rbase + 2) * CS + cs] = a2;
        part_out[(rbase + 3) * CS + cs] = a3;
    }
}

// ---------------------------------------------------------------------------
// fp16 GEMV partial (polish). Same tiling, f32 input vector. __ldcs: K1/K1T
// are 128MB each, no reuse possible, keep them out of L2.
#define HQ_FMA(u, bA, bB, acc)                                                 \
    {                                                                          \
        float2 f0_ = __half22float2(*reinterpret_cast<__half2*>(&(u).x));      \
        float2 f1_ = __half22float2(*reinterpret_cast<__half2*>(&(u).y));      \
        float2 f2_ = __half22float2(*reinterpret_cast<__half2*>(&(u).z));      \
        float2 f3_ = __half22float2(*reinterpret_cast<__half2*>(&(u).w));      \
        acc = fmaf(f0_.x, (bA).x, acc); acc = fmaf(f0_.y, (bA).y, acc);        \
        acc = fmaf(f1_.x, (bA).z, acc); acc = fmaf(f1_.y, (bA).w, acc);        \
        acc = fmaf(f2_.x, (bB).x, acc); acc = fmaf(f2_.y, (bB).y, acc);        \
        acc = fmaf(f3_.x, (bB).z, acc); acc = fmaf(f3_.y, (bB).w, acc);        \
    }

__global__ __launch_bounds__(256) void sink_pass16(
    const __half* __restrict__ K, const float* __restrict__ vin,
    float* __restrict__ part_out)
{
    PDL_TOP();
    if (frozen()) return;
    const int cs = blockIdx.x & (CS - 1);
    const int rb = blockIdx.x / CS;
    const int warp = threadIdx.x >> 5;
    const int lane = threadIdx.x & 31;
    const int rbase = rb * RPB + warp * 4;
    const int col0 = cs * CHUNK + lane * 16;

    const float4* bv = (const float4*)(vin + col0);
    float4 b0 = bv[0], b1 = bv[1], b2 = bv[2], b3 = bv[3];

    const __half* kr = K + (size_t)rbase * MP + col0;
    float a0 = 0.f, a1 = 0.f, a2 = 0.f, a3 = 0.f;
    {
        uint4 u0 = __ldcs((const uint4*)kr);
        uint4 u1 = __ldcs((const uint4*)kr + 1);
        HQ_FMA(u0, b0, b1, a0); HQ_FMA(u1, b2, b3, a0);
    }
    {
        uint4 u0 = __ldcs((const uint4*)(kr + MP));
        uint4 u1 = __ldcs((const uint4*)(kr + MP) + 1);
        HQ_FMA(u0, b0, b1, a1); HQ_FMA(u1, b2, b3, a1);
    }
    {
        uint4 u0 = __ldcs((const uint4*)(kr + 2 * MP));
        uint4 u1 = __ldcs((const uint4*)(kr + 2 * MP) + 1);
        HQ_FMA(u0, b0, b1, a2); HQ_FMA(u1, b2, b3, a2);
    }
    {
        uint4 u0 = __ldcs((const uint4*)(kr + 3 * MP));
        uint4 u1 = __ldcs((const uint4*)(kr + 3 * MP) + 1);
        HQ_FMA(u0, b0, b1, a3); HQ_FMA(u1, b2, b3, a3);
    }

    #pragma unroll
    for (int o = 16; o; o >>= 1) {
        a0 += __shfl_xor_sync(0xffffffffu, a0, o);
        a1 += __shfl_xor_sync(0xffffffffu, a1, o);
        a2 += __shfl_xor_sync(0xffffffffu, a2, o);
        a3 += __shfl_xor_sync(0xffffffffu, a3, o);
    }
    if (lane == 0) {
        part_out[(rbase + 0) * CS + cs] = a0;
        part_out[(rbase + 1) * CS + cs] = a1;
        part_out[(rbase + 2) * CS + cs] = a2;
        part_out[(rbase + 3) * CS + cs] = a3;
    }
}

// ---------------------------------------------------------------------------
__device__ __forceinline__ float combine16(const float* __restrict__ part,
                                           int i)
{
    const float4* p4 = (const float4*)(part + i * CS);
    float4 q0 = p4[0], q1 = p4[1], q2 = p4[2], q3 = p4[3];
    return ((q0.x + q0.y) + (q0.z + q0.w)) + ((q1.x + q1.y) + (q1.z + q1.w)) +
           ((q2.x + q2.y) + (q2.z + q2.w)) + ((q3.x + q3.y) + (q3.z + q3.w));
}

__global__ __launch_bounds__(256) void sink_combine_a(
    const float* __restrict__ p, float scale, float hscale)
{
    PDL_TOP();
    if (frozen()) return;
    const int i = blockIdx.x * 256 + threadIdx.x;
    float s = combine16(g_pa, i);
    float av = __fdividef(p[i] * scale, s);
    g_a[i] = av;
    g_ah[i] = __float2half_rn(av * hscale);
}

// 32-block b combine: update b (+half copy) and write per-block err^2 partial.
__global__ __launch_bounds__(256) void sink_combine_b(
    const float* __restrict__ q, float scale)
{
    PDL_TOP();
    if (frozen()) return;
    const int i = blockIdx.x * 256 + threadIdx.x;
    float s = combine16(g_pb, i);
    float bn = __fdividef(q[i] * scale, s);
    float d = bn - g_b[i];
    g_b[i] = bn;
    g_bh[i] = __float2half_rn(bn);

    __shared__ float sd[256];
    sd[threadIdx.x] = d * d;
    __syncthreads();
    for (int o = 128; o; o >>= 1) {
        if (threadIdx.x < o) sd[threadIdx.x] += sd[threadIdx.x + o];
        __syncthreads();
    }
    if (threadIdx.x == 0) g_errp[blockIdx.x] = sd[0];
}

// ---------------------------------------------------------------------------
// T = a * (K1/2^16) * b; cost term = T * C with C = EPS*(ln 2^16 - ln K1).
__global__ __launch_bounds__(256) void finalize_T(float* __restrict__ Tout,
                                                  int write_T)
{
    PDL_TOP();
    const size_t e0 = ((size_t)blockIdx.x * 4096) + (size_t)threadIdx.x * 16;
    const int i = (int)(e0 >> 13);
    const float ai = g_a[i] * INV_SCALE_F;
    float cs = 0.f;

    #pragma unroll
    for (int g = 0; g < 4; ++g) {
        const size_t e = e0 + g * 4;
        const int j = (int)(e & 8191);
        uint2 kv2 = __ldcs(reinterpret_cast<const uint2*>(g_K1 + e));
        __half2 h0 = *reinterpret_cast<__half2*>(&kv2.x);
        __half2 h1 = *reinterpret_cast<__half2*>(&kv2.y);
        float2 f0 = __half22float2(h0);
        float2 f1 = __half22float2(h1);
        const float4 bv = *reinterpret_cast<const float4*>(g_b + j);

        float t0 = ai * f0.x * bv.x;
        float t1 = ai * f0.y * bv.y;
        float t2 = ai * f1.x * bv.z;
        float t3 = ai * f1.y * bv.w;

        if (f0.x > 0.f) cs = fmaf(t0, EPSV * (LOG_SCALE_F - __logf(f0.x)), cs);
        if (f0.y > 0.f) cs = fmaf(t1, EPSV * (LOG_SCALE_F - __logf(f0.y)), cs);
        if (f1.x > 0.f) cs = fmaf(t2, EPSV * (LOG_SCALE_F - __logf(f1.x)), cs);
        if (f1.y > 0.f) cs = fmaf(t3, EPSV * (LOG_SCALE_F - __logf(f1.y)), cs);

        if (write_T) {
            if ((((uintptr_t)Tout) & 15) == 0) {
                *reinterpret_cast<float4*>(Tout + e) = make_float4(t0, t1, t2, t3);
            } else {
                Tout[e + 0] = t0;
                Tout[e + 1] = t1;
                Tout[e + 2] = t2;
                Tout[e + 3] = t3;
            }
        }
    }

    __shared__ float sd[256];
    sd[threadIdx.x] = cs;
    __syncthreads();
    for (int o = 128; o; o >>= 1) {
        if (threadIdx.x < o) sd[threadIdx.x] += sd[threadIdx.x + o];
        __syncthreads();
    }
    if (threadIdx.x == 0) g_part[blockIdx.x] = sd[0];
}

__global__ __launch_bounds__(256) void reduce_cost(float* __restrict__ cost_out)
{
    PDL_TOP();
    __shared__ double sd[256];
    double s = 0.0;
    for (int i = threadIdx.x; i < 16384; i += 256) s += (double)g_part[i];
    sd[threadIdx.x] = s;
    __syncthreads();
    for (int o = 128; o; o >>= 1) {
        if (threadIdx.x < o) sd[threadIdx.x] += sd[threadIdx.x + o];
        __syncthreads();
    }
    if (threadIdx.x == 0) cost_out[0] = (float)sd[0];
}

// ---------------------------------------------------------------------------
#define LAUNCH_PDL(func, grid, ...)                                            \
    do {                                                                       \
        cudaLaunchConfig_t cfg_ = {};                                          \
        cfg_.gridDim = dim3(grid);                                             \
        cfg_.blockDim = dim3(256);                                             \
        cfg_.stream = 0;                                                       \
        cudaLaunchAttribute at_[1];                                            \
        at_[0].id = cudaLaunchAttributeProgrammaticStreamSerialization;        \
        at_[0].val.programmaticStreamSerializationAllowed = 1;                 \
        cfg_.attrs = at_;                                                      \
        cfg_.numAttrs = 1;                                                     \
        cudaLaunchKernelEx(&cfg_, func, __VA_ARGS__);                          \
    } while (0)

extern "C" void kernel_launch(void* const* d_in, const int* in_sizes, int n_in,
                              void* d_out, int out_size)
{
    const float* x = (const float*)d_in[0];
    const float* y = (const float*)d_in[1];
    const float* p = (const float*)d_in[2];
    const float* q = (const float*)d_in[3];
    float* out = (float*)d_out;

    void *k1p, *k1tp, *k8p, *k8tp, *ap, *bp, *ahp, *bhp, *pap, *pbp;
    cudaGetSymbolAddress(&k1p, g_K1);
    cudaGetSymbolAddress(&k1tp, g_K1T);
    cudaGetSymbolAddress(&k8p, g_K8);
    cudaGetSymbolAddress(&k8tp, g_K8T);
    cudaGetSymbolAddress(&ap, g_a);
    cudaGetSymbolAddress(&bp, g_b);
    cudaGetSymbolAddress(&ahp, g_ah);
    cudaGetSymbolAddress(&bhp, g_bh);
    cudaGetSymbolAddress(&pap, g_pa);
    cudaGetSymbolAddress(&pbp, g_pb);

    sink_init<<<32, 256>>>();
    dim3 bgrid(MP / 64, NP / 64);
    build_K<<<bgrid, 256>>>(x, y);

    const int mv_grid = (NP / RPB) * CS; // 4096
    for (int it = 0; it < TOTAL_ITERS; ++it) {
        if (it < FP8_ITERS) {
            LAUNCH_PDL(sink_pass8<false>, mv_grid, (const uint8_t*)k8p,
                       (const __half*)bhp, (float*)pap);
            LAUNCH_PDL(sink_combine_a, NP / 256, p, 1.0f, AH_SCALE);
            LAUNCH_PDL(sink_pass8<true>, mv_grid, (const uint8_t*)k8tp,
                       (const __half*)ahp, (float*)pbp);
            LAUNCH_PDL(sink_combine_b, MP / 256, q, 1024.0f);
        } else {
            LAUNCH_PDL(sink_pass16, mv_grid, (const __half*)k1p,
                       (const float*)bp, (float*)pap);
            LAUNCH_PDL(sink_combine_a, NP / 256, p, SCALE_F, AH_SCALE);
            LAUNCH_PDL(sink_pass16, mv_grid, (const __half*)k1tp,
                       (const float*)ap, (float*)pbp);
            LAUNCH_PDL(sink_combine_b, MP / 256, q, SCALE_F);
        }
    }

    const long long total = (long long)NP * MP;
    if ((long long)out_size == total + 1) {
        LAUNCH_PDL(finalize_T, 16384, out + 1, 1);
        LAUNCH_PDL(reduce_cost, 1, out);
    } else if ((long long)out_size == total) {
        LAUNCH_PDL(finalize_T, 16384, out, 1);
    } else if ((long long)out_size > total) {
        LAUNCH_PDL(finalize_T, 16384, out + (out_size - total), 1);
        LAUNCH_PDL(reduce_cost, 1, out);
    } else {
        LAUNCH_PDL(finalize_T, 16384, (float*)nullptr, 0);
        LAUNCH_PDL(reduce_cost, 1, out);
    }
}